// round 3
// baseline (speedup 1.0000x reference)
#include <cuda_runtime.h>
#include <math.h>
#include <mma.h>

using namespace nvcuda;

#define Bsz 256
#define Ssz 200
#define Dsz 256
#define Hsz 8
#define DHsz 32
#define BS (Bsz * Ssz)   // 51200 rows

// Scratch (device globals: allocation-free per harness rules).
__device__ float g_img_n[BS * Dsz];
__device__ float g_title_n[BS * Dsz];
__device__ float g_keff[BS * Dsz];
__device__ float g_ctx[BS * Dsz];
__device__ float g_h1[BS * Dsz];
__device__ float g_h1n[BS * Dsz];

// ---------------------------------------------------------------------------
// LayerNorm (torch variant: unbiased var, eps added to std)
// ---------------------------------------------------------------------------
__global__ void __launch_bounds__(256) ln_kernel(
    const float* __restrict__ x, const float* __restrict__ ga,
    const float* __restrict__ gb, float* __restrict__ y) {
    __shared__ float sm[8];
    int row = blockIdx.x;
    int t = threadIdx.x;
    int w = t >> 5, lane = t & 31;
    size_t off = (size_t)row * Dsz + t;
    float v = x[off];

    float s = v;
#pragma unroll
    for (int o = 16; o; o >>= 1) s += __shfl_xor_sync(0xffffffffu, s, o);
    if (lane == 0) sm[w] = s;
    __syncthreads();
    if (w == 0) {
        float x8 = (lane < 8) ? sm[lane] : 0.f;
#pragma unroll
        for (int o = 4; o; o >>= 1) x8 += __shfl_xor_sync(0xffffffffu, x8, o);
        if (lane == 0) sm[0] = x8;
    }
    __syncthreads();
    float mean = sm[0] * (1.0f / Dsz);
    __syncthreads();

    float d = v - mean;
    float ss = d * d;
#pragma unroll
    for (int o = 16; o; o >>= 1) ss += __shfl_xor_sync(0xffffffffu, ss, o);
    if (lane == 0) sm[w] = ss;
    __syncthreads();
    if (w == 0) {
        float x8 = (lane < 8) ? sm[lane] : 0.f;
#pragma unroll
        for (int o = 4; o; o >>= 1) x8 += __shfl_xor_sync(0xffffffffu, x8, o);
        if (lane == 0) sm[0] = x8;
    }
    __syncthreads();
    float var = sm[0] * (1.0f / (Dsz - 1));
    float inv = 1.0f / (sqrtf(var) + 1e-6f);
    y[off] = ga[t] * d * inv + gb[t];
}

// ---------------------------------------------------------------------------
// TF32 tensor-core GEMM with register-prefetch double buffering.
// out[m,n] = sum_k A[m,k]*W[n,k] + bias[n] (+ epilogue)
// EPI==0: out += add[m,n]
// EPI==2: z = sffn[m%S]*out; out = add[m,n] + gelu_tanh(z)
// ---------------------------------------------------------------------------
#define GBM 128
#define GBN 64
#define GBK 32
#define ASTR 40
#define CSTR 72

template <int EPI>
__global__ void __launch_bounds__(256) gemm_tf32(
    const float* __restrict__ A, const float* __restrict__ W,
    const float* __restrict__ bias, const float* __restrict__ add,
    const float* __restrict__ sffn, float* __restrict__ out) {
    __shared__ float sh[GBM * CSTR];           // 36864 B
    float* As = sh;                             // [128][40]
    float* Ws = sh + GBM * ASTR;                // [64][40]
    float* Cs = sh;                             // [128][72] reuse

    int m0 = blockIdx.y * GBM;
    int n0 = blockIdx.x * GBN;
    int tid = threadIdx.x;
    int wid = tid >> 5;
    int wm = wid >> 1;
    int wn = wid & 1;
    int lr = tid >> 3;          // 0..31
    int lc = (tid & 7) * 4;     // 0..28

    wmma::fragment<wmma::accumulator, 16, 16, 8, float> cf[2][2];
#pragma unroll
    for (int i = 0; i < 2; i++)
#pragma unroll
        for (int j = 0; j < 2; j++) wmma::fill_fragment(cf[i][j], 0.0f);

    float4 pa[4], pw[2];
    // prefetch k0 = 0
#pragma unroll
    for (int t = 0; t < 4; t++)
        pa[t] = *reinterpret_cast<const float4*>(
            A + (size_t)(m0 + lr + 32 * t) * Dsz + lc);
#pragma unroll
    for (int t = 0; t < 2; t++)
        pw[t] = *reinterpret_cast<const float4*>(
            W + (size_t)(n0 + lr + 32 * t) * Dsz + lc);

    for (int k0 = 0; k0 < Dsz; k0 += GBK) {
        // commit prefetched tile to smem
#pragma unroll
        for (int t = 0; t < 4; t++)
            *reinterpret_cast<float4*>(As + (lr + 32 * t) * ASTR + lc) = pa[t];
#pragma unroll
        for (int t = 0; t < 2; t++)
            *reinterpret_cast<float4*>(Ws + (lr + 32 * t) * ASTR + lc) = pw[t];
        __syncthreads();

        // prefetch next tile (overlaps with MMA below)
        if (k0 + GBK < Dsz) {
#pragma unroll
            for (int t = 0; t < 4; t++)
                pa[t] = *reinterpret_cast<const float4*>(
                    A + (size_t)(m0 + lr + 32 * t) * Dsz + k0 + GBK + lc);
#pragma unroll
            for (int t = 0; t < 2; t++)
                pw[t] = *reinterpret_cast<const float4*>(
                    W + (size_t)(n0 + lr + 32 * t) * Dsz + k0 + GBK + lc);
        }

#pragma unroll
        for (int kk = 0; kk < GBK; kk += 8) {
            wmma::fragment<wmma::matrix_a, 16, 16, 8, wmma::precision::tf32,
                           wmma::row_major> af[2];
            wmma::fragment<wmma::matrix_b, 16, 16, 8, wmma::precision::tf32,
                           wmma::col_major> bf[2];
#pragma unroll
            for (int i = 0; i < 2; i++) {
                wmma::load_matrix_sync(af[i],
                    As + (wm * 32 + i * 16) * ASTR + kk, ASTR);
#pragma unroll
                for (int e = 0; e < af[i].num_elements; e++)
                    af[i].x[e] = wmma::__float_to_tf32(af[i].x[e]);
            }
#pragma unroll
            for (int j = 0; j < 2; j++) {
                wmma::load_matrix_sync(bf[j],
                    Ws + (wn * 32 + j * 16) * ASTR + kk, ASTR);
#pragma unroll
                for (int e = 0; e < bf[j].num_elements; e++)
                    bf[j].x[e] = wmma::__float_to_tf32(bf[j].x[e]);
            }
#pragma unroll
            for (int i = 0; i < 2; i++)
#pragma unroll
                for (int j = 0; j < 2; j++)
                    wmma::mma_sync(cf[i][j], af[i], bf[j], cf[i][j]);
        }
        __syncthreads();
    }

#pragma unroll
    for (int i = 0; i < 2; i++)
#pragma unroll
        for (int j = 0; j < 2; j++)
            wmma::store_matrix_sync(
                Cs + (wm * 32 + i * 16) * CSTR + wn * 32 + j * 16,
                cf[i][j], CSTR, wmma::mem_row_major);
    __syncthreads();

#pragma unroll
    for (int t = 0; t < 8; t++) {
        int idx = tid + 256 * t;
        int r = idx >> 4, c4 = (idx & 15) * 4;
        int m = m0 + r, n = n0 + c4;
        float4 cv = *reinterpret_cast<float4*>(Cs + r * CSTR + c4);
        float4 bv = *reinterpret_cast<const float4*>(bias + n);
        float4 adv = *reinterpret_cast<const float4*>(add + (size_t)m * Dsz + n);
        float rr[4] = {cv.x + bv.x, cv.y + bv.y, cv.z + bv.z, cv.w + bv.w};
        float ad[4] = {adv.x, adv.y, adv.z, adv.w};
        if (EPI == 0) {
#pragma unroll
            for (int j = 0; j < 4; j++) rr[j] += ad[j];
        } else {
            float sf = sffn[m % Ssz];
#pragma unroll
            for (int j = 0; j < 4; j++) {
                float z = sf * rr[j];
                float th = tanhf(0.79788456080286536f * (z + 0.044715f * z * z * z));
                rr[j] = ad[j] + 0.5f * z * (1.0f + th);
            }
        }
        *reinterpret_cast<float4*>(out + (size_t)m * Dsz + n) =
            make_float4(rr[0], rr[1], rr[2], rr[3]);
    }
}

// ---------------------------------------------------------------------------
// WMMA TF32 attention. One block (256 thr) per (b,h). Q(=V) and K_eff in
// smem padded to 208 rows (zeros). Each warp owns one 16-query tile:
//   scores (13x 16x16 tiles via 4 mma each) -> smem row buffer
//   -> fp32 softmax (scale, mask, exp) -> P.V (26 k-steps x 2 mma) -> ctx.
// Zero-padded V rows + masked k>=200 make padding exact.
// ---------------------------------------------------------------------------
#define SPAD 208
#define QSTR 40
#define SBSTR 216

__global__ void __launch_bounds__(256) attn_wmma(
    const float* __restrict__ img_n, const float* __restrict__ keff,
    const int* __restrict__ mask, const float* __restrict__ sattn,
    float* __restrict__ ctx) {
    extern __shared__ float smw[];
    float* Qs = smw;                         // 208*40  (Q == V)
    float* Ks = Qs + SPAD * QSTR;            // 208*40
    float* SB = Ks + SPAD * QSTR;            // 8 * 16 * 216
    float* m_s = SB + 8 * 16 * SBSTR;        // 208 (1.0 = masked)

    int b = blockIdx.x >> 3;
    int h = blockIdx.x & 7;
    int tid = threadIdx.x;
    size_t base = ((size_t)b * Ssz) * Dsz + h * DHsz;

    for (int idx = tid; idx < SPAD * 8; idx += 256) {
        int r = idx >> 3, c = (idx & 7) * 4;
        float4 qv = make_float4(0.f, 0.f, 0.f, 0.f);
        float4 kv = make_float4(0.f, 0.f, 0.f, 0.f);
        if (r < Ssz) {
            qv = *reinterpret_cast<const float4*>(img_n + base + (size_t)r * Dsz + c);
            kv = *reinterpret_cast<const float4*>(keff + base + (size_t)r * Dsz + c);
        }
        *reinterpret_cast<float4*>(Qs + r * QSTR + c) = qv;
        *reinterpret_cast<float4*>(Ks + r * QSTR + c) = kv;
    }
    for (int k = tid; k < SPAD; k += 256)
        m_s[k] = (k >= Ssz || mask[b * Ssz + k] == 0) ? 1.f : 0.f;
    __syncthreads();

    int w = tid >> 5, lane = tid & 31;
    float* sb = SB + w * 16 * SBSTR;
    const float isq = 0.17677669529663687f;  // 1/sqrt(32)

    for (int qt = w; qt < 13; qt += 8) {
        int q0 = qt * 16;

        // ---- scores: S[16][208] = Q_tile . K^T ----
        wmma::fragment<wmma::matrix_a, 16, 16, 8, wmma::precision::tf32,
                       wmma::row_major> qa[4];
#pragma unroll
        for (int k8 = 0; k8 < 4; k8++) {
            wmma::load_matrix_sync(qa[k8], Qs + q0 * QSTR + k8 * 8, QSTR);
#pragma unroll
            for (int e = 0; e < qa[k8].num_elements; e++)
                qa[k8].x[e] = wmma::__float_to_tf32(qa[k8].x[e]);
        }
        for (int nt = 0; nt < 13; nt++) {
            wmma::fragment<wmma::accumulator, 16, 16, 8, float> sc;
            wmma::fill_fragment(sc, 0.0f);
#pragma unroll
            for (int k8 = 0; k8 < 4; k8++) {
                wmma::fragment<wmma::matrix_b, 16, 16, 8, wmma::precision::tf32,
                               wmma::col_major> kb;
                wmma::load_matrix_sync(kb, Ks + (nt * 16) * QSTR + k8 * 8, QSTR);
#pragma unroll
                for (int e = 0; e < kb.num_elements; e++)
                    kb.x[e] = wmma::__float_to_tf32(kb.x[e]);
                wmma::mma_sync(sc, qa[k8], kb, sc);
            }
            wmma::store_matrix_sync(sb + nt * 16, sc, SBSTR, wmma::mem_row_major);
        }
        __syncwarp();

        // ---- softmax (fp32): scale, mask, exp, normalize ----
        for (int r = 0; r < 16; r++) {
            int q = q0 + r;
            float f = (q < Ssz) ? isq * sattn[h * Ssz + q] : 0.f;
            float* row = sb + r * SBSTR;
            float v[7];
            float mx = -3.0e38f;
#pragma unroll
            for (int i = 0; i < 7; i++) {
                int k = lane + 32 * i;
                float s = -3.0e38f;
                if (k < SPAD) s = (m_s[k] != 0.f) ? -1e9f : row[k] * f;
                v[i] = s;
                mx = fmaxf(mx, s);
            }
#pragma unroll
            for (int o = 16; o; o >>= 1)
                mx = fmaxf(mx, __shfl_xor_sync(0xffffffffu, mx, o));
            float se = 0.f;
#pragma unroll
            for (int i = 0; i < 7; i++) {
                int k = lane + 32 * i;
                float e = (k < SPAD) ? __expf(v[i] - mx) : 0.f;
                v[i] = e;
                se += e;
            }
#pragma unroll
            for (int o = 16; o; o >>= 1)
                se += __shfl_xor_sync(0xffffffffu, se, o);
            float inv = 1.f / se;
#pragma unroll
            for (int i = 0; i < 7; i++) {
                int k = lane + 32 * i;
                if (k < SPAD) row[k] = v[i] * inv;
            }
        }
        __syncwarp();

        // ---- ctx tile: C[16][32] = P[16][208] . V[208][32] ----
        wmma::fragment<wmma::accumulator, 16, 16, 8, float> ca[2];
        wmma::fill_fragment(ca[0], 0.0f);
        wmma::fill_fragment(ca[1], 0.0f);
        for (int k8 = 0; k8 < 26; k8++) {
            wmma::fragment<wmma::matrix_a, 16, 16, 8, wmma::precision::tf32,
                           wmma::row_major> pa;
            wmma::load_matrix_sync(pa, sb + k8 * 8, SBSTR);
#pragma unroll
            for (int e = 0; e < pa.num_elements; e++)
                pa.x[e] = wmma::__float_to_tf32(pa.x[e]);
#pragma unroll
            for (int n2 = 0; n2 < 2; n2++) {
                wmma::fragment<wmma::matrix_b, 16, 16, 8, wmma::precision::tf32,
                               wmma::row_major> vb;
                wmma::load_matrix_sync(vb, Qs + (k8 * 8) * QSTR + n2 * 16, QSTR);
#pragma unroll
                for (int e = 0; e < vb.num_elements; e++)
                    vb.x[e] = wmma::__float_to_tf32(vb.x[e]);
                wmma::mma_sync(ca[n2], pa, vb, ca[n2]);
            }
        }
        __syncwarp();
        // stage ctx tile into sb (done with P), then copy valid rows out
        wmma::store_matrix_sync(sb, ca[0], SBSTR, wmma::mem_row_major);
        wmma::store_matrix_sync(sb + 16, ca[1], SBSTR, wmma::mem_row_major);
        __syncwarp();
        for (int e = lane; e < 16 * 8; e += 32) {
            int r = e >> 3, c4 = (e & 7) * 4;
            int q = q0 + r;
            if (q < Ssz) {
                float4 cv = *reinterpret_cast<float4*>(sb + r * SBSTR + c4);
                *reinterpret_cast<float4*>(ctx + base + (size_t)q * Dsz + c4) = cv;
            }
        }
        __syncwarp();
    }
}

// ---------------------------------------------------------------------------
extern "C" void kernel_launch(void* const* d_in, const int* in_sizes, int n_in,
                              void* d_out, int out_size) {
    const float* hidden_img   = (const float*)d_in[0];
    const float* hidden_title = (const float*)d_in[1];
    const int*   mask         = (const int*)  d_in[2];
    const float* a_img   = (const float*)d_in[3];
    const float* b_img   = (const float*)d_in[4];
    const float* a_title = (const float*)d_in[5];
    const float* b_title = (const float*)d_in[6];
    const float* Wb      = (const float*)d_in[7];
    const float* bb      = (const float*)d_in[8];
    const float* Wo      = (const float*)d_in[9];
    const float* bo      = (const float*)d_in[10];
    const float* sattn   = (const float*)d_in[11];
    const float* a_out   = (const float*)d_in[12];
    const float* b_out   = (const float*)d_in[13];
    const float* W1      = (const float*)d_in[14];
    const float* b1      = (const float*)d_in[15];
    const float* sffn    = (const float*)d_in[16];
    float* out = (float*)d_out;

    float *img_n, *title_n, *keff, *ctxb, *h1, *h1n;
    cudaGetSymbolAddress((void**)&img_n,   g_img_n);
    cudaGetSymbolAddress((void**)&title_n, g_title_n);
    cudaGetSymbolAddress((void**)&keff,    g_keff);
    cudaGetSymbolAddress((void**)&ctxb,    g_ctx);
    cudaGetSymbolAddress((void**)&h1,      g_h1);
    cudaGetSymbolAddress((void**)&h1n,     g_h1n);

    // 1) LayerNorms for both streams
    ln_kernel<<<BS, 256>>>(hidden_img, a_img, b_img, img_n);
    ln_kernel<<<BS, 256>>>(hidden_title, a_title, b_title, title_n);

    // 2) keff = title_n @ Wb^T + bb + img_n  (folds q.k + q.k_b into q.keff)
    dim3 gg(Dsz / GBN, BS / GBM);
    gemm_tf32<0><<<gg, 256>>>(title_n, Wb, bb, img_n, nullptr, keff);

    // 3) attention (tensor cores)
    const int smem_bytes = (SPAD * QSTR * 2 + 8 * 16 * SBSTR + SPAD) * 4;
    cudaFuncSetAttribute(attn_wmma,
                         cudaFuncAttributeMaxDynamicSharedMemorySize, smem_bytes);
    attn_wmma<<<Bsz * Hsz, 256, smem_bytes>>>(img_n, keff, mask, sattn, ctxb);

    // 4) h1 = ctx @ Wo^T + bo + hidden_img
    gemm_tf32<0><<<gg, 256>>>(ctxb, Wo, bo, hidden_img, nullptr, h1);

    // 5) h1_n = LN(h1)
    ln_kernel<<<BS, 256>>>(h1, a_out, b_out, h1n);

    // 6) out = h1 + gelu_tanh(scale_ffn * (h1_n @ W1^T + b1))
    gemm_tf32<2><<<gg, 256>>>(h1n, W1, b1, h1, sffn, out);
}

// round 4
// speedup vs baseline: 1.4521x; 1.4521x over previous
#include <cuda_runtime.h>
#include <math.h>
#include <mma.h>
#include <stdint.h>

using namespace nvcuda;

#define Bsz 256
#define Ssz 200
#define Dsz 256
#define Hsz 8
#define DHsz 32
#define BS (Bsz * Ssz)   // 51200 rows

__device__ float g_img_n[BS * Dsz];
__device__ float g_title_n[BS * Dsz];
__device__ float g_keff[BS * Dsz];
__device__ float g_ctx[BS * Dsz];
__device__ float g_h1[BS * Dsz];
__device__ float g_h1n[BS * Dsz];

__device__ __forceinline__ float to_tf32(float x) {
    float r;
    asm("cvt.rna.tf32.f32 %0, %1;" : "=f"(r) : "f"(x));
    return r;
}

__device__ __forceinline__ void mma_tf32(float* c, const float* a,
                                         float b0, float b1) {
    uint32_t const* ai = reinterpret_cast<uint32_t const*>(a);
    uint32_t bi0 = __float_as_uint(b0), bi1 = __float_as_uint(b1);
    asm volatile(
        "mma.sync.aligned.m16n8k8.row.col.f32.tf32.tf32.f32 "
        "{%0,%1,%2,%3}, {%4,%5,%6,%7}, {%8,%9}, {%0,%1,%2,%3};"
        : "+f"(c[0]), "+f"(c[1]), "+f"(c[2]), "+f"(c[3])
        : "r"(ai[0]), "r"(ai[1]), "r"(ai[2]), "r"(ai[3]), "r"(bi0), "r"(bi1));
}

// ---------------------------------------------------------------------------
// LayerNorm (torch variant: unbiased var, eps added to std)
// ---------------------------------------------------------------------------
__global__ void __launch_bounds__(256) ln_kernel(
    const float* __restrict__ x, const float* __restrict__ ga,
    const float* __restrict__ gb, float* __restrict__ y) {
    __shared__ float sm[8];
    int row = blockIdx.x;
    int t = threadIdx.x;
    int w = t >> 5, lane = t & 31;
    size_t off = (size_t)row * Dsz + t;
    float v = x[off];

    float s = v;
#pragma unroll
    for (int o = 16; o; o >>= 1) s += __shfl_xor_sync(0xffffffffu, s, o);
    if (lane == 0) sm[w] = s;
    __syncthreads();
    if (w == 0) {
        float x8 = (lane < 8) ? sm[lane] : 0.f;
#pragma unroll
        for (int o = 4; o; o >>= 1) x8 += __shfl_xor_sync(0xffffffffu, x8, o);
        if (lane == 0) sm[0] = x8;
    }
    __syncthreads();
    float mean = sm[0] * (1.0f / Dsz);
    __syncthreads();

    float d = v - mean;
    float ss = d * d;
#pragma unroll
    for (int o = 16; o; o >>= 1) ss += __shfl_xor_sync(0xffffffffu, ss, o);
    if (lane == 0) sm[w] = ss;
    __syncthreads();
    if (w == 0) {
        float x8 = (lane < 8) ? sm[lane] : 0.f;
#pragma unroll
        for (int o = 4; o; o >>= 1) x8 += __shfl_xor_sync(0xffffffffu, x8, o);
        if (lane == 0) sm[0] = x8;
    }
    __syncthreads();
    float var = sm[0] * (1.0f / (Dsz - 1));
    float inv = 1.0f / (sqrtf(var) + 1e-6f);
    y[off] = ga[t] * d * inv + gb[t];
}

// ---------------------------------------------------------------------------
// TF32 GEMM, 128x128 tile, BK=32, 256 thr (8 warps = 4m x 2n, warp 32x64).
// Inputs tf32-rounded at staging (exactly once). Register-prefetch dbuf.
// EPI==0: out = A.W^T + bias + add
// EPI==2: z = sffn[m%S]*(A.W^T + bias); out = add + gelu_tanh(z)
// ---------------------------------------------------------------------------
#define GBM 128
#define GBN 128
#define GBK 32
#define ASTR 40
#define CSTR 72

template <int EPI>
__global__ void __launch_bounds__(256) gemm_tf32(
    const float* __restrict__ A, const float* __restrict__ W,
    const float* __restrict__ bias, const float* __restrict__ add,
    const float* __restrict__ sffn, float* __restrict__ out) {
    __shared__ float sh[2 * GBM * ASTR];       // 40.96 KB
    float* As = sh;                             // [128][40]
    float* Ws = sh + GBM * ASTR;                // [128][40]
    float* Cs = sh;                             // [128][72] reuse (36.9KB)

    int m0 = blockIdx.y * GBM;
    int n0 = blockIdx.x * GBN;
    int tid = threadIdx.x;
    int wid = tid >> 5;
    int wm = wid >> 1;          // 0..3
    int wn = wid & 1;           // 0..1
    int lr = tid >> 3;          // 0..31
    int lc = (tid & 7) * 4;     // 0..28

    wmma::fragment<wmma::accumulator, 16, 16, 8, float> cf[2][4];
#pragma unroll
    for (int i = 0; i < 2; i++)
#pragma unroll
        for (int j = 0; j < 4; j++) wmma::fill_fragment(cf[i][j], 0.0f);

    float4 pa[4], pw[4];
#pragma unroll
    for (int t = 0; t < 4; t++) {
        pa[t] = *reinterpret_cast<const float4*>(
            A + (size_t)(m0 + lr + 32 * t) * Dsz + lc);
        pw[t] = *reinterpret_cast<const float4*>(
            W + (size_t)(n0 + lr + 32 * t) * Dsz + lc);
    }

    for (int k0 = 0; k0 < Dsz; k0 += GBK) {
#pragma unroll
        for (int t = 0; t < 4; t++) {
            float4 a = pa[t], w4 = pw[t];
            a.x = to_tf32(a.x); a.y = to_tf32(a.y);
            a.z = to_tf32(a.z); a.w = to_tf32(a.w);
            w4.x = to_tf32(w4.x); w4.y = to_tf32(w4.y);
            w4.z = to_tf32(w4.z); w4.w = to_tf32(w4.w);
            *reinterpret_cast<float4*>(As + (lr + 32 * t) * ASTR + lc) = a;
            *reinterpret_cast<float4*>(Ws + (lr + 32 * t) * ASTR + lc) = w4;
        }
        __syncthreads();

        if (k0 + GBK < Dsz) {
#pragma unroll
            for (int t = 0; t < 4; t++) {
                pa[t] = *reinterpret_cast<const float4*>(
                    A + (size_t)(m0 + lr + 32 * t) * Dsz + k0 + GBK + lc);
                pw[t] = *reinterpret_cast<const float4*>(
                    W + (size_t)(n0 + lr + 32 * t) * Dsz + k0 + GBK + lc);
            }
        }

#pragma unroll
        for (int kk = 0; kk < GBK; kk += 8) {
            wmma::fragment<wmma::matrix_a, 16, 16, 8, wmma::precision::tf32,
                           wmma::row_major> af[2];
            wmma::fragment<wmma::matrix_b, 16, 16, 8, wmma::precision::tf32,
                           wmma::col_major> bf[4];
#pragma unroll
            for (int i = 0; i < 2; i++)
                wmma::load_matrix_sync(af[i],
                    As + (wm * 32 + i * 16) * ASTR + kk, ASTR);
#pragma unroll
            for (int j = 0; j < 4; j++)
                wmma::load_matrix_sync(bf[j],
                    Ws + (wn * 64 + j * 16) * ASTR + kk, ASTR);
#pragma unroll
            for (int i = 0; i < 2; i++)
#pragma unroll
                for (int j = 0; j < 4; j++)
                    wmma::mma_sync(cf[i][j], af[i], bf[j], cf[i][j]);
        }
        __syncthreads();
    }

    // two-phase epilogue through 128x64 smem tile
#pragma unroll
    for (int p = 0; p < 2; p++) {
        if (wn == p) {
#pragma unroll
            for (int i = 0; i < 2; i++)
#pragma unroll
                for (int j = 0; j < 4; j++)
                    wmma::store_matrix_sync(
                        Cs + (wm * 32 + i * 16) * CSTR + j * 16,
                        cf[i][j], CSTR, wmma::mem_row_major);
        }
        __syncthreads();
#pragma unroll
        for (int t = 0; t < 8; t++) {
            int idx = tid + 256 * t;
            int r = idx >> 4, c4 = (idx & 15) * 4;
            int m = m0 + r, n = n0 + p * 64 + c4;
            float4 cv = *reinterpret_cast<float4*>(Cs + r * CSTR + c4);
            float4 bv = *reinterpret_cast<const float4*>(bias + n);
            float4 adv = *reinterpret_cast<const float4*>(add + (size_t)m * Dsz + n);
            float rr[4] = {cv.x + bv.x, cv.y + bv.y, cv.z + bv.z, cv.w + bv.w};
            float ad[4] = {adv.x, adv.y, adv.z, adv.w};
            if (EPI == 0) {
#pragma unroll
                for (int j = 0; j < 4; j++) rr[j] += ad[j];
            } else {
                float sf = sffn[m % Ssz];
#pragma unroll
                for (int j = 0; j < 4; j++) {
                    float z = sf * rr[j];
                    float th = tanhf(0.79788456080286536f * (z + 0.044715f * z * z * z));
                    rr[j] = ad[j] + 0.5f * z * (1.0f + th);
                }
            }
            *reinterpret_cast<float4*>(out + (size_t)m * Dsz + n) =
                make_float4(rr[0], rr[1], rr[2], rr[3]);
        }
        __syncthreads();
    }
}

// ---------------------------------------------------------------------------
// Register flash-attention, raw PTX mma.m16n8k8.tf32.
// Block = (b,h), 256 thr. smem: QV (=img_n slice, tf32) + K (keff, tf32)
// + mask: ~61KB -> ~3 CTAs/SM. Each warp: one 16-query tile (warps 0-4 do a
// second). Online softmax in registers; P moved C-layout -> A-layout via
// 16 shuffles/tile (no smem round trip). V == Q buffer.
// ---------------------------------------------------------------------------
#define SPAD 208
#define QSTR 36

__global__ void __launch_bounds__(256) attn_flash(
    const float* __restrict__ img_n, const float* __restrict__ keff,
    const int* __restrict__ mask, const float* __restrict__ sattn,
    float* __restrict__ ctx) {
    extern __shared__ float smw[];
    float* QV = smw;                 // [208][36] tf32-rounded (Q and V)
    float* Ks = QV + SPAD * QSTR;    // [208][36] tf32-rounded
    float* m_s = Ks + SPAD * QSTR;   // [208] 1.0 = masked

    int b = blockIdx.x >> 3;
    int h = blockIdx.x & 7;
    int tid = threadIdx.x;
    size_t base = ((size_t)b * Ssz) * Dsz + h * DHsz;

    for (int idx = tid; idx < SPAD * 8; idx += 256) {
        int r = idx >> 3, c4 = (idx & 7) * 4;
        float4 qv = make_float4(0.f, 0.f, 0.f, 0.f);
        float4 kv = make_float4(0.f, 0.f, 0.f, 0.f);
        if (r < Ssz) {
            qv = *reinterpret_cast<const float4*>(img_n + base + (size_t)r * Dsz + c4);
            kv = *reinterpret_cast<const float4*>(keff + base + (size_t)r * Dsz + c4);
        }
        qv.x = to_tf32(qv.x); qv.y = to_tf32(qv.y);
        qv.z = to_tf32(qv.z); qv.w = to_tf32(qv.w);
        kv.x = to_tf32(kv.x); kv.y = to_tf32(kv.y);
        kv.z = to_tf32(kv.z); kv.w = to_tf32(kv.w);
        *reinterpret_cast<float4*>(QV + r * QSTR + c4) = qv;
        *reinterpret_cast<float4*>(Ks + r * QSTR + c4) = kv;
    }
    for (int k = tid; k < SPAD; k += 256)
        m_s[k] = (k >= Ssz || mask[b * Ssz + k] == 0) ? 1.f : 0.f;
    __syncthreads();

    int w = tid >> 5, lane = tid & 31;
    int grp = lane >> 2;       // 0..7 (row group)
    int qd = lane & 3;         // 0..3
    const float isq = 0.17677669529663687f;
    const unsigned FULL = 0xffffffffu;

    int ntile = (w < 5) ? 2 : 1;
    for (int it = 0; it < ntile; it++) {
        int qt = w + it * 8;               // 0..12
        int q0 = qt * 16;
        int qr0 = q0 + grp, qr1 = q0 + grp + 8;
        float f0 = (qr0 < Ssz) ? isq * sattn[h * Ssz + qr0] : 0.f;
        float f1 = (qr1 < Ssz) ? isq * sattn[h * Ssz + qr1] : 0.f;

        // Q A-frags (already tf32)
        float aq[4][4];
#pragma unroll
        for (int kk = 0; kk < 4; kk++) {
            aq[kk][0] = QV[qr0 * QSTR + kk * 8 + qd];
            aq[kk][1] = QV[qr1 * QSTR + kk * 8 + qd];
            aq[kk][2] = QV[qr0 * QSTR + kk * 8 + qd + 4];
            aq[kk][3] = QV[qr1 * QSTR + kk * 8 + qd + 4];
        }

        float m0 = -3.0e38f, m1 = -3.0e38f, l0 = 0.f, l1 = 0.f;
        float co[4][4];
#pragma unroll
        for (int n = 0; n < 4; n++)
#pragma unroll
            for (int e = 0; e < 4; e++) co[n][e] = 0.f;

        for (int nt = 0; nt < 13; nt++) {
            int key0 = nt * 16;
            // scores: two n8 C-frags
            float s[2][4] = {{0.f, 0.f, 0.f, 0.f}, {0.f, 0.f, 0.f, 0.f}};
#pragma unroll
            for (int n = 0; n < 2; n++) {
                int keyc = key0 + n * 8 + grp;
#pragma unroll
                for (int kk = 0; kk < 4; kk++) {
                    float b0 = Ks[keyc * QSTR + kk * 8 + qd];
                    float b1 = Ks[keyc * QSTR + kk * 8 + qd + 4];
                    mma_tf32(s[n], aq[kk], b0, b1);
                }
            }
            // scale + mask -> p values (C layout)
            float pv[2][4];
            float rm0 = -3.0e38f, rm1 = -3.0e38f;
#pragma unroll
            for (int n = 0; n < 2; n++) {
                int c = key0 + n * 8 + 2 * qd;
                float mk0 = m_s[c], mk1 = m_s[c + 1];
                float v0 = (mk0 != 0.f) ? -1e9f : s[n][0] * f0;
                float v1 = (mk1 != 0.f) ? -1e9f : s[n][1] * f0;
                float v2 = (mk0 != 0.f) ? -1e9f : s[n][2] * f1;
                float v3 = (mk1 != 0.f) ? -1e9f : s[n][3] * f1;
                pv[n][0] = v0; pv[n][1] = v1; pv[n][2] = v2; pv[n][3] = v3;
                rm0 = fmaxf(rm0, fmaxf(v0, v1));
                rm1 = fmaxf(rm1, fmaxf(v2, v3));
            }
            rm0 = fmaxf(rm0, __shfl_xor_sync(FULL, rm0, 1));
            rm0 = fmaxf(rm0, __shfl_xor_sync(FULL, rm0, 2));
            rm1 = fmaxf(rm1, __shfl_xor_sync(FULL, rm1, 1));
            rm1 = fmaxf(rm1, __shfl_xor_sync(FULL, rm1, 2));
            float nm0 = fmaxf(m0, rm0), nm1 = fmaxf(m1, rm1);
            float al0 = __expf(m0 - nm0), al1 = __expf(m1 - nm1);
            m0 = nm0; m1 = nm1;
            float ts0 = 0.f, ts1 = 0.f;
#pragma unroll
            for (int n = 0; n < 2; n++) {
                pv[n][0] = __expf(pv[n][0] - nm0);
                pv[n][1] = __expf(pv[n][1] - nm0);
                pv[n][2] = __expf(pv[n][2] - nm1);
                pv[n][3] = __expf(pv[n][3] - nm1);
                ts0 += pv[n][0] + pv[n][1];
                ts1 += pv[n][2] + pv[n][3];
            }
            ts0 += __shfl_xor_sync(FULL, ts0, 1);
            ts0 += __shfl_xor_sync(FULL, ts0, 2);
            ts1 += __shfl_xor_sync(FULL, ts1, 1);
            ts1 += __shfl_xor_sync(FULL, ts1, 2);
            l0 = l0 * al0 + ts0;
            l1 = l1 * al1 + ts1;
#pragma unroll
            for (int n = 0; n < 4; n++) {
                co[n][0] *= al0; co[n][1] *= al0;
                co[n][2] *= al1; co[n][3] *= al1;
            }
            // P (C layout) -> A frags via shuffles, then P.V
            int sl = (lane & ~3) | (qd >> 1);
            bool par = (qd & 1) != 0;
#pragma unroll
            for (int kk2 = 0; kk2 < 2; kk2++) {
                float ap[4];
                float u0 = __shfl_sync(FULL, pv[kk2][0], sl);
                float u1 = __shfl_sync(FULL, pv[kk2][1], sl);
                float u2 = __shfl_sync(FULL, pv[kk2][2], sl);
                float u3 = __shfl_sync(FULL, pv[kk2][3], sl);
                ap[0] = par ? u1 : u0;
                ap[1] = par ? u3 : u2;
                float w0 = __shfl_sync(FULL, pv[kk2][0], sl + 2);
                float w1 = __shfl_sync(FULL, pv[kk2][1], sl + 2);
                float w2 = __shfl_sync(FULL, pv[kk2][2], sl + 2);
                float w3 = __shfl_sync(FULL, pv[kk2][3], sl + 2);
                ap[2] = par ? w1 : w0;
                ap[3] = par ? w3 : w2;
                int kr0 = key0 + kk2 * 8 + qd;
#pragma unroll
                for (int n4 = 0; n4 < 4; n4++) {
                    float b0 = QV[kr0 * QSTR + n4 * 8 + grp];
                    float b1 = QV[(kr0 + 4) * QSTR + n4 * 8 + grp];
                    mma_tf32(co[n4], ap, b0, b1);
                }
            }
        }

        float inv0 = 1.f / l0, inv1 = 1.f / l1;
#pragma unroll
        for (int n4 = 0; n4 < 4; n4++) {
            if (qr0 < Ssz) {
                float2 v = make_float2(co[n4][0] * inv0, co[n4][1] * inv0);
                *reinterpret_cast<float2*>(
                    ctx + base + (size_t)qr0 * Dsz + n4 * 8 + 2 * qd) = v;
            }
            if (qr1 < Ssz) {
                float2 v = make_float2(co[n4][2] * inv1, co[n4][3] * inv1);
                *reinterpret_cast<float2*>(
                    ctx + base + (size_t)qr1 * Dsz + n4 * 8 + 2 * qd) = v;
            }
        }
    }
}

// ---------------------------------------------------------------------------
extern "C" void kernel_launch(void* const* d_in, const int* in_sizes, int n_in,
                              void* d_out, int out_size) {
    const float* hidden_img   = (const float*)d_in[0];
    const float* hidden_title = (const float*)d_in[1];
    const int*   mask         = (const int*)  d_in[2];
    const float* a_img   = (const float*)d_in[3];
    const float* b_img   = (const float*)d_in[4];
    const float* a_title = (const float*)d_in[5];
    const float* b_title = (const float*)d_in[6];
    const float* Wb      = (const float*)d_in[7];
    const float* bb      = (const float*)d_in[8];
    const float* Wo      = (const float*)d_in[9];
    const float* bo      = (const float*)d_in[10];
    const float* sattn   = (const float*)d_in[11];
    const float* a_out   = (const float*)d_in[12];
    const float* b_out   = (const float*)d_in[13];
    const float* W1      = (const float*)d_in[14];
    const float* b1      = (const float*)d_in[15];
    const float* sffn    = (const float*)d_in[16];
    float* out = (float*)d_out;

    float *img_n, *title_n, *keff, *ctxb, *h1, *h1n;
    cudaGetSymbolAddress((void**)&img_n,   g_img_n);
    cudaGetSymbolAddress((void**)&title_n, g_title_n);
    cudaGetSymbolAddress((void**)&keff,    g_keff);
    cudaGetSymbolAddress((void**)&ctxb,    g_ctx);
    cudaGetSymbolAddress((void**)&h1,      g_h1);
    cudaGetSymbolAddress((void**)&h1n,     g_h1n);

    ln_kernel<<<BS, 256>>>(hidden_img, a_img, b_img, img_n);
    ln_kernel<<<BS, 256>>>(hidden_title, a_title, b_title, title_n);

    dim3 gg(Dsz / GBN, BS / GBM);
    gemm_tf32<0><<<gg, 256>>>(title_n, Wb, bb, img_n, nullptr, keff);

    const int smem_bytes = (SPAD * QSTR * 2 + SPAD) * 4;
    cudaFuncSetAttribute(attn_flash,
                         cudaFuncAttributeMaxDynamicSharedMemorySize, smem_bytes);
    attn_flash<<<Bsz * Hsz, 256, smem_bytes>>>(img_n, keff, mask, sattn, ctxb);

    gemm_tf32<0><<<gg, 256>>>(ctxb, Wo, bo, hidden_img, nullptr, h1);

    ln_kernel<<<BS, 256>>>(h1, a_out, b_out, h1n);

    gemm_tf32<2><<<gg, 256>>>(h1n, W1, b1, h1, sffn, out);
}

// round 5
// speedup vs baseline: 2.1743x; 1.4974x over previous
#include <cuda_runtime.h>
#include <math.h>
#include <stdint.h>

#define Bsz 256
#define Ssz 200
#define Dsz 256
#define Hsz 8
#define DHsz 32
#define BS (Bsz * Ssz)   // 51200 rows

__device__ float g_img_n[BS * Dsz];
__device__ float g_title_n[BS * Dsz];
__device__ float g_keff[BS * Dsz];
__device__ float g_ctx[BS * Dsz];
__device__ float g_h1[BS * Dsz];
__device__ float g_h1n[BS * Dsz];

__device__ __forceinline__ float to_tf32(float x) {
    float r;
    asm("cvt.rna.tf32.f32 %0, %1;" : "=f"(r) : "f"(x));
    return r;
}

__device__ __forceinline__ void mma_tf32(float* c, const float* a,
                                         float b0, float b1) {
    uint32_t const* ai = reinterpret_cast<uint32_t const*>(a);
    uint32_t bi0 = __float_as_uint(b0), bi1 = __float_as_uint(b1);
    asm volatile(
        "mma.sync.aligned.m16n8k8.row.col.f32.tf32.tf32.f32 "
        "{%0,%1,%2,%3}, {%4,%5,%6,%7}, {%8,%9}, {%0,%1,%2,%3};"
        : "+f"(c[0]), "+f"(c[1]), "+f"(c[2]), "+f"(c[3])
        : "r"(ai[0]), "r"(ai[1]), "r"(ai[2]), "r"(ai[3]), "r"(bi0), "r"(bi1));
}

// ---------------------------------------------------------------------------
// Warp-per-row LayerNorm (torch variant: unbiased var, eps added to std).
// 8 rows per block, shuffle-only reductions, no __syncthreads.
// Dual-source: blocks [0,split) process stream 0, [split, grid) stream 1.
// ---------------------------------------------------------------------------
__global__ void __launch_bounds__(256) ln_fast(
    const float* __restrict__ x0, const float* __restrict__ ga0,
    const float* __restrict__ gb0, float* __restrict__ y0,
    const float* __restrict__ x1, const float* __restrict__ ga1,
    const float* __restrict__ gb1, float* __restrict__ y1, int split) {
    int blk = blockIdx.x;
    const float *x, *ga, *gb;
    float* y;
    int rowbase;
    if (blk < split) {
        x = x0; ga = ga0; gb = gb0; y = y0; rowbase = blk * 8;
    } else {
        x = x1; ga = ga1; gb = gb1; y = y1; rowbase = (blk - split) * 8;
    }
    int w = threadIdx.x >> 5, lane = threadIdx.x & 31;
    size_t row = rowbase + w;
    const float4* x4 = reinterpret_cast<const float4*>(x + row * Dsz);
    float4 v0 = x4[lane];
    float4 v1 = x4[lane + 32];

    float s = v0.x + v0.y + v0.z + v0.w + v1.x + v1.y + v1.z + v1.w;
#pragma unroll
    for (int o = 16; o; o >>= 1) s += __shfl_xor_sync(0xffffffffu, s, o);
    float mean = s * (1.0f / Dsz);

    float d0x = v0.x - mean, d0y = v0.y - mean, d0z = v0.z - mean, d0w = v0.w - mean;
    float d1x = v1.x - mean, d1y = v1.y - mean, d1z = v1.z - mean, d1w = v1.w - mean;
    float ss = d0x * d0x + d0y * d0y + d0z * d0z + d0w * d0w +
               d1x * d1x + d1y * d1y + d1z * d1z + d1w * d1w;
#pragma unroll
    for (int o = 16; o; o >>= 1) ss += __shfl_xor_sync(0xffffffffu, ss, o);
    float var = ss * (1.0f / (Dsz - 1));
    float inv = 1.0f / (sqrtf(var) + 1e-6f);

    const float4* ga4 = reinterpret_cast<const float4*>(ga);
    const float4* gb4 = reinterpret_cast<const float4*>(gb);
    float4 g0 = ga4[lane], g1 = ga4[lane + 32];
    float4 b0 = gb4[lane], b1 = gb4[lane + 32];
    float4 o0 = make_float4(g0.x * d0x * inv + b0.x, g0.y * d0y * inv + b0.y,
                            g0.z * d0z * inv + b0.z, g0.w * d0w * inv + b0.w);
    float4 o1 = make_float4(g1.x * d1x * inv + b1.x, g1.y * d1y * inv + b1.y,
                            g1.z * d1z * inv + b1.z, g1.w * d1w * inv + b1.w);
    float4* y4 = reinterpret_cast<float4*>(y + row * Dsz);
    y4[lane] = o0;
    y4[lane + 32] = o1;
}

// ---------------------------------------------------------------------------
// Raw-mma TF32 GEMM: out[m,n] = sum_k A[m,k]*W[n,k] + bias[n] (+ epilogue)
// Block 128x128, BK=32, 256 thr, 8 warps (4m x 2n), warp tile 32x64.
// Shared memory holds tiles in FRAGMENT ORDER:
//   A frag (mb 0..7, kb 0..3): 32 lanes x float4 (e0..e3 = mma A-frag regs)
//   B frag (nb 0..15, kb 0..3): 32 lanes x float2 (b0,b1 = mma B-frag regs)
// Hot loop: 1 LDS.128 per A frag, 1 LDS.64 per B frag, conflict-free.
// Epilogue: accumulators stored straight to gmem as float2 (C-frag layout).
// EPI==0: out = acc + bias + add
// EPI==2: z = sffn[m%S]*(acc+bias); out = add + gelu_tanh(z)
// ---------------------------------------------------------------------------
#define GBM 128
#define GBN 128
#define GBK 32

template <int EPI>
__global__ void __launch_bounds__(256) gemm_mma(
    const float* __restrict__ A, const float* __restrict__ W,
    const float* __restrict__ bias, const float* __restrict__ add,
    const float* __restrict__ sffn, float* __restrict__ out) {
    __shared__ float As[4096];   // 8 mb * 4 kb * 128 floats
    __shared__ float Bs[4096];   // 16 nb * 4 kb * 64 floats

    int m0 = blockIdx.y * GBM;
    int n0 = blockIdx.x * GBN;
    int tid = threadIdx.x;
    int wid = tid >> 5, lane = tid & 31;
    int wm = wid >> 1, wn = wid & 1;
    int grp = lane >> 2, qd = lane & 3;

    int lr = tid >> 3;                 // 0..31 (row group)
    int c4 = (tid & 7) * 4;            // 0..28 (k column group)
    int kb_s = c4 >> 3;                // frag k-block of this thread's columns
    int half_s = (c4 >> 2) & 1;        // low/high half of k8

    float acc[2][8][4];
#pragma unroll
    for (int i = 0; i < 2; i++)
#pragma unroll
        for (int n = 0; n < 8; n++)
#pragma unroll
            for (int e = 0; e < 4; e++) acc[i][n][e] = 0.f;

    float4 pa[4], pb[4];
#pragma unroll
    for (int t = 0; t < 4; t++) {
        pa[t] = *reinterpret_cast<const float4*>(
            A + (size_t)(m0 + lr + 32 * t) * Dsz + c4);
        pb[t] = *reinterpret_cast<const float4*>(
            W + (size_t)(n0 + lr + 32 * t) * Dsz + c4);
    }

    for (int k0 = 0; k0 < Dsz; k0 += GBK) {
        // scatter prefetched values into fragment-order smem (tf32-rounded)
#pragma unroll
        for (int t = 0; t < 4; t++) {
            int r = lr + 32 * t;
            int mb = r >> 4, ga_ = r & 7, hi = (r >> 3) & 1;
            float* da = As + (mb * 4 + kb_s) * 128 + ga_ * 16 + hi + 2 * half_s;
            da[0]  = to_tf32(pa[t].x);
            da[4]  = to_tf32(pa[t].y);
            da[8]  = to_tf32(pa[t].z);
            da[12] = to_tf32(pa[t].w);
            int nb = r >> 3, gb_ = r & 7;
            float* db = Bs + (nb * 4 + kb_s) * 64 + gb_ * 8 + half_s;
            db[0] = to_tf32(pb[t].x);
            db[2] = to_tf32(pb[t].y);
            db[4] = to_tf32(pb[t].z);
            db[6] = to_tf32(pb[t].w);
        }
        __syncthreads();

        if (k0 + GBK < Dsz) {
#pragma unroll
            for (int t = 0; t < 4; t++) {
                pa[t] = *reinterpret_cast<const float4*>(
                    A + (size_t)(m0 + lr + 32 * t) * Dsz + k0 + GBK + c4);
                pb[t] = *reinterpret_cast<const float4*>(
                    W + (size_t)(n0 + lr + 32 * t) * Dsz + k0 + GBK + c4);
            }
        }

#pragma unroll
        for (int kb = 0; kb < 4; kb++) {
            float4 af[2];
#pragma unroll
            for (int i = 0; i < 2; i++)
                af[i] = reinterpret_cast<const float4*>(As)
                            [((wm * 2 + i) * 4 + kb) * 32 + lane];
            float2 bf[8];
#pragma unroll
            for (int n = 0; n < 8; n++)
                bf[n] = reinterpret_cast<const float2*>(Bs)
                            [((wn * 8 + n) * 4 + kb) * 32 + lane];
#pragma unroll
            for (int i = 0; i < 2; i++)
#pragma unroll
                for (int n = 0; n < 8; n++)
                    mma_tf32(acc[i][n], reinterpret_cast<const float*>(&af[i]),
                             bf[n].x, bf[n].y);
        }
        __syncthreads();
    }

    // epilogue: C-frag layout -> float2 global stores
#pragma unroll
    for (int i = 0; i < 2; i++) {
        int mr0 = m0 + wm * 32 + i * 16 + grp;
        int mr1 = mr0 + 8;
        float sf0 = 0.f, sf1 = 0.f;
        if (EPI == 2) {
            sf0 = sffn[mr0 % Ssz];
            sf1 = sffn[mr1 % Ssz];
        }
#pragma unroll
        for (int n = 0; n < 8; n++) {
            int col = n0 + wn * 64 + n * 8 + 2 * qd;
            float2 bv = *reinterpret_cast<const float2*>(bias + col);
            float2 a0 = *reinterpret_cast<const float2*>(
                add + (size_t)mr0 * Dsz + col);
            float2 a1 = *reinterpret_cast<const float2*>(
                add + (size_t)mr1 * Dsz + col);
            float r00 = acc[i][n][0] + bv.x, r01 = acc[i][n][1] + bv.y;
            float r10 = acc[i][n][2] + bv.x, r11 = acc[i][n][3] + bv.y;
            if (EPI == 0) {
                r00 += a0.x; r01 += a0.y; r10 += a1.x; r11 += a1.y;
            } else {
                float z, th;
                z = sf0 * r00;
                th = tanhf(0.79788456080286536f * (z + 0.044715f * z * z * z));
                r00 = a0.x + 0.5f * z * (1.0f + th);
                z = sf0 * r01;
                th = tanhf(0.79788456080286536f * (z + 0.044715f * z * z * z));
                r01 = a0.y + 0.5f * z * (1.0f + th);
                z = sf1 * r10;
                th = tanhf(0.79788456080286536f * (z + 0.044715f * z * z * z));
                r10 = a1.x + 0.5f * z * (1.0f + th);
                z = sf1 * r11;
                th = tanhf(0.79788456080286536f * (z + 0.044715f * z * z * z));
                r11 = a1.y + 0.5f * z * (1.0f + th);
            }
            *reinterpret_cast<float2*>(out + (size_t)mr0 * Dsz + col) =
                make_float2(r00, r01);
            *reinterpret_cast<float2*>(out + (size_t)mr1 * Dsz + col) =
                make_float2(r10, r11);
        }
    }
}

// ---------------------------------------------------------------------------
// Register flash-attention, raw PTX mma.m16n8k8.tf32 (unchanged from R4).
// ---------------------------------------------------------------------------
#define SPAD 208
#define QSTR 36

__global__ void __launch_bounds__(256) attn_flash(
    const float* __restrict__ img_n, const float* __restrict__ keff,
    const int* __restrict__ mask, const float* __restrict__ sattn,
    float* __restrict__ ctx) {
    extern __shared__ float smw[];
    float* QV = smw;                 // [208][36] tf32-rounded (Q and V)
    float* Ks = QV + SPAD * QSTR;    // [208][36] tf32-rounded
    float* m_s = Ks + SPAD * QSTR;   // [208] 1.0 = masked

    int b = blockIdx.x >> 3;
    int h = blockIdx.x & 7;
    int tid = threadIdx.x;
    size_t base = ((size_t)b * Ssz) * Dsz + h * DHsz;

    for (int idx = tid; idx < SPAD * 8; idx += 256) {
        int r = idx >> 3, c4 = (idx & 7) * 4;
        float4 qv = make_float4(0.f, 0.f, 0.f, 0.f);
        float4 kv = make_float4(0.f, 0.f, 0.f, 0.f);
        if (r < Ssz) {
            qv = *reinterpret_cast<const float4*>(img_n + base + (size_t)r * Dsz + c4);
            kv = *reinterpret_cast<const float4*>(keff + base + (size_t)r * Dsz + c4);
        }
        qv.x = to_tf32(qv.x); qv.y = to_tf32(qv.y);
        qv.z = to_tf32(qv.z); qv.w = to_tf32(qv.w);
        kv.x = to_tf32(kv.x); kv.y = to_tf32(kv.y);
        kv.z = to_tf32(kv.z); kv.w = to_tf32(kv.w);
        *reinterpret_cast<float4*>(QV + r * QSTR + c4) = qv;
        *reinterpret_cast<float4*>(Ks + r * QSTR + c4) = kv;
    }
    for (int k = tid; k < SPAD; k += 256)
        m_s[k] = (k >= Ssz || mask[b * Ssz + k] == 0) ? 1.f : 0.f;
    __syncthreads();

    int w = tid >> 5, lane = tid & 31;
    int grp = lane >> 2;
    int qd = lane & 3;
    const float isq = 0.17677669529663687f;
    const unsigned FULL = 0xffffffffu;

    int ntile = (w < 5) ? 2 : 1;
    for (int it = 0; it < ntile; it++) {
        int qt = w + it * 8;
        int q0 = qt * 16;
        int qr0 = q0 + grp, qr1 = q0 + grp + 8;
        float f0 = (qr0 < Ssz) ? isq * sattn[h * Ssz + qr0] : 0.f;
        float f1 = (qr1 < Ssz) ? isq * sattn[h * Ssz + qr1] : 0.f;

        float aq[4][4];
#pragma unroll
        for (int kk = 0; kk < 4; kk++) {
            aq[kk][0] = QV[qr0 * QSTR + kk * 8 + qd];
            aq[kk][1] = QV[qr1 * QSTR + kk * 8 + qd];
            aq[kk][2] = QV[qr0 * QSTR + kk * 8 + qd + 4];
            aq[kk][3] = QV[qr1 * QSTR + kk * 8 + qd + 4];
        }

        float m0 = -3.0e38f, m1 = -3.0e38f, l0 = 0.f, l1 = 0.f;
        float co[4][4];
#pragma unroll
        for (int n = 0; n < 4; n++)
#pragma unroll
            for (int e = 0; e < 4; e++) co[n][e] = 0.f;

        for (int nt = 0; nt < 13; nt++) {
            int key0 = nt * 16;
            float s[2][4] = {{0.f, 0.f, 0.f, 0.f}, {0.f, 0.f, 0.f, 0.f}};
#pragma unroll
            for (int n = 0; n < 2; n++) {
                int keyc = key0 + n * 8 + grp;
#pragma unroll
                for (int kk = 0; kk < 4; kk++) {
                    float b0 = Ks[keyc * QSTR + kk * 8 + qd];
                    float b1 = Ks[keyc * QSTR + kk * 8 + qd + 4];
                    mma_tf32(s[n], aq[kk], b0, b1);
                }
            }
            float pv[2][4];
            float rm0 = -3.0e38f, rm1 = -3.0e38f;
#pragma unroll
            for (int n = 0; n < 2; n++) {
                int c = key0 + n * 8 + 2 * qd;
                float mk0 = m_s[c], mk1 = m_s[c + 1];
                float v0 = (mk0 != 0.f) ? -1e9f : s[n][0] * f0;
                float v1 = (mk1 != 0.f) ? -1e9f : s[n][1] * f0;
                float v2 = (mk0 != 0.f) ? -1e9f : s[n][2] * f1;
                float v3 = (mk1 != 0.f) ? -1e9f : s[n][3] * f1;
                pv[n][0] = v0; pv[n][1] = v1; pv[n][2] = v2; pv[n][3] = v3;
                rm0 = fmaxf(rm0, fmaxf(v0, v1));
                rm1 = fmaxf(rm1, fmaxf(v2, v3));
            }
            rm0 = fmaxf(rm0, __shfl_xor_sync(FULL, rm0, 1));
            rm0 = fmaxf(rm0, __shfl_xor_sync(FULL, rm0, 2));
            rm1 = fmaxf(rm1, __shfl_xor_sync(FULL, rm1, 1));
            rm1 = fmaxf(rm1, __shfl_xor_sync(FULL, rm1, 2));
            float nm0 = fmaxf(m0, rm0), nm1 = fmaxf(m1, rm1);
            float al0 = __expf(m0 - nm0), al1 = __expf(m1 - nm1);
            m0 = nm0; m1 = nm1;
            float ts0 = 0.f, ts1 = 0.f;
#pragma unroll
            for (int n = 0; n < 2; n++) {
                pv[n][0] = __expf(pv[n][0] - nm0);
                pv[n][1] = __expf(pv[n][1] - nm0);
                pv[n][2] = __expf(pv[n][2] - nm1);
                pv[n][3] = __expf(pv[n][3] - nm1);
                ts0 += pv[n][0] + pv[n][1];
                ts1 += pv[n][2] + pv[n][3];
            }
            ts0 += __shfl_xor_sync(FULL, ts0, 1);
            ts0 += __shfl_xor_sync(FULL, ts0, 2);
            ts1 += __shfl_xor_sync(FULL, ts1, 1);
            ts1 += __shfl_xor_sync(FULL, ts1, 2);
            l0 = l0 * al0 + ts0;
            l1 = l1 * al1 + ts1;
#pragma unroll
            for (int n = 0; n < 4; n++) {
                co[n][0] *= al0; co[n][1] *= al0;
                co[n][2] *= al1; co[n][3] *= al1;
            }
            int sl = (lane & ~3) | (qd >> 1);
            bool par = (qd & 1) != 0;
#pragma unroll
            for (int kk2 = 0; kk2 < 2; kk2++) {
                float ap[4];
                float u0 = __shfl_sync(FULL, pv[kk2][0], sl);
                float u1 = __shfl_sync(FULL, pv[kk2][1], sl);
                float u2 = __shfl_sync(FULL, pv[kk2][2], sl);
                float u3 = __shfl_sync(FULL, pv[kk2][3], sl);
                ap[0] = par ? u1 : u0;
                ap[1] = par ? u3 : u2;
                float w0 = __shfl_sync(FULL, pv[kk2][0], sl + 2);
                float w1 = __shfl_sync(FULL, pv[kk2][1], sl + 2);
                float w2 = __shfl_sync(FULL, pv[kk2][2], sl + 2);
                float w3 = __shfl_sync(FULL, pv[kk2][3], sl + 2);
                ap[2] = par ? w1 : w0;
                ap[3] = par ? w3 : w2;
                int kr0 = key0 + kk2 * 8 + qd;
#pragma unroll
                for (int n4 = 0; n4 < 4; n4++) {
                    float b0 = QV[kr0 * QSTR + n4 * 8 + grp];
                    float b1 = QV[(kr0 + 4) * QSTR + n4 * 8 + grp];
                    mma_tf32(co[n4], ap, b0, b1);
                }
            }
        }

        float inv0 = 1.f / l0, inv1 = 1.f / l1;
#pragma unroll
        for (int n4 = 0; n4 < 4; n4++) {
            if (qr0 < Ssz) {
                float2 v = make_float2(co[n4][0] * inv0, co[n4][1] * inv0);
                *reinterpret_cast<float2*>(
                    ctx + base + (size_t)qr0 * Dsz + n4 * 8 + 2 * qd) = v;
            }
            if (qr1 < Ssz) {
                float2 v = make_float2(co[n4][2] * inv1, co[n4][3] * inv1);
                *reinterpret_cast<float2*>(
                    ctx + base + (size_t)qr1 * Dsz + n4 * 8 + 2 * qd) = v;
            }
        }
    }
}

// ---------------------------------------------------------------------------
extern "C" void kernel_launch(void* const* d_in, const int* in_sizes, int n_in,
                              void* d_out, int out_size) {
    const float* hidden_img   = (const float*)d_in[0];
    const float* hidden_title = (const float*)d_in[1];
    const int*   mask         = (const int*)  d_in[2];
    const float* a_img   = (const float*)d_in[3];
    const float* b_img   = (const float*)d_in[4];
    const float* a_title = (const float*)d_in[5];
    const float* b_title = (const float*)d_in[6];
    const float* Wb      = (const float*)d_in[7];
    const float* bb      = (const float*)d_in[8];
    const float* Wo      = (const float*)d_in[9];
    const float* bo      = (const float*)d_in[10];
    const float* sattn   = (const float*)d_in[11];
    const float* a_out   = (const float*)d_in[12];
    const float* b_out   = (const float*)d_in[13];
    const float* W1      = (const float*)d_in[14];
    const float* b1      = (const float*)d_in[15];
    const float* sffn    = (const float*)d_in[16];
    float* out = (float*)d_out;

    float *img_n, *title_n, *keff, *ctxb, *h1, *h1n;
    cudaGetSymbolAddress((void**)&img_n,   g_img_n);
    cudaGetSymbolAddress((void**)&title_n, g_title_n);
    cudaGetSymbolAddress((void**)&keff,    g_keff);
    cudaGetSymbolAddress((void**)&ctxb,    g_ctx);
    cudaGetSymbolAddress((void**)&h1,      g_h1);
    cudaGetSymbolAddress((void**)&h1n,     g_h1n);

    const int LNB = BS / 8;  // 6400 row-blocks per tensor

    // 1) both input LayerNorms in one launch
    ln_fast<<<2 * LNB, 256>>>(hidden_img, a_img, b_img, img_n,
                              hidden_title, a_title, b_title, title_n, LNB);

    // 2) keff = title_n @ Wb^T + bb + img_n
    dim3 gg(Dsz / GBN, BS / GBM);
    gemm_mma<0><<<gg, 256>>>(title_n, Wb, bb, img_n, nullptr, keff);

    // 3) attention (register flash, tf32 mma)
    const int smem_bytes = (SPAD * QSTR * 2 + SPAD) * 4;
    cudaFuncSetAttribute(attn_flash,
                         cudaFuncAttributeMaxDynamicSharedMemorySize, smem_bytes);
    attn_flash<<<Bsz * Hsz, 256, smem_bytes>>>(img_n, keff, mask, sattn, ctxb);

    // 4) h1 = ctx @ Wo^T + bo + hidden_img
    gemm_mma<0><<<gg, 256>>>(ctxb, Wo, bo, hidden_img, nullptr, h1);

    // 5) h1_n = LN(h1)
    ln_fast<<<LNB, 256>>>(h1, a_out, b_out, h1n,
                          h1, a_out, b_out, h1n, LNB);

    // 6) out = h1 + gelu_tanh(scale_ffn * (h1_n @ W1^T + b1))
    gemm_mma<2><<<gg, 256>>>(h1n, W1, b1, h1, sffn, out);
}

// round 6
// speedup vs baseline: 2.8150x; 1.2947x over previous
#include <cuda_runtime.h>
#include <math.h>
#include <stdint.h>

#define Bsz 256
#define Ssz 200
#define Dsz 256
#define Hsz 8
#define DHsz 32
#define BS (Bsz * Ssz)   // 51200 rows

__device__ float g_img_n[BS * Dsz];
__device__ float g_title_n[BS * Dsz];
__device__ float g_keff[BS * Dsz];
__device__ float g_ctx[BS * Dsz];
__device__ float g_h1[BS * Dsz];
__device__ float g_h1n[BS * Dsz];

__device__ __forceinline__ float to_tf32(float x) {
    float r;
    asm("cvt.rna.tf32.f32 %0, %1;" : "=f"(r) : "f"(x));
    return r;
}

__device__ __forceinline__ void mma_tf32(float* c, const float* a,
                                         float b0, float b1) {
    uint32_t const* ai = reinterpret_cast<uint32_t const*>(a);
    uint32_t bi0 = __float_as_uint(b0), bi1 = __float_as_uint(b1);
    asm volatile(
        "mma.sync.aligned.m16n8k8.row.col.f32.tf32.tf32.f32 "
        "{%0,%1,%2,%3}, {%4,%5,%6,%7}, {%8,%9}, {%0,%1,%2,%3};"
        : "+f"(c[0]), "+f"(c[1]), "+f"(c[2]), "+f"(c[3])
        : "r"(ai[0]), "r"(ai[1]), "r"(ai[2]), "r"(ai[3]), "r"(bi0), "r"(bi1));
}

__device__ __forceinline__ void ldsm_x4(uint32_t& r0, uint32_t& r1,
                                        uint32_t& r2, uint32_t& r3,
                                        uint32_t addr) {
    asm volatile(
        "ldmatrix.sync.aligned.m8n8.x4.shared.b16 {%0,%1,%2,%3}, [%4];"
        : "=r"(r0), "=r"(r1), "=r"(r2), "=r"(r3) : "r"(addr));
}

__device__ __forceinline__ void cp_async16(uint32_t smem, const void* g) {
    asm volatile("cp.async.cg.shared.global [%0], [%1], 16;"
                 :: "r"(smem), "l"(g));
}

// ---------------------------------------------------------------------------
// Warp-per-row LayerNorm (torch variant). 8 rows/block, shuffle-only.
// ---------------------------------------------------------------------------
__global__ void __launch_bounds__(256) ln_fast(
    const float* __restrict__ x0, const float* __restrict__ ga0,
    const float* __restrict__ gb0, float* __restrict__ y0,
    const float* __restrict__ x1, const float* __restrict__ ga1,
    const float* __restrict__ gb1, float* __restrict__ y1, int split) {
    int blk = blockIdx.x;
    const float *x, *ga, *gb;
    float* y;
    int rowbase;
    if (blk < split) {
        x = x0; ga = ga0; gb = gb0; y = y0; rowbase = blk * 8;
    } else {
        x = x1; ga = ga1; gb = gb1; y = y1; rowbase = (blk - split) * 8;
    }
    int w = threadIdx.x >> 5, lane = threadIdx.x & 31;
    size_t row = rowbase + w;
    const float4* x4 = reinterpret_cast<const float4*>(x + row * Dsz);
    float4 v0 = x4[lane];
    float4 v1 = x4[lane + 32];

    float s = v0.x + v0.y + v0.z + v0.w + v1.x + v1.y + v1.z + v1.w;
#pragma unroll
    for (int o = 16; o; o >>= 1) s += __shfl_xor_sync(0xffffffffu, s, o);
    float mean = s * (1.0f / Dsz);

    float d0x = v0.x - mean, d0y = v0.y - mean, d0z = v0.z - mean, d0w = v0.w - mean;
    float d1x = v1.x - mean, d1y = v1.y - mean, d1z = v1.z - mean, d1w = v1.w - mean;
    float ss = d0x * d0x + d0y * d0y + d0z * d0z + d0w * d0w +
               d1x * d1x + d1y * d1y + d1z * d1z + d1w * d1w;
#pragma unroll
    for (int o = 16; o; o >>= 1) ss += __shfl_xor_sync(0xffffffffu, ss, o);
    float var = ss * (1.0f / (Dsz - 1));
    float inv = 1.0f / (sqrtf(var) + 1e-6f);

    const float4* ga4 = reinterpret_cast<const float4*>(ga);
    const float4* gb4 = reinterpret_cast<const float4*>(gb);
    float4 g0 = ga4[lane], g1 = ga4[lane + 32];
    float4 b0 = gb4[lane], b1 = gb4[lane + 32];
    float4 o0 = make_float4(g0.x * d0x * inv + b0.x, g0.y * d0y * inv + b0.y,
                            g0.z * d0z * inv + b0.z, g0.w * d0w * inv + b0.w);
    float4 o1 = make_float4(g1.x * d1x * inv + b1.x, g1.y * d1y * inv + b1.y,
                            g1.z * d1z * inv + b1.z, g1.w * d1w * inv + b1.w);
    float4* y4 = reinterpret_cast<float4*>(y + row * Dsz);
    y4[lane] = o0;
    y4[lane + 32] = o1;
}

// ---------------------------------------------------------------------------
// TF32 GEMM: cp.async 2-stage pipeline + ldmatrix fragment loads.
// Block 128x128, BK=32, 256 thr, 8 warps (4m x 2n), warp tile 32x64.
// smem: row-major tiles, stride 36 floats (conflict-free ldmatrix + staging).
// fp32 bits fed to tf32 mma (HW truncation; within error budget).
// EPI==0: out = acc + bias + add
// EPI==2: z = sffn[m%S]*(acc+bias); out = add + gelu_tanh(z)
// ---------------------------------------------------------------------------
#define GBM 128
#define GBN 128
#define GBK 32
#define TSTR 36
#define TILE_F (128 * TSTR)            // floats per tile
#define STAGE_B (2 * TILE_F * 4)       // bytes per stage (A+B)

template <int EPI>
__global__ void __launch_bounds__(256) gemm_mma(
    const float* __restrict__ A, const float* __restrict__ W,
    const float* __restrict__ bias, const float* __restrict__ add,
    const float* __restrict__ sffn, float* __restrict__ out) {
    extern __shared__ float gsm[];
    uint32_t smemU = (uint32_t)__cvta_generic_to_shared(gsm);

    int m0 = blockIdx.y * GBM;
    int n0 = blockIdx.x * GBN;
    int tid = threadIdx.x;
    int wid = tid >> 5, lane = tid & 31;
    int wm = wid >> 1, wn = wid & 1;
    int grp = lane >> 2, qd = lane & 3;

    int lr = tid >> 3;                 // 0..31
    int c4 = (tid & 7) * 4;            // 0..28

    // ldmatrix per-lane addresses (float offsets within tile)
    int rowA = wm * 32 + (lane & 7) + ((lane >> 3) & 1) * 8;
    int offA = rowA * TSTR + ((lane >> 4) & 1) * 4;
    int rowB = wn * 64 + (lane & 7) + ((lane >> 4) & 1) * 8;
    int offB = rowB * TSTR + ((lane >> 3) & 1) * 4;

    float acc[2][8][4];
#pragma unroll
    for (int i = 0; i < 2; i++)
#pragma unroll
        for (int n = 0; n < 8; n++)
#pragma unroll
            for (int e = 0; e < 4; e++) acc[i][n][e] = 0.f;

    // stage copy helper (buf: 0/1, k0: k offset)
    auto stage = [&](int buf, int k0) {
        uint32_t sa = smemU + buf * STAGE_B;
        uint32_t sb = sa + TILE_F * 4;
#pragma unroll
        for (int t = 0; t < 4; t++) {
            int r = lr + 32 * t;
            cp_async16(sa + (r * TSTR + c4) * 4,
                       A + (size_t)(m0 + r) * Dsz + k0 + c4);
            cp_async16(sb + (r * TSTR + c4) * 4,
                       W + (size_t)(n0 + r) * Dsz + k0 + c4);
        }
    };

    stage(0, 0);
    asm volatile("cp.async.commit_group;");

    const int NSTEP = Dsz / GBK;  // 8
    for (int s = 0; s < NSTEP; s++) {
        if (s + 1 < NSTEP) {
            stage((s + 1) & 1, (s + 1) * GBK);
            asm volatile("cp.async.commit_group;");
            asm volatile("cp.async.wait_group 1;");
        } else {
            asm volatile("cp.async.wait_group 0;");
        }
        __syncthreads();

        uint32_t aB = smemU + (s & 1) * STAGE_B + offA * 4;
        uint32_t bB = smemU + (s & 1) * STAGE_B + TILE_F * 4 + offB * 4;
#pragma unroll
        for (int kb = 0; kb < 4; kb++) {
            uint32_t af[2][4];
#pragma unroll
            for (int i = 0; i < 2; i++)
                ldsm_x4(af[i][0], af[i][1], af[i][2], af[i][3],
                        aB + (i * 16 * TSTR + kb * 8) * 4);
            uint32_t bf[8][2];
#pragma unroll
            for (int p = 0; p < 4; p++) {
                uint32_t r0, r1, r2, r3;
                ldsm_x4(r0, r1, r2, r3, bB + (p * 16 * TSTR + kb * 8) * 4);
                bf[2 * p][0] = r0; bf[2 * p][1] = r1;
                bf[2 * p + 1][0] = r2; bf[2 * p + 1][1] = r3;
            }
#pragma unroll
            for (int i = 0; i < 2; i++)
#pragma unroll
                for (int n = 0; n < 8; n++)
                    mma_tf32(acc[i][n],
                             reinterpret_cast<const float*>(af[i]),
                             __uint_as_float(bf[n][0]),
                             __uint_as_float(bf[n][1]));
        }
        __syncthreads();
    }

    // epilogue: C-frag layout -> float2 global stores
#pragma unroll
    for (int i = 0; i < 2; i++) {
        int mr0 = m0 + wm * 32 + i * 16 + grp;
        int mr1 = mr0 + 8;
        float sf0 = 0.f, sf1 = 0.f;
        if (EPI == 2) {
            sf0 = sffn[mr0 % Ssz];
            sf1 = sffn[mr1 % Ssz];
        }
#pragma unroll
        for (int n = 0; n < 8; n++) {
            int col = n0 + wn * 64 + n * 8 + 2 * qd;
            float2 bv = *reinterpret_cast<const float2*>(bias + col);
            float2 a0 = *reinterpret_cast<const float2*>(
                add + (size_t)mr0 * Dsz + col);
            float2 a1 = *reinterpret_cast<const float2*>(
                add + (size_t)mr1 * Dsz + col);
            float r00 = acc[i][n][0] + bv.x, r01 = acc[i][n][1] + bv.y;
            float r10 = acc[i][n][2] + bv.x, r11 = acc[i][n][3] + bv.y;
            if (EPI == 0) {
                r00 += a0.x; r01 += a0.y; r10 += a1.x; r11 += a1.y;
            } else {
                float z, th;
                z = sf0 * r00;
                th = tanhf(0.79788456080286536f * (z + 0.044715f * z * z * z));
                r00 = a0.x + 0.5f * z * (1.0f + th);
                z = sf0 * r01;
                th = tanhf(0.79788456080286536f * (z + 0.044715f * z * z * z));
                r01 = a0.y + 0.5f * z * (1.0f + th);
                z = sf1 * r10;
                th = tanhf(0.79788456080286536f * (z + 0.044715f * z * z * z));
                r10 = a1.x + 0.5f * z * (1.0f + th);
                z = sf1 * r11;
                th = tanhf(0.79788456080286536f * (z + 0.044715f * z * z * z));
                r11 = a1.y + 0.5f * z * (1.0f + th);
            }
            *reinterpret_cast<float2*>(out + (size_t)mr0 * Dsz + col) =
                make_float2(r00, r01);
            *reinterpret_cast<float2*>(out + (size_t)mr1 * Dsz + col) =
                make_float2(r10, r11);
        }
    }
}

// ---------------------------------------------------------------------------
// Register flash-attention, raw PTX mma.m16n8k8.tf32 (unchanged, 148us).
// ---------------------------------------------------------------------------
#define SPAD 208
#define QSTR 36

__global__ void __launch_bounds__(256) attn_flash(
    const float* __restrict__ img_n, const float* __restrict__ keff,
    const int* __restrict__ mask, const float* __restrict__ sattn,
    float* __restrict__ ctx) {
    extern __shared__ float smw[];
    float* QV = smw;
    float* Ks = QV + SPAD * QSTR;
    float* m_s = Ks + SPAD * QSTR;

    int b = blockIdx.x >> 3;
    int h = blockIdx.x & 7;
    int tid = threadIdx.x;
    size_t base = ((size_t)b * Ssz) * Dsz + h * DHsz;

    for (int idx = tid; idx < SPAD * 8; idx += 256) {
        int r = idx >> 3, c4 = (idx & 7) * 4;
        float4 qv = make_float4(0.f, 0.f, 0.f, 0.f);
        float4 kv = make_float4(0.f, 0.f, 0.f, 0.f);
        if (r < Ssz) {
            qv = *reinterpret_cast<const float4*>(img_n + base + (size_t)r * Dsz + c4);
            kv = *reinterpret_cast<const float4*>(keff + base + (size_t)r * Dsz + c4);
        }
        qv.x = to_tf32(qv.x); qv.y = to_tf32(qv.y);
        qv.z = to_tf32(qv.z); qv.w = to_tf32(qv.w);
        kv.x = to_tf32(kv.x); kv.y = to_tf32(kv.y);
        kv.z = to_tf32(kv.z); kv.w = to_tf32(kv.w);
        *reinterpret_cast<float4*>(QV + r * QSTR + c4) = qv;
        *reinterpret_cast<float4*>(Ks + r * QSTR + c4) = kv;
    }
    for (int k = tid; k < SPAD; k += 256)
        m_s[k] = (k >= Ssz || mask[b * Ssz + k] == 0) ? 1.f : 0.f;
    __syncthreads();

    int w = tid >> 5, lane = tid & 31;
    int grp = lane >> 2;
    int qd = lane & 3;
    const float isq = 0.17677669529663687f;
    const unsigned FULL = 0xffffffffu;

    int ntile = (w < 5) ? 2 : 1;
    for (int it = 0; it < ntile; it++) {
        int qt = w + it * 8;
        int q0 = qt * 16;
        int qr0 = q0 + grp, qr1 = q0 + grp + 8;
        float f0 = (qr0 < Ssz) ? isq * sattn[h * Ssz + qr0] : 0.f;
        float f1 = (qr1 < Ssz) ? isq * sattn[h * Ssz + qr1] : 0.f;

        float aq[4][4];
#pragma unroll
        for (int kk = 0; kk < 4; kk++) {
            aq[kk][0] = QV[qr0 * QSTR + kk * 8 + qd];
            aq[kk][1] = QV[qr1 * QSTR + kk * 8 + qd];
            aq[kk][2] = QV[qr0 * QSTR + kk * 8 + qd + 4];
            aq[kk][3] = QV[qr1 * QSTR + kk * 8 + qd + 4];
        }

        float m0 = -3.0e38f, m1 = -3.0e38f, l0 = 0.f, l1 = 0.f;
        float co[4][4];
#pragma unroll
        for (int n = 0; n < 4; n++)
#pragma unroll
            for (int e = 0; e < 4; e++) co[n][e] = 0.f;

        for (int nt = 0; nt < 13; nt++) {
            int key0 = nt * 16;
            float s[2][4] = {{0.f, 0.f, 0.f, 0.f}, {0.f, 0.f, 0.f, 0.f}};
#pragma unroll
            for (int n = 0; n < 2; n++) {
                int keyc = key0 + n * 8 + grp;
#pragma unroll
                for (int kk = 0; kk < 4; kk++) {
                    float b0 = Ks[keyc * QSTR + kk * 8 + qd];
                    float b1 = Ks[keyc * QSTR + kk * 8 + qd + 4];
                    mma_tf32(s[n], aq[kk], b0, b1);
                }
            }
            float pv[2][4];
            float rm0 = -3.0e38f, rm1 = -3.0e38f;
#pragma unroll
            for (int n = 0; n < 2; n++) {
                int c = key0 + n * 8 + 2 * qd;
                float mk0 = m_s[c], mk1 = m_s[c + 1];
                float v0 = (mk0 != 0.f) ? -1e9f : s[n][0] * f0;
                float v1 = (mk1 != 0.f) ? -1e9f : s[n][1] * f0;
                float v2 = (mk0 != 0.f) ? -1e9f : s[n][2] * f1;
                float v3 = (mk1 != 0.f) ? -1e9f : s[n][3] * f1;
                pv[n][0] = v0; pv[n][1] = v1; pv[n][2] = v2; pv[n][3] = v3;
                rm0 = fmaxf(rm0, fmaxf(v0, v1));
                rm1 = fmaxf(rm1, fmaxf(v2, v3));
            }
            rm0 = fmaxf(rm0, __shfl_xor_sync(FULL, rm0, 1));
            rm0 = fmaxf(rm0, __shfl_xor_sync(FULL, rm0, 2));
            rm1 = fmaxf(rm1, __shfl_xor_sync(FULL, rm1, 1));
            rm1 = fmaxf(rm1, __shfl_xor_sync(FULL, rm1, 2));
            float nm0 = fmaxf(m0, rm0), nm1 = fmaxf(m1, rm1);
            float al0 = __expf(m0 - nm0), al1 = __expf(m1 - nm1);
            m0 = nm0; m1 = nm1;
            float ts0 = 0.f, ts1 = 0.f;
#pragma unroll
            for (int n = 0; n < 2; n++) {
                pv[n][0] = __expf(pv[n][0] - nm0);
                pv[n][1] = __expf(pv[n][1] - nm0);
                pv[n][2] = __expf(pv[n][2] - nm1);
                pv[n][3] = __expf(pv[n][3] - nm1);
                ts0 += pv[n][0] + pv[n][1];
                ts1 += pv[n][2] + pv[n][3];
            }
            ts0 += __shfl_xor_sync(FULL, ts0, 1);
            ts0 += __shfl_xor_sync(FULL, ts0, 2);
            ts1 += __shfl_xor_sync(FULL, ts1, 1);
            ts1 += __shfl_xor_sync(FULL, ts1, 2);
            l0 = l0 * al0 + ts0;
            l1 = l1 * al1 + ts1;
#pragma unroll
            for (int n = 0; n < 4; n++) {
                co[n][0] *= al0; co[n][1] *= al0;
                co[n][2] *= al1; co[n][3] *= al1;
            }
            int sl = (lane & ~3) | (qd >> 1);
            bool par = (qd & 1) != 0;
#pragma unroll
            for (int kk2 = 0; kk2 < 2; kk2++) {
                float ap[4];
                float u0 = __shfl_sync(FULL, pv[kk2][0], sl);
                float u1 = __shfl_sync(FULL, pv[kk2][1], sl);
                float u2 = __shfl_sync(FULL, pv[kk2][2], sl);
                float u3 = __shfl_sync(FULL, pv[kk2][3], sl);
                ap[0] = par ? u1 : u0;
                ap[1] = par ? u3 : u2;
                float w0 = __shfl_sync(FULL, pv[kk2][0], sl + 2);
                float w1 = __shfl_sync(FULL, pv[kk2][1], sl + 2);
                float w2 = __shfl_sync(FULL, pv[kk2][2], sl + 2);
                float w3 = __shfl_sync(FULL, pv[kk2][3], sl + 2);
                ap[2] = par ? w1 : w0;
                ap[3] = par ? w3 : w2;
                int kr0 = key0 + kk2 * 8 + qd;
#pragma unroll
                for (int n4 = 0; n4 < 4; n4++) {
                    float b0 = QV[kr0 * QSTR + n4 * 8 + grp];
                    float b1 = QV[(kr0 + 4) * QSTR + n4 * 8 + grp];
                    mma_tf32(co[n4], ap, b0, b1);
                }
            }
        }

        float inv0 = 1.f / l0, inv1 = 1.f / l1;
#pragma unroll
        for (int n4 = 0; n4 < 4; n4++) {
            if (qr0 < Ssz) {
                float2 v = make_float2(co[n4][0] * inv0, co[n4][1] * inv0);
                *reinterpret_cast<float2*>(
                    ctx + base + (size_t)qr0 * Dsz + n4 * 8 + 2 * qd) = v;
            }
            if (qr1 < Ssz) {
                float2 v = make_float2(co[n4][2] * inv1, co[n4][3] * inv1);
                *reinterpret_cast<float2*>(
                    ctx + base + (size_t)qr1 * Dsz + n4 * 8 + 2 * qd) = v;
            }
        }
    }
}

// ---------------------------------------------------------------------------
extern "C" void kernel_launch(void* const* d_in, const int* in_sizes, int n_in,
                              void* d_out, int out_size) {
    const float* hidden_img   = (const float*)d_in[0];
    const float* hidden_title = (const float*)d_in[1];
    const int*   mask         = (const int*)  d_in[2];
    const float* a_img   = (const float*)d_in[3];
    const float* b_img   = (const float*)d_in[4];
    const float* a_title = (const float*)d_in[5];
    const float* b_title = (const float*)d_in[6];
    const float* Wb      = (const float*)d_in[7];
    const float* bb      = (const float*)d_in[8];
    const float* Wo      = (const float*)d_in[9];
    const float* bo      = (const float*)d_in[10];
    const float* sattn   = (const float*)d_in[11];
    const float* a_out   = (const float*)d_in[12];
    const float* b_out   = (const float*)d_in[13];
    const float* W1      = (const float*)d_in[14];
    const float* b1      = (const float*)d_in[15];
    const float* sffn    = (const float*)d_in[16];
    float* out = (float*)d_out;

    float *img_n, *title_n, *keff, *ctxb, *h1, *h1n;
    cudaGetSymbolAddress((void**)&img_n,   g_img_n);
    cudaGetSymbolAddress((void**)&title_n, g_title_n);
    cudaGetSymbolAddress((void**)&keff,    g_keff);
    cudaGetSymbolAddress((void**)&ctxb,    g_ctx);
    cudaGetSymbolAddress((void**)&h1,      g_h1);
    cudaGetSymbolAddress((void**)&h1n,     g_h1n);

    const int LNB = BS / 8;
    const int gemm_smem = 2 * STAGE_B;   // 73728 bytes
    cudaFuncSetAttribute(gemm_mma<0>,
                         cudaFuncAttributeMaxDynamicSharedMemorySize, gemm_smem);
    cudaFuncSetAttribute(gemm_mma<2>,
                         cudaFuncAttributeMaxDynamicSharedMemorySize, gemm_smem);

    // 1) both input LayerNorms in one launch
    ln_fast<<<2 * LNB, 256>>>(hidden_img, a_img, b_img, img_n,
                              hidden_title, a_title, b_title, title_n, LNB);

    // 2) keff = title_n @ Wb^T + bb + img_n
    dim3 gg(Dsz / GBN, BS / GBM);
    gemm_mma<0><<<gg, 256, gemm_smem>>>(title_n, Wb, bb, img_n, nullptr, keff);

    // 3) attention (register flash, tf32 mma)
    const int smem_bytes = (SPAD * QSTR * 2 + SPAD) * 4;
    cudaFuncSetAttribute(attn_flash,
                         cudaFuncAttributeMaxDynamicSharedMemorySize, smem_bytes);
    attn_flash<<<Bsz * Hsz, 256, smem_bytes>>>(img_n, keff, mask, sattn, ctxb);

    // 4) h1 = ctx @ Wo^T + bo + hidden_img
    gemm_mma<0><<<gg, 256, gemm_smem>>>(ctxb, Wo, bo, hidden_img, nullptr, h1);

    // 5) h1_n = LN(h1)
    ln_fast<<<LNB, 256>>>(h1, a_out, b_out, h1n,
                          h1, a_out, b_out, h1n, LNB);

    // 6) out = h1 + gelu_tanh(scale_ffn * (h1_n @ W1^T + b1))
    gemm_mma<2><<<gg, 256, gemm_smem>>>(h1n, W1, b1, h1, sffn, out);
}

// round 7
// speedup vs baseline: 3.0787x; 1.0937x over previous
#include <cuda_runtime.h>
#include <math.h>
#include <stdint.h>

#define Bsz 256
#define Ssz 200
#define Dsz 256
#define Hsz 8
#define DHsz 32
#define BS (Bsz * Ssz)   // 51200 rows

__device__ float g_img_n[BS * Dsz];
__device__ float g_title_n[BS * Dsz];
__device__ float g_keff[BS * Dsz];
__device__ float g_ctx[BS * Dsz];
__device__ float g_h1[BS * Dsz];
__device__ float g_rsum[BS];
__device__ float g_rsumsq[BS];

__device__ __forceinline__ float to_tf32(float x) {
    float r;
    asm("cvt.rna.tf32.f32 %0, %1;" : "=f"(r) : "f"(x));
    return r;
}

__device__ __forceinline__ void mma_tf32(float* c, const float* a,
                                         float b0, float b1) {
    uint32_t const* ai = reinterpret_cast<uint32_t const*>(a);
    uint32_t bi0 = __float_as_uint(b0), bi1 = __float_as_uint(b1);
    asm volatile(
        "mma.sync.aligned.m16n8k8.row.col.f32.tf32.tf32.f32 "
        "{%0,%1,%2,%3}, {%4,%5,%6,%7}, {%8,%9}, {%0,%1,%2,%3};"
        : "+f"(c[0]), "+f"(c[1]), "+f"(c[2]), "+f"(c[3])
        : "r"(ai[0]), "r"(ai[1]), "r"(ai[2]), "r"(ai[3]), "r"(bi0), "r"(bi1));
}

__device__ __forceinline__ void ldsm_x4(uint32_t& r0, uint32_t& r1,
                                        uint32_t& r2, uint32_t& r3,
                                        uint32_t addr) {
    asm volatile(
        "ldmatrix.sync.aligned.m8n8.x4.shared.b16 {%0,%1,%2,%3}, [%4];"
        : "=r"(r0), "=r"(r1), "=r"(r2), "=r"(r3) : "r"(addr));
}

__device__ __forceinline__ void cp_async16(uint32_t smem, const void* g) {
    asm volatile("cp.async.cg.shared.global [%0], [%1], 16;"
                 :: "r"(smem), "l"(g));
}

// ---------------------------------------------------------------------------
// Warp-per-row LayerNorm (torch variant). 8 rows/block, shuffle-only.
// ---------------------------------------------------------------------------
__global__ void __launch_bounds__(256) ln_fast(
    const float* __restrict__ x0, const float* __restrict__ ga0,
    const float* __restrict__ gb0, float* __restrict__ y0,
    const float* __restrict__ x1, const float* __restrict__ ga1,
    const float* __restrict__ gb1, float* __restrict__ y1, int split) {
    int blk = blockIdx.x;
    const float *x, *ga, *gb;
    float* y;
    int rowbase;
    if (blk < split) {
        x = x0; ga = ga0; gb = gb0; y = y0; rowbase = blk * 8;
    } else {
        x = x1; ga = ga1; gb = gb1; y = y1; rowbase = (blk - split) * 8;
    }
    int w = threadIdx.x >> 5, lane = threadIdx.x & 31;
    size_t row = rowbase + w;
    const float4* x4 = reinterpret_cast<const float4*>(x + row * Dsz);
    float4 v0 = x4[lane];
    float4 v1 = x4[lane + 32];

    float s = v0.x + v0.y + v0.z + v0.w + v1.x + v1.y + v1.z + v1.w;
#pragma unroll
    for (int o = 16; o; o >>= 1) s += __shfl_xor_sync(0xffffffffu, s, o);
    float mean = s * (1.0f / Dsz);

    float d0x = v0.x - mean, d0y = v0.y - mean, d0z = v0.z - mean, d0w = v0.w - mean;
    float d1x = v1.x - mean, d1y = v1.y - mean, d1z = v1.z - mean, d1w = v1.w - mean;
    float ss = d0x * d0x + d0y * d0y + d0z * d0z + d0w * d0w +
               d1x * d1x + d1y * d1y + d1z * d1z + d1w * d1w;
#pragma unroll
    for (int o = 16; o; o >>= 1) ss += __shfl_xor_sync(0xffffffffu, ss, o);
    float var = ss * (1.0f / (Dsz - 1));
    float inv = 1.0f / (sqrtf(var) + 1e-6f);

    const float4* ga4 = reinterpret_cast<const float4*>(ga);
    const float4* gb4 = reinterpret_cast<const float4*>(gb);
    float4 g0 = ga4[lane], g1 = ga4[lane + 32];
    float4 b0 = gb4[lane], b1 = gb4[lane + 32];
    float4 o0 = make_float4(g0.x * d0x * inv + b0.x, g0.y * d0y * inv + b0.y,
                            g0.z * d0z * inv + b0.z, g0.w * d0w * inv + b0.w);
    float4 o1 = make_float4(g1.x * d1x * inv + b1.x, g1.y * d1y * inv + b1.y,
                            g1.z * d1z * inv + b1.z, g1.w * d1w * inv + b1.w);
    float4* y4 = reinterpret_cast<float4*>(y + row * Dsz);
    y4[lane] = o0;
    y4[lane + 32] = o1;
}

// ---------------------------------------------------------------------------
// TF32 GEMM: cp.async/LDG staging + ldmatrix fragment loads, 2-stage pipeline.
// Block 128x128, BK=32, 256 thr, 8 warps (4m x 2n), warp tile 32x64.
// EPI==0: out = acc + bias + add          (STATS: also row-sum/sumsq atomics)
// EPI==2: A normalized on the fly: a=(A[r,k]-mean[r])*inv[r]*ga[k]+gb[k]
//         z = sffn[m%S]*(acc+bias); out = add + gelu_tanh(z)
// ---------------------------------------------------------------------------
#define GBM 128
#define GBN 128
#define GBK 32
#define TSTR 36
#define TILE_F (128 * TSTR)
#define STAGE_B (2 * TILE_F * 4)

template <int EPI, bool STATS>
__global__ void __launch_bounds__(256) gemm_mma(
    const float* __restrict__ A, const float* __restrict__ W,
    const float* __restrict__ bias, const float* __restrict__ add,
    const float* __restrict__ sffn, float* __restrict__ out,
    const float* __restrict__ lga, const float* __restrict__ lgb,
    float* __restrict__ rsum, float* __restrict__ rsumsq) {
    extern __shared__ float gsm[];
    uint32_t smemU = (uint32_t)__cvta_generic_to_shared(gsm);

    int m0 = blockIdx.y * GBM;
    int n0 = blockIdx.x * GBN;
    int tid = threadIdx.x;
    int wid = tid >> 5, lane = tid & 31;
    int wm = wid >> 1, wn = wid & 1;
    int grp = lane >> 2, qd = lane & 3;

    int lr = tid >> 3;                 // 0..31
    int c4 = (tid & 7) * 4;            // 0..28

    int rowA = wm * 32 + (lane & 7) + ((lane >> 3) & 1) * 8;
    int offA = rowA * TSTR + ((lane >> 4) & 1) * 4;
    int rowB = wn * 64 + (lane & 7) + ((lane >> 4) & 1) * 8;
    int offB = rowB * TSTR + ((lane >> 3) & 1) * 4;

    // EPI==2: per-thread LN params for its 4 staged rows
    float mean_t[4], inv_t[4];
    if (EPI == 2) {
#pragma unroll
        for (int t = 0; t < 4; t++) {
            int r = m0 + lr + 32 * t;
            float s = rsum[r], sq = rsumsq[r];
            float mn = s * (1.0f / Dsz);
            float var = (sq - (float)Dsz * mn * mn) * (1.0f / (Dsz - 1));
            mean_t[t] = mn;
            inv_t[t] = 1.0f / (sqrtf(var) + 1e-6f);
        }
    }

    float acc[2][8][4];
#pragma unroll
    for (int i = 0; i < 2; i++)
#pragma unroll
        for (int n = 0; n < 8; n++)
#pragma unroll
            for (int e = 0; e < 4; e++) acc[i][n][e] = 0.f;

    auto stageW = [&](int buf, int k0) {
        uint32_t sb = smemU + buf * STAGE_B + TILE_F * 4;
#pragma unroll
        for (int t = 0; t < 4; t++) {
            int r = lr + 32 * t;
            cp_async16(sb + (r * TSTR + c4) * 4,
                       W + (size_t)(n0 + r) * Dsz + k0 + c4);
        }
    };
    auto stageA_async = [&](int buf, int k0) {
        uint32_t sa = smemU + buf * STAGE_B;
#pragma unroll
        for (int t = 0; t < 4; t++) {
            int r = lr + 32 * t;
            cp_async16(sa + (r * TSTR + c4) * 4,
                       A + (size_t)(m0 + r) * Dsz + k0 + c4);
        }
    };

    const int NSTEP = Dsz / GBK;  // 8
    float4 pa[4];

    if (EPI == 2) {
#pragma unroll
        for (int t = 0; t < 4; t++)
            pa[t] = *reinterpret_cast<const float4*>(
                A + (size_t)(m0 + lr + 32 * t) * Dsz + c4);
        stageW(0, 0);
        asm volatile("cp.async.commit_group;");
    } else {
        stageA_async(0, 0);
        stageW(0, 0);
        asm volatile("cp.async.commit_group;");
    }

    for (int s = 0; s < NSTEP; s++) {
        if (EPI == 2) {
            // transform + store A stage s
            float4 g4 = *reinterpret_cast<const float4*>(lga + s * GBK + c4);
            float4 b4 = *reinterpret_cast<const float4*>(lgb + s * GBK + c4);
            uint32_t sa = smemU + (s & 1) * STAGE_B;
#pragma unroll
            for (int t = 0; t < 4; t++) {
                int r = lr + 32 * t;
                float4 v;
                v.x = (pa[t].x - mean_t[t]) * inv_t[t] * g4.x + b4.x;
                v.y = (pa[t].y - mean_t[t]) * inv_t[t] * g4.y + b4.y;
                v.z = (pa[t].z - mean_t[t]) * inv_t[t] * g4.z + b4.z;
                v.w = (pa[t].w - mean_t[t]) * inv_t[t] * g4.w + b4.w;
                asm volatile("st.shared.v4.b32 [%0], {%1,%2,%3,%4};"
                             :: "r"(sa + (r * TSTR + c4) * 4),
                                "f"(v.x), "f"(v.y), "f"(v.z), "f"(v.w));
            }
            if (s + 1 < NSTEP) {
#pragma unroll
                for (int t = 0; t < 4; t++)
                    pa[t] = *reinterpret_cast<const float4*>(
                        A + (size_t)(m0 + lr + 32 * t) * Dsz + (s + 1) * GBK + c4);
                stageW((s + 1) & 1, (s + 1) * GBK);
                asm volatile("cp.async.commit_group;");
                asm volatile("cp.async.wait_group 1;");
            } else {
                asm volatile("cp.async.wait_group 0;");
            }
        } else {
            if (s + 1 < NSTEP) {
                stageA_async((s + 1) & 1, (s + 1) * GBK);
                stageW((s + 1) & 1, (s + 1) * GBK);
                asm volatile("cp.async.commit_group;");
                asm volatile("cp.async.wait_group 1;");
            } else {
                asm volatile("cp.async.wait_group 0;");
            }
        }
        __syncthreads();

        uint32_t aB = smemU + (s & 1) * STAGE_B + offA * 4;
        uint32_t bB = smemU + (s & 1) * STAGE_B + TILE_F * 4 + offB * 4;
#pragma unroll
        for (int kb = 0; kb < 4; kb++) {
            uint32_t af[2][4];
#pragma unroll
            for (int i = 0; i < 2; i++)
                ldsm_x4(af[i][0], af[i][1], af[i][2], af[i][3],
                        aB + (i * 16 * TSTR + kb * 8) * 4);
            uint32_t bf[8][2];
#pragma unroll
            for (int p = 0; p < 4; p++) {
                uint32_t r0, r1, r2, r3;
                ldsm_x4(r0, r1, r2, r3, bB + (p * 16 * TSTR + kb * 8) * 4);
                bf[2 * p][0] = r0; bf[2 * p][1] = r1;
                bf[2 * p + 1][0] = r2; bf[2 * p + 1][1] = r3;
            }
#pragma unroll
            for (int i = 0; i < 2; i++)
#pragma unroll
                for (int n = 0; n < 8; n++)
                    mma_tf32(acc[i][n],
                             reinterpret_cast<const float*>(af[i]),
                             __uint_as_float(bf[n][0]),
                             __uint_as_float(bf[n][1]));
        }
        __syncthreads();
    }

    // epilogue: C-frag layout -> float2 global stores (+ optional row stats)
#pragma unroll
    for (int i = 0; i < 2; i++) {
        int mr0 = m0 + wm * 32 + i * 16 + grp;
        int mr1 = mr0 + 8;
        float sf0 = 0.f, sf1 = 0.f;
        if (EPI == 2) {
            sf0 = sffn[mr0 % Ssz];
            sf1 = sffn[mr1 % Ssz];
        }
        float s0 = 0.f, q0s = 0.f, s1 = 0.f, q1s = 0.f;
#pragma unroll
        for (int n = 0; n < 8; n++) {
            int col = n0 + wn * 64 + n * 8 + 2 * qd;
            float2 bv = *reinterpret_cast<const float2*>(bias + col);
            float2 a0 = *reinterpret_cast<const float2*>(
                add + (size_t)mr0 * Dsz + col);
            float2 a1 = *reinterpret_cast<const float2*>(
                add + (size_t)mr1 * Dsz + col);
            float r00 = acc[i][n][0] + bv.x, r01 = acc[i][n][1] + bv.y;
            float r10 = acc[i][n][2] + bv.x, r11 = acc[i][n][3] + bv.y;
            if (EPI == 0) {
                r00 += a0.x; r01 += a0.y; r10 += a1.x; r11 += a1.y;
                if (STATS) {
                    s0 += r00 + r01; q0s += r00 * r00 + r01 * r01;
                    s1 += r10 + r11; q1s += r10 * r10 + r11 * r11;
                }
            } else {
                float z, th;
                z = sf0 * r00;
                th = tanhf(0.79788456080286536f * (z + 0.044715f * z * z * z));
                r00 = a0.x + 0.5f * z * (1.0f + th);
                z = sf0 * r01;
                th = tanhf(0.79788456080286536f * (z + 0.044715f * z * z * z));
                r01 = a0.y + 0.5f * z * (1.0f + th);
                z = sf1 * r10;
                th = tanhf(0.79788456080286536f * (z + 0.044715f * z * z * z));
                r10 = a1.x + 0.5f * z * (1.0f + th);
                z = sf1 * r11;
                th = tanhf(0.79788456080286536f * (z + 0.044715f * z * z * z));
                r11 = a1.y + 0.5f * z * (1.0f + th);
            }
            *reinterpret_cast<float2*>(out + (size_t)mr0 * Dsz + col) =
                make_float2(r00, r01);
            *reinterpret_cast<float2*>(out + (size_t)mr1 * Dsz + col) =
                make_float2(r10, r11);
        }
        if (STATS) {
            const unsigned FULL = 0xffffffffu;
            s0 += __shfl_xor_sync(FULL, s0, 1);
            s0 += __shfl_xor_sync(FULL, s0, 2);
            q0s += __shfl_xor_sync(FULL, q0s, 1);
            q0s += __shfl_xor_sync(FULL, q0s, 2);
            s1 += __shfl_xor_sync(FULL, s1, 1);
            s1 += __shfl_xor_sync(FULL, s1, 2);
            q1s += __shfl_xor_sync(FULL, q1s, 1);
            q1s += __shfl_xor_sync(FULL, q1s, 2);
            if (qd == 0) {
                atomicAdd(&rsum[mr0], s0);
                atomicAdd(&rsumsq[mr0], q0s);
                atomicAdd(&rsum[mr1], s1);
                atomicAdd(&rsumsq[mr1], q1s);
            }
        }
    }
}

// ---------------------------------------------------------------------------
// Register flash-attention, raw PTX mma.m16n8k8.tf32.
// 416 threads = 13 warps: exactly one 16-query tile per warp (no imbalance).
// ---------------------------------------------------------------------------
#define SPAD 208
#define QSTR 36
#define ATHR 416

__global__ void __launch_bounds__(ATHR) attn_flash(
    const float* __restrict__ img_n, const float* __restrict__ keff,
    const int* __restrict__ mask, const float* __restrict__ sattn,
    float* __restrict__ ctx) {
    extern __shared__ float smw[];
    float* QV = smw;
    float* Ks = QV + SPAD * QSTR;
    float* m_s = Ks + SPAD * QSTR;

    int b = blockIdx.x >> 3;
    int h = blockIdx.x & 7;
    int tid = threadIdx.x;
    size_t base = ((size_t)b * Ssz) * Dsz + h * DHsz;

    for (int idx = tid; idx < SPAD * 8; idx += ATHR) {
        int r = idx >> 3, c4 = (idx & 7) * 4;
        float4 qv = make_float4(0.f, 0.f, 0.f, 0.f);
        float4 kv = make_float4(0.f, 0.f, 0.f, 0.f);
        if (r < Ssz) {
            qv = *reinterpret_cast<const float4*>(img_n + base + (size_t)r * Dsz + c4);
            kv = *reinterpret_cast<const float4*>(keff + base + (size_t)r * Dsz + c4);
        }
        qv.x = to_tf32(qv.x); qv.y = to_tf32(qv.y);
        qv.z = to_tf32(qv.z); qv.w = to_tf32(qv.w);
        kv.x = to_tf32(kv.x); kv.y = to_tf32(kv.y);
        kv.z = to_tf32(kv.z); kv.w = to_tf32(kv.w);
        *reinterpret_cast<float4*>(QV + r * QSTR + c4) = qv;
        *reinterpret_cast<float4*>(Ks + r * QSTR + c4) = kv;
    }
    for (int k = tid; k < SPAD; k += ATHR)
        m_s[k] = (k >= Ssz || mask[b * Ssz + k] == 0) ? 1.f : 0.f;
    __syncthreads();

    int w = tid >> 5, lane = tid & 31;
    int grp = lane >> 2;
    int qd = lane & 3;
    const float isq = 0.17677669529663687f;
    const unsigned FULL = 0xffffffffu;

    int q0 = w * 16;
    int qr0 = q0 + grp, qr1 = q0 + grp + 8;
    float f0 = (qr0 < Ssz) ? isq * sattn[h * Ssz + qr0] : 0.f;
    float f1 = (qr1 < Ssz) ? isq * sattn[h * Ssz + qr1] : 0.f;

    float aq[4][4];
#pragma unroll
    for (int kk = 0; kk < 4; kk++) {
        aq[kk][0] = QV[qr0 * QSTR + kk * 8 + qd];
        aq[kk][1] = QV[qr1 * QSTR + kk * 8 + qd];
        aq[kk][2] = QV[qr0 * QSTR + kk * 8 + qd + 4];
        aq[kk][3] = QV[qr1 * QSTR + kk * 8 + qd + 4];
    }

    float m0 = -3.0e38f, m1 = -3.0e38f, l0 = 0.f, l1 = 0.f;
    float co[4][4];
#pragma unroll
    for (int n = 0; n < 4; n++)
#pragma unroll
        for (int e = 0; e < 4; e++) co[n][e] = 0.f;

    for (int nt = 0; nt < 13; nt++) {
        int key0 = nt * 16;
        float s[2][4] = {{0.f, 0.f, 0.f, 0.f}, {0.f, 0.f, 0.f, 0.f}};
#pragma unroll
        for (int n = 0; n < 2; n++) {
            int keyc = key0 + n * 8 + grp;
#pragma unroll
            for (int kk = 0; kk < 4; kk++) {
                float b0 = Ks[keyc * QSTR + kk * 8 + qd];
                float b1 = Ks[keyc * QSTR + kk * 8 + qd + 4];
                mma_tf32(s[n], aq[kk], b0, b1);
            }
        }
        float pv[2][4];
        float rm0 = -3.0e38f, rm1 = -3.0e38f;
#pragma unroll
        for (int n = 0; n < 2; n++) {
            int c = key0 + n * 8 + 2 * qd;
            float mk0 = m_s[c], mk1 = m_s[c + 1];
            float v0 = (mk0 != 0.f) ? -1e9f : s[n][0] * f0;
            float v1 = (mk1 != 0.f) ? -1e9f : s[n][1] * f0;
            float v2 = (mk0 != 0.f) ? -1e9f : s[n][2] * f1;
            float v3 = (mk1 != 0.f) ? -1e9f : s[n][3] * f1;
            pv[n][0] = v0; pv[n][1] = v1; pv[n][2] = v2; pv[n][3] = v3;
            rm0 = fmaxf(rm0, fmaxf(v0, v1));
            rm1 = fmaxf(rm1, fmaxf(v2, v3));
        }
        rm0 = fmaxf(rm0, __shfl_xor_sync(FULL, rm0, 1));
        rm0 = fmaxf(rm0, __shfl_xor_sync(FULL, rm0, 2));
        rm1 = fmaxf(rm1, __shfl_xor_sync(FULL, rm1, 1));
        rm1 = fmaxf(rm1, __shfl_xor_sync(FULL, rm1, 2));
        float nm0 = fmaxf(m0, rm0), nm1 = fmaxf(m1, rm1);
        float al0 = __expf(m0 - nm0), al1 = __expf(m1 - nm1);
        m0 = nm0; m1 = nm1;
        float ts0 = 0.f, ts1 = 0.f;
#pragma unroll
        for (int n = 0; n < 2; n++) {
            pv[n][0] = __expf(pv[n][0] - nm0);
            pv[n][1] = __expf(pv[n][1] - nm0);
            pv[n][2] = __expf(pv[n][2] - nm1);
            pv[n][3] = __expf(pv[n][3] - nm1);
            ts0 += pv[n][0] + pv[n][1];
            ts1 += pv[n][2] + pv[n][3];
        }
        ts0 += __shfl_xor_sync(FULL, ts0, 1);
        ts0 += __shfl_xor_sync(FULL, ts0, 2);
        ts1 += __shfl_xor_sync(FULL, ts1, 1);
        ts1 += __shfl_xor_sync(FULL, ts1, 2);
        l0 = l0 * al0 + ts0;
        l1 = l1 * al1 + ts1;
#pragma unroll
        for (int n = 0; n < 4; n++) {
            co[n][0] *= al0; co[n][1] *= al0;
            co[n][2] *= al1; co[n][3] *= al1;
        }
        int sl = (lane & ~3) | (qd >> 1);
        bool par = (qd & 1) != 0;
#pragma unroll
        for (int kk2 = 0; kk2 < 2; kk2++) {
            float ap[4];
            float u0 = __shfl_sync(FULL, pv[kk2][0], sl);
            float u1 = __shfl_sync(FULL, pv[kk2][1], sl);
            float u2 = __shfl_sync(FULL, pv[kk2][2], sl);
            float u3 = __shfl_sync(FULL, pv[kk2][3], sl);
            ap[0] = par ? u1 : u0;
            ap[1] = par ? u3 : u2;
            float w0 = __shfl_sync(FULL, pv[kk2][0], sl + 2);
            float w1 = __shfl_sync(FULL, pv[kk2][1], sl + 2);
            float w2 = __shfl_sync(FULL, pv[kk2][2], sl + 2);
            float w3 = __shfl_sync(FULL, pv[kk2][3], sl + 2);
            ap[2] = par ? w1 : w0;
            ap[3] = par ? w3 : w2;
            int kr0 = key0 + kk2 * 8 + qd;
#pragma unroll
            for (int n4 = 0; n4 < 4; n4++) {
                float b0 = QV[kr0 * QSTR + n4 * 8 + grp];
                float b1 = QV[(kr0 + 4) * QSTR + n4 * 8 + grp];
                mma_tf32(co[n4], ap, b0, b1);
            }
        }
    }

    float inv0 = 1.f / l0, inv1 = 1.f / l1;
#pragma unroll
    for (int n4 = 0; n4 < 4; n4++) {
        if (qr0 < Ssz) {
            float2 v = make_float2(co[n4][0] * inv0, co[n4][1] * inv0);
            *reinterpret_cast<float2*>(
                ctx + base + (size_t)qr0 * Dsz + n4 * 8 + 2 * qd) = v;
        }
        if (qr1 < Ssz) {
            float2 v = make_float2(co[n4][2] * inv1, co[n4][3] * inv1);
            *reinterpret_cast<float2*>(
                ctx + base + (size_t)qr1 * Dsz + n4 * 8 + 2 * qd) = v;
        }
    }
}

// ---------------------------------------------------------------------------
extern "C" void kernel_launch(void* const* d_in, const int* in_sizes, int n_in,
                              void* d_out, int out_size) {
    const float* hidden_img   = (const float*)d_in[0];
    const float* hidden_title = (const float*)d_in[1];
    const int*   mask         = (const int*)  d_in[2];
    const float* a_img   = (const float*)d_in[3];
    const float* b_img   = (const float*)d_in[4];
    const float* a_title = (const float*)d_in[5];
    const float* b_title = (const float*)d_in[6];
    const float* Wb      = (const float*)d_in[7];
    const float* bb      = (const float*)d_in[8];
    const float* Wo      = (const float*)d_in[9];
    const float* bo      = (const float*)d_in[10];
    const float* sattn   = (const float*)d_in[11];
    const float* a_out   = (const float*)d_in[12];
    const float* b_out   = (const float*)d_in[13];
    const float* W1      = (const float*)d_in[14];
    const float* b1      = (const float*)d_in[15];
    const float* sffn    = (const float*)d_in[16];
    float* out = (float*)d_out;

    float *img_n, *title_n, *keff, *ctxb, *h1, *rsum, *rsumsq;
    cudaGetSymbolAddress((void**)&img_n,   g_img_n);
    cudaGetSymbolAddress((void**)&title_n, g_title_n);
    cudaGetSymbolAddress((void**)&keff,    g_keff);
    cudaGetSymbolAddress((void**)&ctxb,    g_ctx);
    cudaGetSymbolAddress((void**)&h1,      g_h1);
    cudaGetSymbolAddress((void**)&rsum,    g_rsum);
    cudaGetSymbolAddress((void**)&rsumsq,  g_rsumsq);

    const int LNB = BS / 8;
    const int gemm_smem = 2 * STAGE_B;   // 73728 bytes
    cudaFuncSetAttribute((const void*)gemm_mma<0, false>,
                         cudaFuncAttributeMaxDynamicSharedMemorySize, gemm_smem);
    cudaFuncSetAttribute((const void*)gemm_mma<0, true>,
                         cudaFuncAttributeMaxDynamicSharedMemorySize, gemm_smem);
    cudaFuncSetAttribute((const void*)gemm_mma<2, false>,
                         cudaFuncAttributeMaxDynamicSharedMemorySize, gemm_smem);

    // zero the row-stat accumulators (graph-capturable async memset)
    cudaMemsetAsync(rsum, 0, BS * sizeof(float));
    cudaMemsetAsync(rsumsq, 0, BS * sizeof(float));

    // 1) both input LayerNorms in one launch
    ln_fast<<<2 * LNB, 256>>>(hidden_img, a_img, b_img, img_n,
                              hidden_title, a_title, b_title, title_n, LNB);

    // 2) keff = title_n @ Wb^T + bb + img_n
    dim3 gg(Dsz / GBN, BS / GBM);
    gemm_mma<0, false><<<gg, 256, gemm_smem>>>(
        title_n, Wb, bb, img_n, nullptr, keff, nullptr, nullptr, nullptr, nullptr);

    // 3) attention (register flash, tf32 mma, 13 warps = 1 tile/warp)
    const int smem_bytes = (SPAD * QSTR * 2 + SPAD) * 4;
    cudaFuncSetAttribute(attn_flash,
                         cudaFuncAttributeMaxDynamicSharedMemorySize, smem_bytes);
    attn_flash<<<Bsz * Hsz, ATHR, smem_bytes>>>(img_n, keff, mask, sattn, ctxb);

    // 4) h1 = ctx @ Wo^T + bo + hidden_img  (+ row stats for fused LN)
    gemm_mma<0, true><<<gg, 256, gemm_smem>>>(
        ctxb, Wo, bo, hidden_img, nullptr, h1, nullptr, nullptr, rsum, rsumsq);

    // 5) out = h1 + gelu_tanh(scale_ffn * (LN(h1) @ W1^T + b1)), LN fused
    gemm_mma<2, false><<<gg, 256, gemm_smem>>>(
        h1, W1, b1, h1, sffn, out, a_out, b_out, rsum, rsumsq);
}

// round 8
// speedup vs baseline: 3.5374x; 1.1490x over previous
#include <cuda_runtime.h>
#include <cuda_fp16.h>
#include <math.h>
#include <stdint.h>

#define Bsz 256
#define Ssz 200
#define Dsz 256
#define Hsz 8
#define DHsz 32
#define BS (Bsz * Ssz)   // 51200 rows

__device__ float g_img_n[BS * Dsz];
__device__ float g_keff[BS * Dsz];
__device__ float g_h1[BS * Dsz];
__device__ float g_rsum[BS];
__device__ float g_rsumsq[BS];
__device__ __half g_title_h[BS * Dsz];
__device__ __half g_ctx_h[BS * Dsz];
__device__ __half g_Wb_h[Dsz * Dsz];
__device__ __half g_Wo_h[Dsz * Dsz];
__device__ __half g_W1_h[Dsz * Dsz];

__device__ __forceinline__ float to_tf32(float x) {
    float r;
    asm("cvt.rna.tf32.f32 %0, %1;" : "=f"(r) : "f"(x));
    return r;
}

__device__ __forceinline__ void mma_tf32(float* c, const float* a,
                                         float b0, float b1) {
    uint32_t const* ai = reinterpret_cast<uint32_t const*>(a);
    uint32_t bi0 = __float_as_uint(b0), bi1 = __float_as_uint(b1);
    asm volatile(
        "mma.sync.aligned.m16n8k8.row.col.f32.tf32.tf32.f32 "
        "{%0,%1,%2,%3}, {%4,%5,%6,%7}, {%8,%9}, {%0,%1,%2,%3};"
        : "+f"(c[0]), "+f"(c[1]), "+f"(c[2]), "+f"(c[3])
        : "r"(ai[0]), "r"(ai[1]), "r"(ai[2]), "r"(ai[3]), "r"(bi0), "r"(bi1));
}

__device__ __forceinline__ void mma_f16(float* c, const uint32_t* a,
                                        uint32_t b0, uint32_t b1) {
    asm volatile(
        "mma.sync.aligned.m16n8k16.row.col.f32.f16.f16.f32 "
        "{%0,%1,%2,%3}, {%4,%5,%6,%7}, {%8,%9}, {%0,%1,%2,%3};"
        : "+f"(c[0]), "+f"(c[1]), "+f"(c[2]), "+f"(c[3])
        : "r"(a[0]), "r"(a[1]), "r"(a[2]), "r"(a[3]), "r"(b0), "r"(b1));
}

__device__ __forceinline__ void ldsm_x4(uint32_t& r0, uint32_t& r1,
                                        uint32_t& r2, uint32_t& r3,
                                        uint32_t addr) {
    asm volatile(
        "ldmatrix.sync.aligned.m8n8.x4.shared.b16 {%0,%1,%2,%3}, [%4];"
        : "=r"(r0), "=r"(r1), "=r"(r2), "=r"(r3) : "r"(addr));
}

__device__ __forceinline__ void cp_async16(uint32_t smem, const void* g) {
    asm volatile("cp.async.cg.shared.global [%0], [%1], 16;"
                 :: "r"(smem), "l"(g));
}

// ---------------------------------------------------------------------------
// Convert the 3 weight matrices to half (once per launch; tiny).
// ---------------------------------------------------------------------------
__global__ void __launch_bounds__(256) w2h_kernel(
    const float* __restrict__ w0, const float* __restrict__ w1,
    const float* __restrict__ w2, __half* __restrict__ h0,
    __half* __restrict__ h1, __half* __restrict__ h2) {
    int i = blockIdx.x * 256 + threadIdx.x;   // 0..98303 (float2 units)
    const float2* s;
    __half2* d;
    int j;
    if (i < 32768)      { s = (const float2*)w0; d = (__half2*)h0; j = i; }
    else if (i < 65536) { s = (const float2*)w1; d = (__half2*)h1; j = i - 32768; }
    else                { s = (const float2*)w2; d = (__half2*)h2; j = i - 65536; }
    float2 v = s[j];
    d[j] = __floats2half2_rn(v.x, v.y);
}

// ---------------------------------------------------------------------------
// Warp-per-row LayerNorm. Stream 0 -> float out (img_n); stream 1 -> half
// out (title_n, consumed only as fp16 GEMM A-operand).
// ---------------------------------------------------------------------------
__global__ void __launch_bounds__(256) ln_fast(
    const float* __restrict__ x0, const float* __restrict__ ga0,
    const float* __restrict__ gb0, float* __restrict__ yf,
    const float* __restrict__ x1, const float* __restrict__ ga1,
    const float* __restrict__ gb1, __half* __restrict__ yh, int split) {
    int blk = blockIdx.x;
    bool tohalf = (blk >= split);
    const float *x, *ga, *gb;
    int rowbase;
    if (!tohalf) { x = x0; ga = ga0; gb = gb0; rowbase = blk * 8; }
    else         { x = x1; ga = ga1; gb = gb1; rowbase = (blk - split) * 8; }
    int w = threadIdx.x >> 5, lane = threadIdx.x & 31;
    size_t row = rowbase + w;
    const float4* x4 = reinterpret_cast<const float4*>(x + row * Dsz);
    float4 v0 = x4[lane];
    float4 v1 = x4[lane + 32];

    float s = v0.x + v0.y + v0.z + v0.w + v1.x + v1.y + v1.z + v1.w;
#pragma unroll
    for (int o = 16; o; o >>= 1) s += __shfl_xor_sync(0xffffffffu, s, o);
    float mean = s * (1.0f / Dsz);

    float d0x = v0.x - mean, d0y = v0.y - mean, d0z = v0.z - mean, d0w = v0.w - mean;
    float d1x = v1.x - mean, d1y = v1.y - mean, d1z = v1.z - mean, d1w = v1.w - mean;
    float ss = d0x * d0x + d0y * d0y + d0z * d0z + d0w * d0w +
               d1x * d1x + d1y * d1y + d1z * d1z + d1w * d1w;
#pragma unroll
    for (int o = 16; o; o >>= 1) ss += __shfl_xor_sync(0xffffffffu, ss, o);
    float var = ss * (1.0f / (Dsz - 1));
    float inv = 1.0f / (sqrtf(var) + 1e-6f);

    const float4* ga4 = reinterpret_cast<const float4*>(ga);
    const float4* gb4 = reinterpret_cast<const float4*>(gb);
    float4 g0 = ga4[lane], g1 = ga4[lane + 32];
    float4 b0 = gb4[lane], b1 = gb4[lane + 32];
    float4 o0 = make_float4(g0.x * d0x * inv + b0.x, g0.y * d0y * inv + b0.y,
                            g0.z * d0z * inv + b0.z, g0.w * d0w * inv + b0.w);
    float4 o1 = make_float4(g1.x * d1x * inv + b1.x, g1.y * d1y * inv + b1.y,
                            g1.z * d1z * inv + b1.z, g1.w * d1w * inv + b1.w);
    if (!tohalf) {
        float4* y4 = reinterpret_cast<float4*>(yf + row * Dsz);
        y4[lane] = o0;
        y4[lane + 32] = o1;
    } else {
        __half2 h0a = __floats2half2_rn(o0.x, o0.y);
        __half2 h0b = __floats2half2_rn(o0.z, o0.w);
        __half2 h1a = __floats2half2_rn(o1.x, o1.y);
        __half2 h1b = __floats2half2_rn(o1.z, o1.w);
        uint2* y2 = reinterpret_cast<uint2*>(yh + row * Dsz);
        y2[lane] = make_uint2(*(uint32_t*)&h0a, *(uint32_t*)&h0b);
        y2[lane + 32] = make_uint2(*(uint32_t*)&h1a, *(uint32_t*)&h1b);
    }
}

// ---------------------------------------------------------------------------
// fp16 GEMM (fp32 accum): out[m,n] = sum_k A[m,k]*W[n,k] + bias[n] (+ epi)
// Block 128x128, BK=32, 256 thr, 8 warps (4m x 2n), warp tile 32x64.
// Half tiles in smem, row pitch 80B; ldmatrix x4 fragment loads.
// EPI==0: A is half (cp.async staging). out = acc+bias+add (+row stats)
// EPI==2: A is float; staging applies LN(rsum/rsumsq,lga,lgb) + f16 convert.
//         z = sffn[m%S]*(acc+bias); out = add + gelu_tanh(z)
// ---------------------------------------------------------------------------
#define GBM 128
#define GBN 128
#define HPITCH 80                       // bytes per 32-half row
#define TILE_B (128 * HPITCH)           // 10240 bytes per tile
#define STAGE_B (2 * TILE_B)            // A+B per stage

template <int EPI, bool STATS>
__global__ void __launch_bounds__(256) gemm_f16(
    const void* __restrict__ Aptr, const __half* __restrict__ W,
    const float* __restrict__ bias, const float* __restrict__ add,
    const float* __restrict__ sffn, float* __restrict__ out,
    const float* __restrict__ lga, const float* __restrict__ lgb,
    float* __restrict__ rsum, float* __restrict__ rsumsq) {
    extern __shared__ char gsm[];
    uint32_t smemU = (uint32_t)__cvta_generic_to_shared(gsm);

    int m0 = blockIdx.y * GBM;
    int n0 = blockIdx.x * GBN;
    int tid = threadIdx.x;
    int wid = tid >> 5, lane = tid & 31;
    int wm = wid >> 1, wn = wid & 1;
    int grp = lane >> 2, qd = lane & 3;

    // ldmatrix lane offsets (bytes within tile)
    int rA = (lane & 7) + ((lane >> 3) & 1) * 8;
    int offA = (wm * 32 + rA) * HPITCH + ((lane >> 4) & 1) * 16;
    int rB = (lane & 7) + ((lane >> 4) & 1) * 8;
    int offB = (wn * 64 + rB) * HPITCH + ((lane >> 3) & 1) * 16;

    float mean_t[4], inv_t[4];
    int lr = tid >> 3;               // 0..31 (EPI2 A staging rows)
    int c4f = (tid & 7) * 4;         // 0..28 (float cols)
    if (EPI == 2) {
#pragma unroll
        for (int t = 0; t < 4; t++) {
            int r = m0 + lr + 32 * t;
            float s = rsum[r], sq = rsumsq[r];
            float mn = s * (1.0f / Dsz);
            float var = (sq - (float)Dsz * mn * mn) * (1.0f / (Dsz - 1));
            mean_t[t] = mn;
            inv_t[t] = 1.0f / (sqrtf(var) + 1e-6f);
        }
    }

    float acc[2][8][4];
#pragma unroll
    for (int i = 0; i < 2; i++)
#pragma unroll
        for (int n = 0; n < 8; n++)
#pragma unroll
            for (int e = 0; e < 4; e++) acc[i][n][e] = 0.f;

    int crow = tid >> 2, cu = tid & 3;   // cp.async mapping: 64 rows x 4 units
    const __half* Ah = (const __half*)Aptr;
    const float* Af = (const float*)Aptr;

    auto stageW = [&](int buf, int k0) {
        uint32_t sb = smemU + buf * STAGE_B + TILE_B;
        cp_async16(sb + crow * HPITCH + cu * 16,
                   W + (size_t)(n0 + crow) * Dsz + k0 + cu * 8);
        cp_async16(sb + (crow + 64) * HPITCH + cu * 16,
                   W + (size_t)(n0 + crow + 64) * Dsz + k0 + cu * 8);
    };
    auto stageA = [&](int buf, int k0) {
        uint32_t sa = smemU + buf * STAGE_B;
        cp_async16(sa + crow * HPITCH + cu * 16,
                   Ah + (size_t)(m0 + crow) * Dsz + k0 + cu * 8);
        cp_async16(sa + (crow + 64) * HPITCH + cu * 16,
                   Ah + (size_t)(m0 + crow + 64) * Dsz + k0 + cu * 8);
    };

    const int NSTEP = Dsz / 32;  // 8
    float4 pa[4];

    if (EPI == 2) {
#pragma unroll
        for (int t = 0; t < 4; t++)
            pa[t] = *reinterpret_cast<const float4*>(
                Af + (size_t)(m0 + lr + 32 * t) * Dsz + c4f);
        stageW(0, 0);
        asm volatile("cp.async.commit_group;");
    } else {
        stageA(0, 0);
        stageW(0, 0);
        asm volatile("cp.async.commit_group;");
    }

    for (int s = 0; s < NSTEP; s++) {
        if (EPI == 2) {
            float4 g4 = *reinterpret_cast<const float4*>(lga + s * 32 + c4f);
            float4 b4 = *reinterpret_cast<const float4*>(lgb + s * 32 + c4f);
            uint32_t sa = smemU + (s & 1) * STAGE_B;
#pragma unroll
            for (int t = 0; t < 4; t++) {
                int r = lr + 32 * t;
                float vx = (pa[t].x - mean_t[t]) * inv_t[t] * g4.x + b4.x;
                float vy = (pa[t].y - mean_t[t]) * inv_t[t] * g4.y + b4.y;
                float vz = (pa[t].z - mean_t[t]) * inv_t[t] * g4.z + b4.z;
                float vw = (pa[t].w - mean_t[t]) * inv_t[t] * g4.w + b4.w;
                __half2 h01 = __floats2half2_rn(vx, vy);
                __half2 h23 = __floats2half2_rn(vz, vw);
                asm volatile("st.shared.v2.b32 [%0], {%1,%2};"
                             :: "r"(sa + r * HPITCH + c4f * 2),
                                "r"(*(uint32_t*)&h01), "r"(*(uint32_t*)&h23));
            }
            if (s + 1 < NSTEP) {
#pragma unroll
                for (int t = 0; t < 4; t++)
                    pa[t] = *reinterpret_cast<const float4*>(
                        Af + (size_t)(m0 + lr + 32 * t) * Dsz + (s + 1) * 32 + c4f);
                stageW((s + 1) & 1, (s + 1) * 32);
                asm volatile("cp.async.commit_group;");
                asm volatile("cp.async.wait_group 1;");
            } else {
                asm volatile("cp.async.wait_group 0;");
            }
        } else {
            if (s + 1 < NSTEP) {
                stageA((s + 1) & 1, (s + 1) * 32);
                stageW((s + 1) & 1, (s + 1) * 32);
                asm volatile("cp.async.commit_group;");
                asm volatile("cp.async.wait_group 1;");
            } else {
                asm volatile("cp.async.wait_group 0;");
            }
        }
        __syncthreads();

        uint32_t aB = smemU + (s & 1) * STAGE_B + offA;
        uint32_t bB = smemU + (s & 1) * STAGE_B + TILE_B + offB;
#pragma unroll
        for (int kb = 0; kb < 2; kb++) {   // two k16 blocks per stage
            uint32_t af[2][4];
#pragma unroll
            for (int i = 0; i < 2; i++)
                ldsm_x4(af[i][0], af[i][1], af[i][2], af[i][3],
                        aB + i * 16 * HPITCH + kb * 32);
            uint32_t bf[8][2];
#pragma unroll
            for (int p = 0; p < 4; p++) {
                uint32_t r0, r1, r2, r3;
                ldsm_x4(r0, r1, r2, r3, bB + p * 16 * HPITCH + kb * 32);
                bf[2 * p][0] = r0; bf[2 * p][1] = r1;
                bf[2 * p + 1][0] = r2; bf[2 * p + 1][1] = r3;
            }
#pragma unroll
            for (int i = 0; i < 2; i++)
#pragma unroll
                for (int n = 0; n < 8; n++)
                    mma_f16(acc[i][n], af[i], bf[n][0], bf[n][1]);
        }
        __syncthreads();
    }

    // epilogue: C-frag layout -> float2 global stores (+ optional row stats)
#pragma unroll
    for (int i = 0; i < 2; i++) {
        int mr0 = m0 + wm * 32 + i * 16 + grp;
        int mr1 = mr0 + 8;
        float sf0 = 0.f, sf1 = 0.f;
        if (EPI == 2) {
            sf0 = sffn[mr0 % Ssz];
            sf1 = sffn[mr1 % Ssz];
        }
        float s0 = 0.f, q0s = 0.f, s1 = 0.f, q1s = 0.f;
#pragma unroll
        for (int n = 0; n < 8; n++) {
            int col = n0 + wn * 64 + n * 8 + 2 * qd;
            float2 bv = *reinterpret_cast<const float2*>(bias + col);
            float2 a0 = *reinterpret_cast<const float2*>(
                add + (size_t)mr0 * Dsz + col);
            float2 a1 = *reinterpret_cast<const float2*>(
                add + (size_t)mr1 * Dsz + col);
            float r00 = acc[i][n][0] + bv.x, r01 = acc[i][n][1] + bv.y;
            float r10 = acc[i][n][2] + bv.x, r11 = acc[i][n][3] + bv.y;
            if (EPI == 0) {
                r00 += a0.x; r01 += a0.y; r10 += a1.x; r11 += a1.y;
                if (STATS) {
                    s0 += r00 + r01; q0s += r00 * r00 + r01 * r01;
                    s1 += r10 + r11; q1s += r10 * r10 + r11 * r11;
                }
            } else {
                float z, th;
                z = sf0 * r00;
                th = tanhf(0.79788456080286536f * (z + 0.044715f * z * z * z));
                r00 = a0.x + 0.5f * z * (1.0f + th);
                z = sf0 * r01;
                th = tanhf(0.79788456080286536f * (z + 0.044715f * z * z * z));
                r01 = a0.y + 0.5f * z * (1.0f + th);
                z = sf1 * r10;
                th = tanhf(0.79788456080286536f * (z + 0.044715f * z * z * z));
                r10 = a1.x + 0.5f * z * (1.0f + th);
                z = sf1 * r11;
                th = tanhf(0.79788456080286536f * (z + 0.044715f * z * z * z));
                r11 = a1.y + 0.5f * z * (1.0f + th);
            }
            *reinterpret_cast<float2*>(out + (size_t)mr0 * Dsz + col) =
                make_float2(r00, r01);
            *reinterpret_cast<float2*>(out + (size_t)mr1 * Dsz + col) =
                make_float2(r10, r11);
        }
        if (STATS) {
            const unsigned FULL = 0xffffffffu;
            s0 += __shfl_xor_sync(FULL, s0, 1);
            s0 += __shfl_xor_sync(FULL, s0, 2);
            q0s += __shfl_xor_sync(FULL, q0s, 1);
            q0s += __shfl_xor_sync(FULL, q0s, 2);
            s1 += __shfl_xor_sync(FULL, s1, 1);
            s1 += __shfl_xor_sync(FULL, s1, 2);
            q1s += __shfl_xor_sync(FULL, q1s, 1);
            q1s += __shfl_xor_sync(FULL, q1s, 2);
            if (qd == 0) {
                atomicAdd(&rsum[mr0], s0);
                atomicAdd(&rsumsq[mr0], q0s);
                atomicAdd(&rsum[mr1], s1);
                atomicAdd(&rsumsq[mr1], q1s);
            }
        }
    }
}

// ---------------------------------------------------------------------------
// Register flash-attention, raw PTX mma.m16n8k8.tf32 (13 warps, 1 tile/warp).
// ctx written as HALF (feeds fp16 GEMM directly).
// ---------------------------------------------------------------------------
#define SPAD 208
#define QSTR 36
#define ATHR 416

__global__ void __launch_bounds__(ATHR) attn_flash(
    const float* __restrict__ img_n, const float* __restrict__ keff,
    const int* __restrict__ mask, const float* __restrict__ sattn,
    __half* __restrict__ ctx_h) {
    extern __shared__ float smw[];
    float* QV = smw;
    float* Ks = QV + SPAD * QSTR;
    float* m_s = Ks + SPAD * QSTR;

    int b = blockIdx.x >> 3;
    int h = blockIdx.x & 7;
    int tid = threadIdx.x;
    size_t base = ((size_t)b * Ssz) * Dsz + h * DHsz;

    for (int idx = tid; idx < SPAD * 8; idx += ATHR) {
        int r = idx >> 3, c4 = (idx & 7) * 4;
        float4 qv = make_float4(0.f, 0.f, 0.f, 0.f);
        float4 kv = make_float4(0.f, 0.f, 0.f, 0.f);
        if (r < Ssz) {
            qv = *reinterpret_cast<const float4*>(img_n + base + (size_t)r * Dsz + c4);
            kv = *reinterpret_cast<const float4*>(keff + base + (size_t)r * Dsz + c4);
        }
        qv.x = to_tf32(qv.x); qv.y = to_tf32(qv.y);
        qv.z = to_tf32(qv.z); qv.w = to_tf32(qv.w);
        kv.x = to_tf32(kv.x); kv.y = to_tf32(kv.y);
        kv.z = to_tf32(kv.z); kv.w = to_tf32(kv.w);
        *reinterpret_cast<float4*>(QV + r * QSTR + c4) = qv;
        *reinterpret_cast<float4*>(Ks + r * QSTR + c4) = kv;
    }
    for (int k = tid; k < SPAD; k += ATHR)
        m_s[k] = (k >= Ssz || mask[b * Ssz + k] == 0) ? 1.f : 0.f;
    __syncthreads();

    int w = tid >> 5, lane = tid & 31;
    int grp = lane >> 2;
    int qd = lane & 3;
    const float isq = 0.17677669529663687f;
    const unsigned FULL = 0xffffffffu;

    int q0 = w * 16;
    int qr0 = q0 + grp, qr1 = q0 + grp + 8;
    float f0 = (qr0 < Ssz) ? isq * sattn[h * Ssz + qr0] : 0.f;
    float f1 = (qr1 < Ssz) ? isq * sattn[h * Ssz + qr1] : 0.f;

    float aq[4][4];
#pragma unroll
    for (int kk = 0; kk < 4; kk++) {
        aq[kk][0] = QV[qr0 * QSTR + kk * 8 + qd];
        aq[kk][1] = QV[qr1 * QSTR + kk * 8 + qd];
        aq[kk][2] = QV[qr0 * QSTR + kk * 8 + qd + 4];
        aq[kk][3] = QV[qr1 * QSTR + kk * 8 + qd + 4];
    }

    float m0 = -3.0e38f, m1 = -3.0e38f, l0 = 0.f, l1 = 0.f;
    float co[4][4];
#pragma unroll
    for (int n = 0; n < 4; n++)
#pragma unroll
        for (int e = 0; e < 4; e++) co[n][e] = 0.f;

    for (int nt = 0; nt < 13; nt++) {
        int key0 = nt * 16;
        float s[2][4] = {{0.f, 0.f, 0.f, 0.f}, {0.f, 0.f, 0.f, 0.f}};
#pragma unroll
        for (int n = 0; n < 2; n++) {
            int keyc = key0 + n * 8 + grp;
#pragma unroll
            for (int kk = 0; kk < 4; kk++) {
                float b0 = Ks[keyc * QSTR + kk * 8 + qd];
                float b1 = Ks[keyc * QSTR + kk * 8 + qd + 4];
                mma_tf32(s[n], aq[kk], b0, b1);
            }
        }
        float pv[2][4];
        float rm0 = -3.0e38f, rm1 = -3.0e38f;
#pragma unroll
        for (int n = 0; n < 2; n++) {
            int c = key0 + n * 8 + 2 * qd;
            float mk0 = m_s[c], mk1 = m_s[c + 1];
            float v0 = (mk0 != 0.f) ? -1e9f : s[n][0] * f0;
            float v1 = (mk1 != 0.f) ? -1e9f : s[n][1] * f0;
            float v2 = (mk0 != 0.f) ? -1e9f : s[n][2] * f1;
            float v3 = (mk1 != 0.f) ? -1e9f : s[n][3] * f1;
            pv[n][0] = v0; pv[n][1] = v1; pv[n][2] = v2; pv[n][3] = v3;
            rm0 = fmaxf(rm0, fmaxf(v0, v1));
            rm1 = fmaxf(rm1, fmaxf(v2, v3));
        }
        rm0 = fmaxf(rm0, __shfl_xor_sync(FULL, rm0, 1));
        rm0 = fmaxf(rm0, __shfl_xor_sync(FULL, rm0, 2));
        rm1 = fmaxf(rm1, __shfl_xor_sync(FULL, rm1, 1));
        rm1 = fmaxf(rm1, __shfl_xor_sync(FULL, rm1, 2));
        float nm0 = fmaxf(m0, rm0), nm1 = fmaxf(m1, rm1);
        float al0 = __expf(m0 - nm0), al1 = __expf(m1 - nm1);
        m0 = nm0; m1 = nm1;
        float ts0 = 0.f, ts1 = 0.f;
#pragma unroll
        for (int n = 0; n < 2; n++) {
            pv[n][0] = __expf(pv[n][0] - nm0);
            pv[n][1] = __expf(pv[n][1] - nm0);
            pv[n][2] = __expf(pv[n][2] - nm1);
            pv[n][3] = __expf(pv[n][3] - nm1);
            ts0 += pv[n][0] + pv[n][1];
            ts1 += pv[n][2] + pv[n][3];
        }
        ts0 += __shfl_xor_sync(FULL, ts0, 1);
        ts0 += __shfl_xor_sync(FULL, ts0, 2);
        ts1 += __shfl_xor_sync(FULL, ts1, 1);
        ts1 += __shfl_xor_sync(FULL, ts1, 2);
        l0 = l0 * al0 + ts0;
        l1 = l1 * al1 + ts1;
#pragma unroll
        for (int n = 0; n < 4; n++) {
            co[n][0] *= al0; co[n][1] *= al0;
            co[n][2] *= al1; co[n][3] *= al1;
        }
        int sl = (lane & ~3) | (qd >> 1);
        bool par = (qd & 1) != 0;
#pragma unroll
        for (int kk2 = 0; kk2 < 2; kk2++) {
            float ap[4];
            float u0 = __shfl_sync(FULL, pv[kk2][0], sl);
            float u1 = __shfl_sync(FULL, pv[kk2][1], sl);
            float u2 = __shfl_sync(FULL, pv[kk2][2], sl);
            float u3 = __shfl_sync(FULL, pv[kk2][3], sl);
            ap[0] = par ? u1 : u0;
            ap[1] = par ? u3 : u2;
            float w0 = __shfl_sync(FULL, pv[kk2][0], sl + 2);
            float w1 = __shfl_sync(FULL, pv[kk2][1], sl + 2);
            float w2 = __shfl_sync(FULL, pv[kk2][2], sl + 2);
            float w3 = __shfl_sync(FULL, pv[kk2][3], sl + 2);
            ap[2] = par ? w1 : w0;
            ap[3] = par ? w3 : w2;
            int kr0 = key0 + kk2 * 8 + qd;
#pragma unroll
            for (int n4 = 0; n4 < 4; n4++) {
                float b0 = QV[kr0 * QSTR + n4 * 8 + grp];
                float b1 = QV[(kr0 + 4) * QSTR + n4 * 8 + grp];
                mma_tf32(co[n4], ap, b0, b1);
            }
        }
    }

    float inv0 = 1.f / l0, inv1 = 1.f / l1;
#pragma unroll
    for (int n4 = 0; n4 < 4; n4++) {
        if (qr0 < Ssz) {
            __half2 v = __floats2half2_rn(co[n4][0] * inv0, co[n4][1] * inv0);
            *reinterpret_cast<__half2*>(
                ctx_h + base + (size_t)qr0 * Dsz + n4 * 8 + 2 * qd) = v;
        }
        if (qr1 < Ssz) {
            __half2 v = __floats2half2_rn(co[n4][2] * inv1, co[n4][3] * inv1);
            *reinterpret_cast<__half2*>(
                ctx_h + base + (size_t)qr1 * Dsz + n4 * 8 + 2 * qd) = v;
        }
    }
}

// ---------------------------------------------------------------------------
extern "C" void kernel_launch(void* const* d_in, const int* in_sizes, int n_in,
                              void* d_out, int out_size) {
    const float* hidden_img   = (const float*)d_in[0];
    const float* hidden_title = (const float*)d_in[1];
    const int*   mask         = (const int*)  d_in[2];
    const float* a_img   = (const float*)d_in[3];
    const float* b_img   = (const float*)d_in[4];
    const float* a_title = (const float*)d_in[5];
    const float* b_title = (const float*)d_in[6];
    const float* Wb      = (const float*)d_in[7];
    const float* bb      = (const float*)d_in[8];
    const float* Wo      = (const float*)d_in[9];
    const float* bo      = (const float*)d_in[10];
    const float* sattn   = (const float*)d_in[11];
    const float* a_out   = (const float*)d_in[12];
    const float* b_out   = (const float*)d_in[13];
    const float* W1      = (const float*)d_in[14];
    const float* b1      = (const float*)d_in[15];
    const float* sffn    = (const float*)d_in[16];
    float* out = (float*)d_out;

    float *img_n, *keff, *h1, *rsum, *rsumsq;
    __half *title_h, *ctx_h, *Wb_h, *Wo_h, *W1_h;
    cudaGetSymbolAddress((void**)&img_n,   g_img_n);
    cudaGetSymbolAddress((void**)&keff,    g_keff);
    cudaGetSymbolAddress((void**)&h1,      g_h1);
    cudaGetSymbolAddress((void**)&rsum,    g_rsum);
    cudaGetSymbolAddress((void**)&rsumsq,  g_rsumsq);
    cudaGetSymbolAddress((void**)&title_h, g_title_h);
    cudaGetSymbolAddress((void**)&ctx_h,   g_ctx_h);
    cudaGetSymbolAddress((void**)&Wb_h,    g_Wb_h);
    cudaGetSymbolAddress((void**)&Wo_h,    g_Wo_h);
    cudaGetSymbolAddress((void**)&W1_h,    g_W1_h);

    const int LNB = BS / 8;
    const int gemm_smem = 2 * STAGE_B;   // 40960 bytes
    cudaFuncSetAttribute((const void*)gemm_f16<0, false>,
                         cudaFuncAttributeMaxDynamicSharedMemorySize, gemm_smem);
    cudaFuncSetAttribute((const void*)gemm_f16<0, true>,
                         cudaFuncAttributeMaxDynamicSharedMemorySize, gemm_smem);
    cudaFuncSetAttribute((const void*)gemm_f16<2, false>,
                         cudaFuncAttributeMaxDynamicSharedMemorySize, gemm_smem);

    cudaMemsetAsync(rsum, 0, BS * sizeof(float));
    cudaMemsetAsync(rsumsq, 0, BS * sizeof(float));

    // 0) weights -> half (tiny)
    w2h_kernel<<<384, 256>>>(Wb, Wo, W1, Wb_h, Wo_h, W1_h);

    // 1) both input LayerNorms (img -> float, title -> half)
    ln_fast<<<2 * LNB, 256>>>(hidden_img, a_img, b_img, img_n,
                              hidden_title, a_title, b_title, title_h, LNB);

    // 2) keff = title_n @ Wb^T + bb + img_n   (fp16 tensor cores)
    dim3 gg(Dsz / GBN, BS / GBM);
    gemm_f16<0, false><<<gg, 256, gemm_smem>>>(
        title_h, Wb_h, bb, img_n, nullptr, keff, nullptr, nullptr, nullptr, nullptr);

    // 3) attention (register flash, tf32 mma) -> ctx in half
    const int smem_bytes = (SPAD * QSTR * 2 + SPAD) * 4;
    cudaFuncSetAttribute(attn_flash,
                         cudaFuncAttributeMaxDynamicSharedMemorySize, smem_bytes);
    attn_flash<<<Bsz * Hsz, ATHR, smem_bytes>>>(img_n, keff, mask, sattn, ctx_h);

    // 4) h1 = ctx @ Wo^T + bo + hidden_img  (+ row stats for fused LN)
    gemm_f16<0, true><<<gg, 256, gemm_smem>>>(
        ctx_h, Wo_h, bo, hidden_img, nullptr, h1, nullptr, nullptr, rsum, rsumsq);

    // 5) out = h1 + gelu_tanh(scale_ffn * (LN(h1) @ W1^T + b1)), LN fused
    gemm_f16<2, false><<<gg, 256, gemm_smem>>>(
        h1, W1_h, b1, h1, sffn, out, a_out, b_out, rsum, rsumsq);
}

// round 9
// speedup vs baseline: 4.0391x; 1.1418x over previous
#include <cuda_runtime.h>
#include <cuda_fp16.h>
#include <math.h>
#include <stdint.h>

#define Bsz 256
#define Ssz 200
#define Dsz 256
#define Hsz 8
#define DHsz 32
#define BS (Bsz * Ssz)   // 51200 rows

__device__ float g_img_n[BS * Dsz];
__device__ float g_keff[BS * Dsz];
__device__ float g_h1[BS * Dsz];
__device__ float g_rsum[BS];
__device__ float g_rsumsq[BS];
__device__ __half g_title_h[BS * Dsz];
__device__ __half g_ctx_h[BS * Dsz];
__device__ __half g_Wb_h[Dsz * Dsz];
__device__ __half g_Wo_h[Dsz * Dsz];
__device__ __half g_W1_h[Dsz * Dsz];

__device__ __forceinline__ void mma_f16(float* c, const uint32_t* a,
                                        uint32_t b0, uint32_t b1) {
    asm volatile(
        "mma.sync.aligned.m16n8k16.row.col.f32.f16.f16.f32 "
        "{%0,%1,%2,%3}, {%4,%5,%6,%7}, {%8,%9}, {%0,%1,%2,%3};"
        : "+f"(c[0]), "+f"(c[1]), "+f"(c[2]), "+f"(c[3])
        : "r"(a[0]), "r"(a[1]), "r"(a[2]), "r"(a[3]), "r"(b0), "r"(b1));
}

__device__ __forceinline__ void ldsm_x4(uint32_t& r0, uint32_t& r1,
                                        uint32_t& r2, uint32_t& r3,
                                        uint32_t addr) {
    asm volatile(
        "ldmatrix.sync.aligned.m8n8.x4.shared.b16 {%0,%1,%2,%3}, [%4];"
        : "=r"(r0), "=r"(r1), "=r"(r2), "=r"(r3) : "r"(addr));
}

__device__ __forceinline__ void ldsm_x4t(uint32_t& r0, uint32_t& r1,
                                         uint32_t& r2, uint32_t& r3,
                                         uint32_t addr) {
    asm volatile(
        "ldmatrix.sync.aligned.m8n8.x4.trans.shared.b16 {%0,%1,%2,%3}, [%4];"
        : "=r"(r0), "=r"(r1), "=r"(r2), "=r"(r3) : "r"(addr));
}

__device__ __forceinline__ void cp_async16(uint32_t smem, const void* g) {
    asm volatile("cp.async.cg.shared.global [%0], [%1], 16;"
                 :: "r"(smem), "l"(g));
}

__device__ __forceinline__ uint32_t packh2(float a, float b) {
    __half2 h = __floats2half2_rn(a, b);
    return *reinterpret_cast<uint32_t*>(&h);
}

// ---------------------------------------------------------------------------
// Convert the 3 weight matrices to half (once per launch; tiny).
// ---------------------------------------------------------------------------
__global__ void __launch_bounds__(256) w2h_kernel(
    const float* __restrict__ w0, const float* __restrict__ w1,
    const float* __restrict__ w2, __half* __restrict__ h0,
    __half* __restrict__ h1, __half* __restrict__ h2) {
    int i = blockIdx.x * 256 + threadIdx.x;
    const float2* s;
    __half2* d;
    int j;
    if (i < 32768)      { s = (const float2*)w0; d = (__half2*)h0; j = i; }
    else if (i < 65536) { s = (const float2*)w1; d = (__half2*)h1; j = i - 32768; }
    else                { s = (const float2*)w2; d = (__half2*)h2; j = i - 65536; }
    float2 v = s[j];
    d[j] = __floats2half2_rn(v.x, v.y);
}

// ---------------------------------------------------------------------------
// Warp-per-row LayerNorm. Stream 0 -> float out; stream 1 -> half out.
// ---------------------------------------------------------------------------
__global__ void __launch_bounds__(256) ln_fast(
    const float* __restrict__ x0, const float* __restrict__ ga0,
    const float* __restrict__ gb0, float* __restrict__ yf,
    const float* __restrict__ x1, const float* __restrict__ ga1,
    const float* __restrict__ gb1, __half* __restrict__ yh, int split) {
    int blk = blockIdx.x;
    bool tohalf = (blk >= split);
    const float *x, *ga, *gb;
    int rowbase;
    if (!tohalf) { x = x0; ga = ga0; gb = gb0; rowbase = blk * 8; }
    else         { x = x1; ga = ga1; gb = gb1; rowbase = (blk - split) * 8; }
    int w = threadIdx.x >> 5, lane = threadIdx.x & 31;
    size_t row = rowbase + w;
    const float4* x4 = reinterpret_cast<const float4*>(x + row * Dsz);
    float4 v0 = x4[lane];
    float4 v1 = x4[lane + 32];

    float s = v0.x + v0.y + v0.z + v0.w + v1.x + v1.y + v1.z + v1.w;
#pragma unroll
    for (int o = 16; o; o >>= 1) s += __shfl_xor_sync(0xffffffffu, s, o);
    float mean = s * (1.0f / Dsz);

    float d0x = v0.x - mean, d0y = v0.y - mean, d0z = v0.z - mean, d0w = v0.w - mean;
    float d1x = v1.x - mean, d1y = v1.y - mean, d1z = v1.z - mean, d1w = v1.w - mean;
    float ss = d0x * d0x + d0y * d0y + d0z * d0z + d0w * d0w +
               d1x * d1x + d1y * d1y + d1z * d1z + d1w * d1w;
#pragma unroll
    for (int o = 16; o; o >>= 1) ss += __shfl_xor_sync(0xffffffffu, ss, o);
    float var = ss * (1.0f / (Dsz - 1));
    float inv = 1.0f / (sqrtf(var) + 1e-6f);

    const float4* ga4 = reinterpret_cast<const float4*>(ga);
    const float4* gb4 = reinterpret_cast<const float4*>(gb);
    float4 g0 = ga4[lane], g1 = ga4[lane + 32];
    float4 b0 = gb4[lane], b1 = gb4[lane + 32];
    float4 o0 = make_float4(g0.x * d0x * inv + b0.x, g0.y * d0y * inv + b0.y,
                            g0.z * d0z * inv + b0.z, g0.w * d0w * inv + b0.w);
    float4 o1 = make_float4(g1.x * d1x * inv + b1.x, g1.y * d1y * inv + b1.y,
                            g1.z * d1z * inv + b1.z, g1.w * d1w * inv + b1.w);
    if (!tohalf) {
        float4* y4 = reinterpret_cast<float4*>(yf + row * Dsz);
        y4[lane] = o0;
        y4[lane + 32] = o1;
    } else {
        uint2* y2 = reinterpret_cast<uint2*>(yh + row * Dsz);
        y2[lane] = make_uint2(packh2(o0.x, o0.y), packh2(o0.z, o0.w));
        y2[lane + 32] = make_uint2(packh2(o1.x, o1.y), packh2(o1.z, o1.w));
    }
}

// ---------------------------------------------------------------------------
// fp16 GEMM (fp32 accum), unchanged from R8.
// ---------------------------------------------------------------------------
#define GBM 128
#define GBN 128
#define HPITCH 80
#define TILE_B (128 * HPITCH)
#define STAGE_B (2 * TILE_B)

template <int EPI, bool STATS>
__global__ void __launch_bounds__(256) gemm_f16(
    const void* __restrict__ Aptr, const __half* __restrict__ W,
    const float* __restrict__ bias, const float* __restrict__ add,
    const float* __restrict__ sffn, float* __restrict__ out,
    const float* __restrict__ lga, const float* __restrict__ lgb,
    float* __restrict__ rsum, float* __restrict__ rsumsq) {
    extern __shared__ char gsm[];
    uint32_t smemU = (uint32_t)__cvta_generic_to_shared(gsm);

    int m0 = blockIdx.y * GBM;
    int n0 = blockIdx.x * GBN;
    int tid = threadIdx.x;
    int wid = tid >> 5, lane = tid & 31;
    int wm = wid >> 1, wn = wid & 1;
    int grp = lane >> 2, qd = lane & 3;

    int rA = (lane & 7) + ((lane >> 3) & 1) * 8;
    int offA = (wm * 32 + rA) * HPITCH + ((lane >> 4) & 1) * 16;
    int rB = (lane & 7) + ((lane >> 4) & 1) * 8;
    int offB = (wn * 64 + rB) * HPITCH + ((lane >> 3) & 1) * 16;

    float mean_t[4], inv_t[4];
    int lr = tid >> 3;
    int c4f = (tid & 7) * 4;
    if (EPI == 2) {
#pragma unroll
        for (int t = 0; t < 4; t++) {
            int r = m0 + lr + 32 * t;
            float s = rsum[r], sq = rsumsq[r];
            float mn = s * (1.0f / Dsz);
            float var = (sq - (float)Dsz * mn * mn) * (1.0f / (Dsz - 1));
            mean_t[t] = mn;
            inv_t[t] = 1.0f / (sqrtf(var) + 1e-6f);
        }
    }

    float acc[2][8][4];
#pragma unroll
    for (int i = 0; i < 2; i++)
#pragma unroll
        for (int n = 0; n < 8; n++)
#pragma unroll
            for (int e = 0; e < 4; e++) acc[i][n][e] = 0.f;

    int crow = tid >> 2, cu = tid & 3;
    const __half* Ah = (const __half*)Aptr;
    const float* Af = (const float*)Aptr;

    auto stageW = [&](int buf, int k0) {
        uint32_t sb = smemU + buf * STAGE_B + TILE_B;
        cp_async16(sb + crow * HPITCH + cu * 16,
                   W + (size_t)(n0 + crow) * Dsz + k0 + cu * 8);
        cp_async16(sb + (crow + 64) * HPITCH + cu * 16,
                   W + (size_t)(n0 + crow + 64) * Dsz + k0 + cu * 8);
    };
    auto stageA = [&](int buf, int k0) {
        uint32_t sa = smemU + buf * STAGE_B;
        cp_async16(sa + crow * HPITCH + cu * 16,
                   Ah + (size_t)(m0 + crow) * Dsz + k0 + cu * 8);
        cp_async16(sa + (crow + 64) * HPITCH + cu * 16,
                   Ah + (size_t)(m0 + crow + 64) * Dsz + k0 + cu * 8);
    };

    const int NSTEP = Dsz / 32;
    float4 pa[4];

    if (EPI == 2) {
#pragma unroll
        for (int t = 0; t < 4; t++)
            pa[t] = *reinterpret_cast<const float4*>(
                Af + (size_t)(m0 + lr + 32 * t) * Dsz + c4f);
        stageW(0, 0);
        asm volatile("cp.async.commit_group;");
    } else {
        stageA(0, 0);
        stageW(0, 0);
        asm volatile("cp.async.commit_group;");
    }

    for (int s = 0; s < NSTEP; s++) {
        if (EPI == 2) {
            float4 g4 = *reinterpret_cast<const float4*>(lga + s * 32 + c4f);
            float4 b4 = *reinterpret_cast<const float4*>(lgb + s * 32 + c4f);
            uint32_t sa = smemU + (s & 1) * STAGE_B;
#pragma unroll
            for (int t = 0; t < 4; t++) {
                int r = lr + 32 * t;
                float vx = (pa[t].x - mean_t[t]) * inv_t[t] * g4.x + b4.x;
                float vy = (pa[t].y - mean_t[t]) * inv_t[t] * g4.y + b4.y;
                float vz = (pa[t].z - mean_t[t]) * inv_t[t] * g4.z + b4.z;
                float vw = (pa[t].w - mean_t[t]) * inv_t[t] * g4.w + b4.w;
                asm volatile("st.shared.v2.b32 [%0], {%1,%2};"
                             :: "r"(sa + r * HPITCH + c4f * 2),
                                "r"(packh2(vx, vy)), "r"(packh2(vz, vw)));
            }
            if (s + 1 < NSTEP) {
#pragma unroll
                for (int t = 0; t < 4; t++)
                    pa[t] = *reinterpret_cast<const float4*>(
                        Af + (size_t)(m0 + lr + 32 * t) * Dsz + (s + 1) * 32 + c4f);
                stageW((s + 1) & 1, (s + 1) * 32);
                asm volatile("cp.async.commit_group;");
                asm volatile("cp.async.wait_group 1;");
            } else {
                asm volatile("cp.async.wait_group 0;");
            }
        } else {
            if (s + 1 < NSTEP) {
                stageA((s + 1) & 1, (s + 1) * 32);
                stageW((s + 1) & 1, (s + 1) * 32);
                asm volatile("cp.async.commit_group;");
                asm volatile("cp.async.wait_group 1;");
            } else {
                asm volatile("cp.async.wait_group 0;");
            }
        }
        __syncthreads();

        uint32_t aB = smemU + (s & 1) * STAGE_B + offA;
        uint32_t bB = smemU + (s & 1) * STAGE_B + TILE_B + offB;
#pragma unroll
        for (int kb = 0; kb < 2; kb++) {
            uint32_t af[2][4];
#pragma unroll
            for (int i = 0; i < 2; i++)
                ldsm_x4(af[i][0], af[i][1], af[i][2], af[i][3],
                        aB + i * 16 * HPITCH + kb * 32);
            uint32_t bf[8][2];
#pragma unroll
            for (int p = 0; p < 4; p++) {
                uint32_t r0, r1, r2, r3;
                ldsm_x4(r0, r1, r2, r3, bB + p * 16 * HPITCH + kb * 32);
                bf[2 * p][0] = r0; bf[2 * p][1] = r1;
                bf[2 * p + 1][0] = r2; bf[2 * p + 1][1] = r3;
            }
#pragma unroll
            for (int i = 0; i < 2; i++)
#pragma unroll
                for (int n = 0; n < 8; n++)
                    mma_f16(acc[i][n], af[i], bf[n][0], bf[n][1]);
        }
        __syncthreads();
    }

#pragma unroll
    for (int i = 0; i < 2; i++) {
        int mr0 = m0 + wm * 32 + i * 16 + grp;
        int mr1 = mr0 + 8;
        float sf0 = 0.f, sf1 = 0.f;
        if (EPI == 2) {
            sf0 = sffn[mr0 % Ssz];
            sf1 = sffn[mr1 % Ssz];
        }
        float s0 = 0.f, q0s = 0.f, s1 = 0.f, q1s = 0.f;
#pragma unroll
        for (int n = 0; n < 8; n++) {
            int col = n0 + wn * 64 + n * 8 + 2 * qd;
            float2 bv = *reinterpret_cast<const float2*>(bias + col);
            float2 a0 = *reinterpret_cast<const float2*>(
                add + (size_t)mr0 * Dsz + col);
            float2 a1 = *reinterpret_cast<const float2*>(
                add + (size_t)mr1 * Dsz + col);
            float r00 = acc[i][n][0] + bv.x, r01 = acc[i][n][1] + bv.y;
            float r10 = acc[i][n][2] + bv.x, r11 = acc[i][n][3] + bv.y;
            if (EPI == 0) {
                r00 += a0.x; r01 += a0.y; r10 += a1.x; r11 += a1.y;
                if (STATS) {
                    s0 += r00 + r01; q0s += r00 * r00 + r01 * r01;
                    s1 += r10 + r11; q1s += r10 * r10 + r11 * r11;
                }
            } else {
                float z, th;
                z = sf0 * r00;
                th = tanhf(0.79788456080286536f * (z + 0.044715f * z * z * z));
                r00 = a0.x + 0.5f * z * (1.0f + th);
                z = sf0 * r01;
                th = tanhf(0.79788456080286536f * (z + 0.044715f * z * z * z));
                r01 = a0.y + 0.5f * z * (1.0f + th);
                z = sf1 * r10;
                th = tanhf(0.79788456080286536f * (z + 0.044715f * z * z * z));
                r10 = a1.x + 0.5f * z * (1.0f + th);
                z = sf1 * r11;
                th = tanhf(0.79788456080286536f * (z + 0.044715f * z * z * z));
                r11 = a1.y + 0.5f * z * (1.0f + th);
            }
            *reinterpret_cast<float2*>(out + (size_t)mr0 * Dsz + col) =
                make_float2(r00, r01);
            *reinterpret_cast<float2*>(out + (size_t)mr1 * Dsz + col) =
                make_float2(r10, r11);
        }
        if (STATS) {
            const unsigned FULL = 0xffffffffu;
            s0 += __shfl_xor_sync(FULL, s0, 1);
            s0 += __shfl_xor_sync(FULL, s0, 2);
            q0s += __shfl_xor_sync(FULL, q0s, 1);
            q0s += __shfl_xor_sync(FULL, q0s, 2);
            s1 += __shfl_xor_sync(FULL, s1, 1);
            s1 += __shfl_xor_sync(FULL, s1, 2);
            q1s += __shfl_xor_sync(FULL, q1s, 1);
            q1s += __shfl_xor_sync(FULL, q1s, 2);
            if (qd == 0) {
                atomicAdd(&rsum[mr0], s0);
                atomicAdd(&rsumsq[mr0], q0s);
                atomicAdd(&rsum[mr1], s1);
                atomicAdd(&rsumsq[mr1], q1s);
            }
        }
    }
}

// ---------------------------------------------------------------------------
// fp16 register flash-attention. 13 warps, 1 q-tile/warp.
// Q/V (img_n) and K (keff) in half smem (80B pitch). Scores & P.V via
// mma.m16n8k16.f16 with ldmatrix fragment loads; S C-frag == P A-frag
// layout (no shuffles). V via ldmatrix.trans. ctx written half.
// ---------------------------------------------------------------------------
#define SPAD 208
#define HP 80                    // bytes per row (32 halves + pad)
#define QV_B (SPAD * HP)         // 16640
#define ATHR 416

__global__ void __launch_bounds__(ATHR) attn_flash(
    const float* __restrict__ img_n, const float* __restrict__ keff,
    const int* __restrict__ mask, const float* __restrict__ sattn,
    __half* __restrict__ ctx_h) {
    extern __shared__ char smw[];
    uint32_t smemU = (uint32_t)__cvta_generic_to_shared(smw);
    uint32_t qvU = smemU;
    uint32_t ksU = smemU + QV_B;
    float* m_s = reinterpret_cast<float*>(smw + 2 * QV_B);

    int b = blockIdx.x >> 3;
    int h = blockIdx.x & 7;
    int tid = threadIdx.x;
    size_t base = ((size_t)b * Ssz) * Dsz + h * DHsz;

    for (int idx = tid; idx < SPAD * 8; idx += ATHR) {
        int r = idx >> 3, c4 = (idx & 7) * 4;
        float4 qv = make_float4(0.f, 0.f, 0.f, 0.f);
        float4 kv = make_float4(0.f, 0.f, 0.f, 0.f);
        if (r < Ssz) {
            qv = *reinterpret_cast<const float4*>(img_n + base + (size_t)r * Dsz + c4);
            kv = *reinterpret_cast<const float4*>(keff + base + (size_t)r * Dsz + c4);
        }
        asm volatile("st.shared.v2.b32 [%0], {%1,%2};"
                     :: "r"(qvU + r * HP + c4 * 2),
                        "r"(packh2(qv.x, qv.y)), "r"(packh2(qv.z, qv.w)));
        asm volatile("st.shared.v2.b32 [%0], {%1,%2};"
                     :: "r"(ksU + r * HP + c4 * 2),
                        "r"(packh2(kv.x, kv.y)), "r"(packh2(kv.z, kv.w)));
    }
    for (int k = tid; k < SPAD; k += ATHR)
        m_s[k] = (k >= Ssz || mask[b * Ssz + k] == 0) ? 1.f : 0.f;
    __syncthreads();

    int w = tid >> 5, lane = tid & 31;
    int grp = lane >> 2;
    int qd = lane & 3;
    const float isq = 0.17677669529663687f;
    const unsigned FULL = 0xffffffffu;

    int q0 = w * 16;
    int qr0 = q0 + grp, qr1 = q0 + grp + 8;
    float f0 = (qr0 < Ssz) ? isq * sattn[h * Ssz + qr0] : 0.f;
    float f1 = (qr1 < Ssz) ? isq * sattn[h * Ssz + qr1] : 0.f;

    // Q A-frags: 16 rows x 32 k -> two x4 ldmatrix
    uint32_t aq[2][4];
    {
        int rA = (lane & 7) + ((lane >> 3) & 1) * 8;
        uint32_t offA = qvU + (q0 + rA) * HP + ((lane >> 4) & 1) * 16;
        ldsm_x4(aq[0][0], aq[0][1], aq[0][2], aq[0][3], offA);
        ldsm_x4(aq[1][0], aq[1][1], aq[1][2], aq[1][3], offA + 32);
    }

    int rB = (lane & 7) + ((lane >> 4) & 1) * 8;     // keys for K (B-frag)
    int rV = (lane & 7) + ((lane >> 3) & 1) * 8;     // keys for V (trans)
    int cB = ((lane >> 3) & 1) * 16;
    int cV = ((lane >> 4) & 1) * 16;

    float m0 = -3.0e38f, m1 = -3.0e38f, l0 = 0.f, l1 = 0.f;
    float co[4][4];
#pragma unroll
    for (int n = 0; n < 4; n++)
#pragma unroll
        for (int e = 0; e < 4; e++) co[n][e] = 0.f;

    for (int nt = 0; nt < 13; nt++) {
        int key0 = nt * 16;
        // ---- scores S[16q][16k] ----
        float s[2][4] = {{0.f, 0.f, 0.f, 0.f}, {0.f, 0.f, 0.f, 0.f}};
        uint32_t offB = ksU + (key0 + rB) * HP + cB;
#pragma unroll
        for (int kk = 0; kk < 2; kk++) {
            uint32_t r0, r1, r2, r3;
            ldsm_x4(r0, r1, r2, r3, offB + kk * 32);
            mma_f16(s[0], aq[kk], r0, r1);
            mma_f16(s[1], aq[kk], r2, r3);
        }
        // ---- scale + mask + online softmax ----
        float pv[2][4];
        float rm0 = -3.0e38f, rm1 = -3.0e38f;
#pragma unroll
        for (int n = 0; n < 2; n++) {
            int c = key0 + n * 8 + 2 * qd;
            float mk0 = m_s[c], mk1 = m_s[c + 1];
            float v0 = (mk0 != 0.f) ? -1e9f : s[n][0] * f0;
            float v1 = (mk1 != 0.f) ? -1e9f : s[n][1] * f0;
            float v2 = (mk0 != 0.f) ? -1e9f : s[n][2] * f1;
            float v3 = (mk1 != 0.f) ? -1e9f : s[n][3] * f1;
            pv[n][0] = v0; pv[n][1] = v1; pv[n][2] = v2; pv[n][3] = v3;
            rm0 = fmaxf(rm0, fmaxf(v0, v1));
            rm1 = fmaxf(rm1, fmaxf(v2, v3));
        }
        rm0 = fmaxf(rm0, __shfl_xor_sync(FULL, rm0, 1));
        rm0 = fmaxf(rm0, __shfl_xor_sync(FULL, rm0, 2));
        rm1 = fmaxf(rm1, __shfl_xor_sync(FULL, rm1, 1));
        rm1 = fmaxf(rm1, __shfl_xor_sync(FULL, rm1, 2));
        float nm0 = fmaxf(m0, rm0), nm1 = fmaxf(m1, rm1);
        float al0 = __expf(m0 - nm0), al1 = __expf(m1 - nm1);
        m0 = nm0; m1 = nm1;
        float ts0 = 0.f, ts1 = 0.f;
#pragma unroll
        for (int n = 0; n < 2; n++) {
            pv[n][0] = __expf(pv[n][0] - nm0);
            pv[n][1] = __expf(pv[n][1] - nm0);
            pv[n][2] = __expf(pv[n][2] - nm1);
            pv[n][3] = __expf(pv[n][3] - nm1);
            ts0 += pv[n][0] + pv[n][1];
            ts1 += pv[n][2] + pv[n][3];
        }
        ts0 += __shfl_xor_sync(FULL, ts0, 1);
        ts0 += __shfl_xor_sync(FULL, ts0, 2);
        ts1 += __shfl_xor_sync(FULL, ts1, 1);
        ts1 += __shfl_xor_sync(FULL, ts1, 2);
        l0 = l0 * al0 + ts0;
        l1 = l1 * al1 + ts1;
#pragma unroll
        for (int n = 0; n < 4; n++) {
            co[n][0] *= al0; co[n][1] *= al0;
            co[n][2] *= al1; co[n][3] *= al1;
        }
        // ---- P A-frag = packed S C-frag (no shuffles) ----
        uint32_t ap[4];
        ap[0] = packh2(pv[0][0], pv[0][1]);
        ap[1] = packh2(pv[0][2], pv[0][3]);
        ap[2] = packh2(pv[1][0], pv[1][1]);
        ap[3] = packh2(pv[1][2], pv[1][3]);
        // ---- P.V: V B-frags via ldmatrix.trans ----
        uint32_t offV = qvU + (key0 + rV) * HP + cV;
        {
            uint32_t r0, r1, r2, r3;
            ldsm_x4t(r0, r1, r2, r3, offV);
            mma_f16(co[0], ap, r0, r1);
            mma_f16(co[1], ap, r2, r3);
            ldsm_x4t(r0, r1, r2, r3, offV + 32);
            mma_f16(co[2], ap, r0, r1);
            mma_f16(co[3], ap, r2, r3);
        }
    }

    float inv0 = 1.f / l0, inv1 = 1.f / l1;
#pragma unroll
    for (int n4 = 0; n4 < 4; n4++) {
        if (qr0 < Ssz) {
            __half2 v = __floats2half2_rn(co[n4][0] * inv0, co[n4][1] * inv0);
            *reinterpret_cast<__half2*>(
                ctx_h + base + (size_t)qr0 * Dsz + n4 * 8 + 2 * qd) = v;
        }
        if (qr1 < Ssz) {
            __half2 v = __floats2half2_rn(co[n4][2] * inv1, co[n4][3] * inv1);
            *reinterpret_cast<__half2*>(
                ctx_h + base + (size_t)qr1 * Dsz + n4 * 8 + 2 * qd) = v;
        }
    }
}

// ---------------------------------------------------------------------------
extern "C" void kernel_launch(void* const* d_in, const int* in_sizes, int n_in,
                              void* d_out, int out_size) {
    const float* hidden_img   = (const float*)d_in[0];
    const float* hidden_title = (const float*)d_in[1];
    const int*   mask         = (const int*)  d_in[2];
    const float* a_img   = (const float*)d_in[3];
    const float* b_img   = (const float*)d_in[4];
    const float* a_title = (const float*)d_in[5];
    const float* b_title = (const float*)d_in[6];
    const float* Wb      = (const float*)d_in[7];
    const float* bb      = (const float*)d_in[8];
    const float* Wo      = (const float*)d_in[9];
    const float* bo      = (const float*)d_in[10];
    const float* sattn   = (const float*)d_in[11];
    const float* a_out   = (const float*)d_in[12];
    const float* b_out   = (const float*)d_in[13];
    const float* W1      = (const float*)d_in[14];
    const float* b1      = (const float*)d_in[15];
    const float* sffn    = (const float*)d_in[16];
    float* out = (float*)d_out;

    float *img_n, *keff, *h1, *rsum, *rsumsq;
    __half *title_h, *ctx_h, *Wb_h, *Wo_h, *W1_h;
    cudaGetSymbolAddress((void**)&img_n,   g_img_n);
    cudaGetSymbolAddress((void**)&keff,    g_keff);
    cudaGetSymbolAddress((void**)&h1,      g_h1);
    cudaGetSymbolAddress((void**)&rsum,    g_rsum);
    cudaGetSymbolAddress((void**)&rsumsq,  g_rsumsq);
    cudaGetSymbolAddress((void**)&title_h, g_title_h);
    cudaGetSymbolAddress((void**)&ctx_h,   g_ctx_h);
    cudaGetSymbolAddress((void**)&Wb_h,    g_Wb_h);
    cudaGetSymbolAddress((void**)&Wo_h,    g_Wo_h);
    cudaGetSymbolAddress((void**)&W1_h,    g_W1_h);

    const int LNB = BS / 8;
    const int gemm_smem = 2 * STAGE_B;   // 40960 bytes
    cudaFuncSetAttribute((const void*)gemm_f16<0, false>,
                         cudaFuncAttributeMaxDynamicSharedMemorySize, gemm_smem);
    cudaFuncSetAttribute((const void*)gemm_f16<0, true>,
                         cudaFuncAttributeMaxDynamicSharedMemorySize, gemm_smem);
    cudaFuncSetAttribute((const void*)gemm_f16<2, false>,
                         cudaFuncAttributeMaxDynamicSharedMemorySize, gemm_smem);

    cudaMemsetAsync(rsum, 0, BS * sizeof(float));
    cudaMemsetAsync(rsumsq, 0, BS * sizeof(float));

    // 0) weights -> half
    w2h_kernel<<<384, 256>>>(Wb, Wo, W1, Wb_h, Wo_h, W1_h);

    // 1) both input LayerNorms (img -> float, title -> half)
    ln_fast<<<2 * LNB, 256>>>(hidden_img, a_img, b_img, img_n,
                              hidden_title, a_title, b_title, title_h, LNB);

    // 2) keff = title_n @ Wb^T + bb + img_n
    dim3 gg(Dsz / GBN, BS / GBM);
    gemm_f16<0, false><<<gg, 256, gemm_smem>>>(
        title_h, Wb_h, bb, img_n, nullptr, keff, nullptr, nullptr, nullptr, nullptr);

    // 3) fp16 flash attention -> ctx half
    const int attn_smem = 2 * QV_B + SPAD * 4;   // 34112 B
    cudaFuncSetAttribute(attn_flash,
                         cudaFuncAttributeMaxDynamicSharedMemorySize, attn_smem);
    attn_flash<<<Bsz * Hsz, ATHR, attn_smem>>>(img_n, keff, mask, sattn, ctx_h);

    // 4) h1 = ctx @ Wo^T + bo + hidden_img  (+ row stats)
    gemm_f16<0, true><<<gg, 256, gemm_smem>>>(
        ctx_h, Wo_h, bo, hidden_img, nullptr, h1, nullptr, nullptr, rsum, rsumsq);

    // 5) out = h1 + gelu_tanh(scale_ffn * (LN(h1) @ W1^T + b1))
    gemm_f16<2, false><<<gg, 256, gemm_smem>>>(
        h1, W1_h, b1, h1, sffn, out, a_out, b_out, rsum, rsumsq);
}

// round 11
// speedup vs baseline: 4.2057x; 1.0412x over previous
#include <cuda_runtime.h>
#include <cuda_fp16.h>
#include <math.h>
#include <stdint.h>

#define Bsz 256
#define Ssz 200
#define Dsz 256
#define Hsz 8
#define DHsz 32
#define BS (Bsz * Ssz)   // 51200 rows

__device__ float g_img_n[BS * Dsz];
__device__ float g_keff[BS * Dsz];
__device__ float g_h1[BS * Dsz];
__device__ float g_rsum[BS];
__device__ float g_rsumsq[BS];
__device__ __half g_title_h[BS * Dsz];
__device__ __half g_ctx_h[BS * Dsz];
__device__ __half g_Wb_h[Dsz * Dsz];
__device__ __half g_Wo_h[Dsz * Dsz];
__device__ __half g_W1_h[Dsz * Dsz];

__device__ __forceinline__ void mma_f16(float* c, const uint32_t* a,
                                        uint32_t b0, uint32_t b1) {
    asm volatile(
        "mma.sync.aligned.m16n8k16.row.col.f32.f16.f16.f32 "
        "{%0,%1,%2,%3}, {%4,%5,%6,%7}, {%8,%9}, {%0,%1,%2,%3};"
        : "+f"(c[0]), "+f"(c[1]), "+f"(c[2]), "+f"(c[3])
        : "r"(a[0]), "r"(a[1]), "r"(a[2]), "r"(a[3]), "r"(b0), "r"(b1));
}

__device__ __forceinline__ void ldsm_x4(uint32_t& r0, uint32_t& r1,
                                        uint32_t& r2, uint32_t& r3,
                                        uint32_t addr) {
    asm volatile(
        "ldmatrix.sync.aligned.m8n8.x4.shared.b16 {%0,%1,%2,%3}, [%4];"
        : "=r"(r0), "=r"(r1), "=r"(r2), "=r"(r3) : "r"(addr));
}

__device__ __forceinline__ void ldsm_x4t(uint32_t& r0, uint32_t& r1,
                                         uint32_t& r2, uint32_t& r3,
                                         uint32_t addr) {
    asm volatile(
        "ldmatrix.sync.aligned.m8n8.x4.trans.shared.b16 {%0,%1,%2,%3}, [%4];"
        : "=r"(r0), "=r"(r1), "=r"(r2), "=r"(r3) : "r"(addr));
}

__device__ __forceinline__ void cp_async16(uint32_t smem, const void* g) {
    asm volatile("cp.async.cg.shared.global [%0], [%1], 16;"
                 :: "r"(smem), "l"(g));
}

__device__ __forceinline__ uint32_t packh2(float a, float b) {
    __half2 h = __floats2half2_rn(a, b);
    return *reinterpret_cast<uint32_t*>(&h);
}

// ---------------------------------------------------------------------------
// Weights -> half + zero rsum/rsumsq (one launch).
// ---------------------------------------------------------------------------
__global__ void __launch_bounds__(256) w2h_kernel(
    const float* __restrict__ w0, const float* __restrict__ w1,
    const float* __restrict__ w2, __half* __restrict__ h0,
    __half* __restrict__ h1, __half* __restrict__ h2,
    float* __restrict__ rsum, float* __restrict__ rsumsq) {
    int i = blockIdx.x * 256 + threadIdx.x;
    if (i < 98304) {
        const float2* s;
        __half2* d;
        int j;
        if (i < 32768)      { s = (const float2*)w0; d = (__half2*)h0; j = i; }
        else if (i < 65536) { s = (const float2*)w1; d = (__half2*)h1; j = i - 32768; }
        else                { s = (const float2*)w2; d = (__half2*)h2; j = i - 65536; }
        float2 v = s[j];
        d[j] = __floats2half2_rn(v.x, v.y);
    } else {
        int j = i - 98304;   // 0..25599 float4 units
        float4 z = make_float4(0.f, 0.f, 0.f, 0.f);
        if (j < 12800) reinterpret_cast<float4*>(rsum)[j] = z;
        else           reinterpret_cast<float4*>(rsumsq)[j - 12800] = z;
    }
}

// ---------------------------------------------------------------------------
// Warp-per-row LayerNorm. Stream 0 -> float out; stream 1 -> half out.
// ---------------------------------------------------------------------------
__global__ void __launch_bounds__(256) ln_fast(
    const float* __restrict__ x0, const float* __restrict__ ga0,
    const float* __restrict__ gb0, float* __restrict__ yf,
    const float* __restrict__ x1, const float* __restrict__ ga1,
    const float* __restrict__ gb1, __half* __restrict__ yh, int split) {
    int blk = blockIdx.x;
    bool tohalf = (blk >= split);
    const float *x, *ga, *gb;
    int rowbase;
    if (!tohalf) { x = x0; ga = ga0; gb = gb0; rowbase = blk * 8; }
    else         { x = x1; ga = ga1; gb = gb1; rowbase = (blk - split) * 8; }
    int w = threadIdx.x >> 5, lane = threadIdx.x & 31;
    size_t row = rowbase + w;
    const float4* x4 = reinterpret_cast<const float4*>(x + row * Dsz);
    float4 v0 = x4[lane];
    float4 v1 = x4[lane + 32];

    float s = v0.x + v0.y + v0.z + v0.w + v1.x + v1.y + v1.z + v1.w;
#pragma unroll
    for (int o = 16; o; o >>= 1) s += __shfl_xor_sync(0xffffffffu, s, o);
    float mean = s * (1.0f / Dsz);

    float d0x = v0.x - mean, d0y = v0.y - mean, d0z = v0.z - mean, d0w = v0.w - mean;
    float d1x = v1.x - mean, d1y = v1.y - mean, d1z = v1.z - mean, d1w = v1.w - mean;
    float ss = d0x * d0x + d0y * d0y + d0z * d0z + d0w * d0w +
               d1x * d1x + d1y * d1y + d1z * d1z + d1w * d1w;
#pragma unroll
    for (int o = 16; o; o >>= 1) ss += __shfl_xor_sync(0xffffffffu, ss, o);
    float var = ss * (1.0f / (Dsz - 1));
    float inv = 1.0f / (sqrtf(var) + 1e-6f);

    const float4* ga4 = reinterpret_cast<const float4*>(ga);
    const float4* gb4 = reinterpret_cast<const float4*>(gb);
    float4 g0 = ga4[lane], g1 = ga4[lane + 32];
    float4 b0 = gb4[lane], b1 = gb4[lane + 32];
    float4 o0 = make_float4(g0.x * d0x * inv + b0.x, g0.y * d0y * inv + b0.y,
                            g0.z * d0z * inv + b0.z, g0.w * d0w * inv + b0.w);
    float4 o1 = make_float4(g1.x * d1x * inv + b1.x, g1.y * d1y * inv + b1.y,
                            g1.z * d1z * inv + b1.z, g1.w * d1w * inv + b1.w);
    if (!tohalf) {
        float4* y4 = reinterpret_cast<float4*>(yf + row * Dsz);
        y4[lane] = o0;
        y4[lane + 32] = o1;
    } else {
        uint2* y2 = reinterpret_cast<uint2*>(yh + row * Dsz);
        y2[lane] = make_uint2(packh2(o0.x, o0.y), packh2(o0.z, o0.w));
        y2[lane + 32] = make_uint2(packh2(o1.x, o1.y), packh2(o1.z, o1.w));
    }
}

// ---------------------------------------------------------------------------
// fp16 GEMM (fp32 accum), unchanged.
// ---------------------------------------------------------------------------
#define GBM 128
#define GBN 128
#define HPITCH 80
#define TILE_B (128 * HPITCH)
#define STAGE_B (2 * TILE_B)

template <int EPI, bool STATS>
__global__ void __launch_bounds__(256) gemm_f16(
    const void* __restrict__ Aptr, const __half* __restrict__ W,
    const float* __restrict__ bias, const float* __restrict__ add,
    const float* __restrict__ sffn, float* __restrict__ out,
    const float* __restrict__ lga, const float* __restrict__ lgb,
    float* __restrict__ rsum, float* __restrict__ rsumsq) {
    extern __shared__ char gsm[];
    uint32_t smemU = (uint32_t)__cvta_generic_to_shared(gsm);

    int m0 = blockIdx.y * GBM;
    int n0 = blockIdx.x * GBN;
    int tid = threadIdx.x;
    int wid = tid >> 5, lane = tid & 31;
    int wm = wid >> 1, wn = wid & 1;
    int grp = lane >> 2, qd = lane & 3;

    int rA = (lane & 7) + ((lane >> 3) & 1) * 8;
    int offA = (wm * 32 + rA) * HPITCH + ((lane >> 4) & 1) * 16;
    int rB = (lane & 7) + ((lane >> 4) & 1) * 8;
    int offB = (wn * 64 + rB) * HPITCH + ((lane >> 3) & 1) * 16;

    float mean_t[4], inv_t[4];
    int lr = tid >> 3;
    int c4f = (tid & 7) * 4;
    if (EPI == 2) {
#pragma unroll
        for (int t = 0; t < 4; t++) {
            int r = m0 + lr + 32 * t;
            float s = rsum[r], sq = rsumsq[r];
            float mn = s * (1.0f / Dsz);
            float var = (sq - (float)Dsz * mn * mn) * (1.0f / (Dsz - 1));
            mean_t[t] = mn;
            inv_t[t] = 1.0f / (sqrtf(var) + 1e-6f);
        }
    }

    float acc[2][8][4];
#pragma unroll
    for (int i = 0; i < 2; i++)
#pragma unroll
        for (int n = 0; n < 8; n++)
#pragma unroll
            for (int e = 0; e < 4; e++) acc[i][n][e] = 0.f;

    int crow = tid >> 2, cu = tid & 3;
    const __half* Ah = (const __half*)Aptr;
    const float* Af = (const float*)Aptr;

    auto stageW = [&](int buf, int k0) {
        uint32_t sb = smemU + buf * STAGE_B + TILE_B;
        cp_async16(sb + crow * HPITCH + cu * 16,
                   W + (size_t)(n0 + crow) * Dsz + k0 + cu * 8);
        cp_async16(sb + (crow + 64) * HPITCH + cu * 16,
                   W + (size_t)(n0 + crow + 64) * Dsz + k0 + cu * 8);
    };
    auto stageA = [&](int buf, int k0) {
        uint32_t sa = smemU + buf * STAGE_B;
        cp_async16(sa + crow * HPITCH + cu * 16,
                   Ah + (size_t)(m0 + crow) * Dsz + k0 + cu * 8);
        cp_async16(sa + (crow + 64) * HPITCH + cu * 16,
                   Ah + (size_t)(m0 + crow + 64) * Dsz + k0 + cu * 8);
    };

    const int NSTEP = Dsz / 32;
    float4 pa[4];

    if (EPI == 2) {
#pragma unroll
        for (int t = 0; t < 4; t++)
            pa[t] = *reinterpret_cast<const float4*>(
                Af + (size_t)(m0 + lr + 32 * t) * Dsz + c4f);
        stageW(0, 0);
        asm volatile("cp.async.commit_group;");
    } else {
        stageA(0, 0);
        stageW(0, 0);
        asm volatile("cp.async.commit_group;");
    }

    for (int s = 0; s < NSTEP; s++) {
        if (EPI == 2) {
            float4 g4 = *reinterpret_cast<const float4*>(lga + s * 32 + c4f);
            float4 b4 = *reinterpret_cast<const float4*>(lgb + s * 32 + c4f);
            uint32_t sa = smemU + (s & 1) * STAGE_B;
#pragma unroll
            for (int t = 0; t < 4; t++) {
                int r = lr + 32 * t;
                float vx = (pa[t].x - mean_t[t]) * inv_t[t] * g4.x + b4.x;
                float vy = (pa[t].y - mean_t[t]) * inv_t[t] * g4.y + b4.y;
                float vz = (pa[t].z - mean_t[t]) * inv_t[t] * g4.z + b4.z;
                float vw = (pa[t].w - mean_t[t]) * inv_t[t] * g4.w + b4.w;
                asm volatile("st.shared.v2.b32 [%0], {%1,%2};"
                             :: "r"(sa + r * HPITCH + c4f * 2),
                                "r"(packh2(vx, vy)), "r"(packh2(vz, vw)));
            }
            if (s + 1 < NSTEP) {
#pragma unroll
                for (int t = 0; t < 4; t++)
                    pa[t] = *reinterpret_cast<const float4*>(
                        Af + (size_t)(m0 + lr + 32 * t) * Dsz + (s + 1) * 32 + c4f);
                stageW((s + 1) & 1, (s + 1) * 32);
                asm volatile("cp.async.commit_group;");
                asm volatile("cp.async.wait_group 1;");
            } else {
                asm volatile("cp.async.wait_group 0;");
            }
        } else {
            if (s + 1 < NSTEP) {
                stageA((s + 1) & 1, (s + 1) * 32);
                stageW((s + 1) & 1, (s + 1) * 32);
                asm volatile("cp.async.commit_group;");
                asm volatile("cp.async.wait_group 1;");
            } else {
                asm volatile("cp.async.wait_group 0;");
            }
        }
        __syncthreads();

        uint32_t aB = smemU + (s & 1) * STAGE_B + offA;
        uint32_t bB = smemU + (s & 1) * STAGE_B + TILE_B + offB;
#pragma unroll
        for (int kb = 0; kb < 2; kb++) {
            uint32_t af[2][4];
#pragma unroll
            for (int i = 0; i < 2; i++)
                ldsm_x4(af[i][0], af[i][1], af[i][2], af[i][3],
                        aB + i * 16 * HPITCH + kb * 32);
            uint32_t bf[8][2];
#pragma unroll
            for (int p = 0; p < 4; p++) {
                uint32_t r0, r1, r2, r3;
                ldsm_x4(r0, r1, r2, r3, bB + p * 16 * HPITCH + kb * 32);
                bf[2 * p][0] = r0; bf[2 * p][1] = r1;
                bf[2 * p + 1][0] = r2; bf[2 * p + 1][1] = r3;
            }
#pragma unroll
            for (int i = 0; i < 2; i++)
#pragma unroll
                for (int n = 0; n < 8; n++)
                    mma_f16(acc[i][n], af[i], bf[n][0], bf[n][1]);
        }
        __syncthreads();
    }

#pragma unroll
    for (int i = 0; i < 2; i++) {
        int mr0 = m0 + wm * 32 + i * 16 + grp;
        int mr1 = mr0 + 8;
        float sf0 = 0.f, sf1 = 0.f;
        if (EPI == 2) {
            sf0 = sffn[mr0 % Ssz];
            sf1 = sffn[mr1 % Ssz];
        }
        float s0 = 0.f, q0s = 0.f, s1 = 0.f, q1s = 0.f;
#pragma unroll
        for (int n = 0; n < 8; n++) {
            int col = n0 + wn * 64 + n * 8 + 2 * qd;
            float2 bv = *reinterpret_cast<const float2*>(bias + col);
            float2 a0 = *reinterpret_cast<const float2*>(
                add + (size_t)mr0 * Dsz + col);
            float2 a1 = *reinterpret_cast<const float2*>(
                add + (size_t)mr1 * Dsz + col);
            float r00 = acc[i][n][0] + bv.x, r01 = acc[i][n][1] + bv.y;
            float r10 = acc[i][n][2] + bv.x, r11 = acc[i][n][3] + bv.y;
            if (EPI == 0) {
                r00 += a0.x; r01 += a0.y; r10 += a1.x; r11 += a1.y;
                if (STATS) {
                    s0 += r00 + r01; q0s += r00 * r00 + r01 * r01;
                    s1 += r10 + r11; q1s += r10 * r10 + r11 * r11;
                }
            } else {
                float z, th;
                z = sf0 * r00;
                th = tanhf(0.79788456080286536f * (z + 0.044715f * z * z * z));
                r00 = a0.x + 0.5f * z * (1.0f + th);
                z = sf0 * r01;
                th = tanhf(0.79788456080286536f * (z + 0.044715f * z * z * z));
                r01 = a0.y + 0.5f * z * (1.0f + th);
                z = sf1 * r10;
                th = tanhf(0.79788456080286536f * (z + 0.044715f * z * z * z));
                r10 = a1.x + 0.5f * z * (1.0f + th);
                z = sf1 * r11;
                th = tanhf(0.79788456080286536f * (z + 0.044715f * z * z * z));
                r11 = a1.y + 0.5f * z * (1.0f + th);
            }
            *reinterpret_cast<float2*>(out + (size_t)mr0 * Dsz + col) =
                make_float2(r00, r01);
            *reinterpret_cast<float2*>(out + (size_t)mr1 * Dsz + col) =
                make_float2(r10, r11);
        }
        if (STATS) {
            const unsigned FULL = 0xffffffffu;
            s0 += __shfl_xor_sync(FULL, s0, 1);
            s0 += __shfl_xor_sync(FULL, s0, 2);
            q0s += __shfl_xor_sync(FULL, q0s, 1);
            q0s += __shfl_xor_sync(FULL, q0s, 2);
            s1 += __shfl_xor_sync(FULL, s1, 1);
            s1 += __shfl_xor_sync(FULL, s1, 2);
            q1s += __shfl_xor_sync(FULL, q1s, 1);
            q1s += __shfl_xor_sync(FULL, q1s, 2);
            if (qd == 0) {
                atomicAdd(&rsum[mr0], s0);
                atomicAdd(&rsumsq[mr0], q0s);
                atomicAdd(&rsum[mr1], s1);
                atomicAdd(&rsumsq[mr1], q1s);
            }
        }
    }
}

// ---------------------------------------------------------------------------
// fp16 flash-attention, ONLINE max softmax (p<=1 so fp16 pack is safe),
// 32-key double tiles (one max-reduce/rescale per 32 keys), deferred
// per-thread ell with end reduction. S padded to 224 (V=0, bias=-1e9).
// ---------------------------------------------------------------------------
#define SPAD 224
#define HP 80
#define QV_B (SPAD * HP)        // 17920
#define ATHR 416

__global__ void __launch_bounds__(ATHR) attn_flash(
    const float* __restrict__ img_n, const float* __restrict__ keff,
    const int* __restrict__ mask, const float* __restrict__ sattn,
    __half* __restrict__ ctx_h) {
    extern __shared__ char smw[];
    uint32_t smemU = (uint32_t)__cvta_generic_to_shared(smw);
    uint32_t qvU = smemU;
    uint32_t ksU = smemU + QV_B;
    float* bias_s = reinterpret_cast<float*>(smw + 2 * QV_B);  // 0 or -1e9

    int b = blockIdx.x >> 3;
    int h = blockIdx.x & 7;
    int tid = threadIdx.x;
    size_t base = ((size_t)b * Ssz) * Dsz + h * DHsz;

    for (int idx = tid; idx < SPAD * 8; idx += ATHR) {
        int r = idx >> 3, c4 = (idx & 7) * 4;
        float4 qv = make_float4(0.f, 0.f, 0.f, 0.f);
        float4 kv = make_float4(0.f, 0.f, 0.f, 0.f);
        if (r < Ssz) {
            qv = *reinterpret_cast<const float4*>(img_n + base + (size_t)r * Dsz + c4);
            kv = *reinterpret_cast<const float4*>(keff + base + (size_t)r * Dsz + c4);
        }
        asm volatile("st.shared.v2.b32 [%0], {%1,%2};"
                     :: "r"(qvU + r * HP + c4 * 2),
                        "r"(packh2(qv.x, qv.y)), "r"(packh2(qv.z, qv.w)));
        asm volatile("st.shared.v2.b32 [%0], {%1,%2};"
                     :: "r"(ksU + r * HP + c4 * 2),
                        "r"(packh2(kv.x, kv.y)), "r"(packh2(kv.z, kv.w)));
    }
    for (int k = tid; k < SPAD; k += ATHR)
        bias_s[k] = (k >= Ssz || mask[b * Ssz + k] == 0) ? -1e9f : 0.f;
    __syncthreads();

    int w = tid >> 5, lane = tid & 31;
    int grp = lane >> 2;
    int qd = lane & 3;
    const float isq = 0.17677669529663687f;
    const unsigned FULL = 0xffffffffu;

    int q0 = w * 16;
    int qr0 = q0 + grp, qr1 = q0 + grp + 8;
    float f0 = (qr0 < Ssz) ? isq * sattn[h * Ssz + qr0] : 0.f;
    float f1 = (qr1 < Ssz) ? isq * sattn[h * Ssz + qr1] : 0.f;

    uint32_t aq[2][4];
    {
        int rA = (lane & 7) + ((lane >> 3) & 1) * 8;
        uint32_t offA = qvU + (q0 + rA) * HP + ((lane >> 4) & 1) * 16;
        ldsm_x4(aq[0][0], aq[0][1], aq[0][2], aq[0][3], offA);
        ldsm_x4(aq[1][0], aq[1][1], aq[1][2], aq[1][3], offA + 32);
    }

    int rB = (lane & 7) + ((lane >> 4) & 1) * 8;
    int rV = (lane & 7) + ((lane >> 3) & 1) * 8;
    int cB = ((lane >> 3) & 1) * 16;
    int cV = ((lane >> 4) & 1) * 16;

    float m0 = -3.0e38f, m1 = -3.0e38f, l0 = 0.f, l1 = 0.f;
    float co[4][4];
#pragma unroll
    for (int n = 0; n < 4; n++)
#pragma unroll
        for (int e = 0; e < 4; e++) co[n][e] = 0.f;

    for (int it = 0; it < 7; it++) {
        int key0 = it * 32;
        // ---- scores for 32 keys (two 16-key tiles A/B) ----
        float sA[2][4] = {{0.f, 0.f, 0.f, 0.f}, {0.f, 0.f, 0.f, 0.f}};
        float sB[2][4] = {{0.f, 0.f, 0.f, 0.f}, {0.f, 0.f, 0.f, 0.f}};
        uint32_t offB = ksU + (key0 + rB) * HP + cB;
#pragma unroll
        for (int kk = 0; kk < 2; kk++) {
            uint32_t r0, r1, r2, r3;
            ldsm_x4(r0, r1, r2, r3, offB + kk * 32);
            mma_f16(sA[0], aq[kk], r0, r1);
            mma_f16(sA[1], aq[kk], r2, r3);
            ldsm_x4(r0, r1, r2, r3, offB + 16 * HP + kk * 32);
            mma_f16(sB[0], aq[kk], r0, r1);
            mma_f16(sB[1], aq[kk], r2, r3);
        }
        // ---- scale + additive mask bias, row max over 32 keys ----
        float vA[2][4], vB[2][4];
        float rm0 = -3.0e38f, rm1 = -3.0e38f;
#pragma unroll
        for (int n = 0; n < 2; n++) {
            float2 bkA = *reinterpret_cast<const float2*>(
                bias_s + key0 + n * 8 + 2 * qd);
            vA[n][0] = fmaf(sA[n][0], f0, bkA.x);
            vA[n][1] = fmaf(sA[n][1], f0, bkA.y);
            vA[n][2] = fmaf(sA[n][2], f1, bkA.x);
            vA[n][3] = fmaf(sA[n][3], f1, bkA.y);
            float2 bkB = *reinterpret_cast<const float2*>(
                bias_s + key0 + 16 + n * 8 + 2 * qd);
            vB[n][0] = fmaf(sB[n][0], f0, bkB.x);
            vB[n][1] = fmaf(sB[n][1], f0, bkB.y);
            vB[n][2] = fmaf(sB[n][2], f1, bkB.x);
            vB[n][3] = fmaf(sB[n][3], f1, bkB.y);
            rm0 = fmaxf(rm0, fmaxf(fmaxf(vA[n][0], vA[n][1]),
                                   fmaxf(vB[n][0], vB[n][1])));
            rm1 = fmaxf(rm1, fmaxf(fmaxf(vA[n][2], vA[n][3]),
                                   fmaxf(vB[n][2], vB[n][3])));
        }
        rm0 = fmaxf(rm0, __shfl_xor_sync(FULL, rm0, 1));
        rm0 = fmaxf(rm0, __shfl_xor_sync(FULL, rm0, 2));
        rm1 = fmaxf(rm1, __shfl_xor_sync(FULL, rm1, 1));
        rm1 = fmaxf(rm1, __shfl_xor_sync(FULL, rm1, 2));
        float nm0 = fmaxf(m0, rm0), nm1 = fmaxf(m1, rm1);
        float al0 = __expf(m0 - nm0), al1 = __expf(m1 - nm1);
        m0 = nm0; m1 = nm1;
#pragma unroll
        for (int n = 0; n < 4; n++) {
            co[n][0] *= al0; co[n][1] *= al0;
            co[n][2] *= al1; co[n][3] *= al1;
        }
        // ---- exp + pack (p <= 1, fp16-safe); per-thread partial ell ----
        float ts0 = 0.f, ts1 = 0.f;
        uint32_t ap[4], ap2[4];
#pragma unroll
        for (int n = 0; n < 2; n++) {
            float e0 = __expf(vA[n][0] - nm0);
            float e1 = __expf(vA[n][1] - nm0);
            float e2 = __expf(vA[n][2] - nm1);
            float e3 = __expf(vA[n][3] - nm1);
            ts0 += e0 + e1;
            ts1 += e2 + e3;
            ap[2 * n]     = packh2(e0, e1);
            ap[2 * n + 1] = packh2(e2, e3);
            e0 = __expf(vB[n][0] - nm0);
            e1 = __expf(vB[n][1] - nm0);
            e2 = __expf(vB[n][2] - nm1);
            e3 = __expf(vB[n][3] - nm1);
            ts0 += e0 + e1;
            ts1 += e2 + e3;
            ap2[2 * n]     = packh2(e0, e1);
            ap2[2 * n + 1] = packh2(e2, e3);
        }
        l0 = l0 * al0 + ts0;
        l1 = l1 * al1 + ts1;
        // ---- P.V for both tiles ----
        uint32_t offV = qvU + (key0 + rV) * HP + cV;
        {
            uint32_t r0, r1, r2, r3;
            ldsm_x4t(r0, r1, r2, r3, offV);
            mma_f16(co[0], ap, r0, r1);
            mma_f16(co[1], ap, r2, r3);
            ldsm_x4t(r0, r1, r2, r3, offV + 32);
            mma_f16(co[2], ap, r0, r1);
            mma_f16(co[3], ap, r2, r3);
            ldsm_x4t(r0, r1, r2, r3, offV + 16 * HP);
            mma_f16(co[0], ap2, r0, r1);
            mma_f16(co[1], ap2, r2, r3);
            ldsm_x4t(r0, r1, r2, r3, offV + 16 * HP + 32);
            mma_f16(co[2], ap2, r0, r1);
            mma_f16(co[3], ap2, r2, r3);
        }
    }

    // end reduction of ell over the quad
    l0 += __shfl_xor_sync(FULL, l0, 1);
    l0 += __shfl_xor_sync(FULL, l0, 2);
    l1 += __shfl_xor_sync(FULL, l1, 1);
    l1 += __shfl_xor_sync(FULL, l1, 2);
    float inv0 = 1.f / l0, inv1 = 1.f / l1;
#pragma unroll
    for (int n4 = 0; n4 < 4; n4++) {
        if (qr0 < Ssz) {
            __half2 v = __floats2half2_rn(co[n4][0] * inv0, co[n4][1] * inv0);
            *reinterpret_cast<__half2*>(
                ctx_h + base + (size_t)qr0 * Dsz + n4 * 8 + 2 * qd) = v;
        }
        if (qr1 < Ssz) {
            __half2 v = __floats2half2_rn(co[n4][2] * inv1, co[n4][3] * inv1);
            *reinterpret_cast<__half2*>(
                ctx_h + base + (size_t)qr1 * Dsz + n4 * 8 + 2 * qd) = v;
        }
    }
}

// ---------------------------------------------------------------------------
extern "C" void kernel_launch(void* const* d_in, const int* in_sizes, int n_in,
                              void* d_out, int out_size) {
    const float* hidden_img   = (const float*)d_in[0];
    const float* hidden_title = (const float*)d_in[1];
    const int*   mask         = (const int*)  d_in[2];
    const float* a_img   = (const float*)d_in[3];
    const float* b_img   = (const float*)d_in[4];
    const float* a_title = (const float*)d_in[5];
    const float* b_title = (const float*)d_in[6];
    const float* Wb      = (const float*)d_in[7];
    const float* bb      = (const float*)d_in[8];
    const float* Wo      = (const float*)d_in[9];
    const float* bo      = (const float*)d_in[10];
    const float* sattn   = (const float*)d_in[11];
    const float* a_out   = (const float*)d_in[12];
    const float* b_out   = (const float*)d_in[13];
    const float* W1      = (const float*)d_in[14];
    const float* b1      = (const float*)d_in[15];
    const float* sffn    = (const float*)d_in[16];
    float* out = (float*)d_out;

    float *img_n, *keff, *h1, *rsum, *rsumsq;
    __half *title_h, *ctx_h, *Wb_h, *Wo_h, *W1_h;
    cudaGetSymbolAddress((void**)&img_n,   g_img_n);
    cudaGetSymbolAddress((void**)&keff,    g_keff);
    cudaGetSymbolAddress((void**)&h1,      g_h1);
    cudaGetSymbolAddress((void**)&rsum,    g_rsum);
    cudaGetSymbolAddress((void**)&rsumsq,  g_rsumsq);
    cudaGetSymbolAddress((void**)&title_h, g_title_h);
    cudaGetSymbolAddress((void**)&ctx_h,   g_ctx_h);
    cudaGetSymbolAddress((void**)&Wb_h,    g_Wb_h);
    cudaGetSymbolAddress((void**)&Wo_h,    g_Wo_h);
    cudaGetSymbolAddress((void**)&W1_h,    g_W1_h);

    const int LNB = BS / 8;
    const int gemm_smem = 2 * STAGE_B;
    cudaFuncSetAttribute((const void*)gemm_f16<0, false>,
                         cudaFuncAttributeMaxDynamicSharedMemorySize, gemm_smem);
    cudaFuncSetAttribute((const void*)gemm_f16<0, true>,
                         cudaFuncAttributeMaxDynamicSharedMemorySize, gemm_smem);
    cudaFuncSetAttribute((const void*)gemm_f16<2, false>,
                         cudaFuncAttributeMaxDynamicSharedMemorySize, gemm_smem);

    // 0) weights -> half + zero row stats
    w2h_kernel<<<484, 256>>>(Wb, Wo, W1, Wb_h, Wo_h, W1_h, rsum, rsumsq);

    // 1) both input LayerNorms
    ln_fast<<<2 * LNB, 256>>>(hidden_img, a_img, b_img, img_n,
                              hidden_title, a_title, b_title, title_h, LNB);

    // 2) keff = title_n @ Wb^T + bb + img_n
    dim3 gg(Dsz / GBN, BS / GBM);
    gemm_f16<0, false><<<gg, 256, gemm_smem>>>(
        title_h, Wb_h, bb, img_n, nullptr, keff, nullptr, nullptr, nullptr, nullptr);

    // 3) fp16 flash attention (online max, 32-key tiles) -> ctx half
    const int attn_smem = 2 * QV_B + SPAD * 4;   // 36736 B
    cudaFuncSetAttribute(attn_flash,
                         cudaFuncAttributeMaxDynamicSharedMemorySize, attn_smem);
    attn_flash<<<Bsz * Hsz, ATHR, attn_smem>>>(img_n, keff, mask, sattn, ctx_h);

    // 4) h1 = ctx @ Wo^T + bo + hidden_img  (+ row stats)
    gemm_f16<0, true><<<gg, 256, gemm_smem>>>(
        ctx_h, Wo_h, bo, hidden_img, nullptr, h1, nullptr, nullptr, rsum, rsumsq);

    // 5) out = h1 + gelu_tanh(scale_ffn * (LN(h1) @ W1^T + b1))
    gemm_f16<2, false><<<gg, 256, gemm_smem>>>(
        h1, W1_h, b1, h1, sffn, out, a_out, b_out, rsum, rsumsq);
}

// round 12
// speedup vs baseline: 4.6206x; 1.0986x over previous
#include <cuda_runtime.h>
#include <cuda_fp16.h>
#include <math.h>
#include <stdint.h>

#define Bsz 256
#define Ssz 200
#define Dsz 256
#define Hsz 8
#define DHsz 32
#define BS (Bsz * Ssz)   // 51200 rows

__device__ float g_h1[BS * Dsz];
__device__ float g_rsum[BS];
__device__ float g_rsumsq[BS];
__device__ __half g_img_h[BS * Dsz];
__device__ __half g_title_h[BS * Dsz];
__device__ __half g_keff_h[BS * Dsz];
__device__ __half g_ctx_h[BS * Dsz];
__device__ __half g_Wb_h[Dsz * Dsz];
__device__ __half g_Wo_h[Dsz * Dsz];
__device__ __half g_W1_h[Dsz * Dsz];

__device__ __forceinline__ void mma_f16(float* c, const uint32_t* a,
                                        uint32_t b0, uint32_t b1) {
    asm volatile(
        "mma.sync.aligned.m16n8k16.row.col.f32.f16.f16.f32 "
        "{%0,%1,%2,%3}, {%4,%5,%6,%7}, {%8,%9}, {%0,%1,%2,%3};"
        : "+f"(c[0]), "+f"(c[1]), "+f"(c[2]), "+f"(c[3])
        : "r"(a[0]), "r"(a[1]), "r"(a[2]), "r"(a[3]), "r"(b0), "r"(b1));
}

__device__ __forceinline__ void ldsm_x4(uint32_t& r0, uint32_t& r1,
                                        uint32_t& r2, uint32_t& r3,
                                        uint32_t addr) {
    asm volatile(
        "ldmatrix.sync.aligned.m8n8.x4.shared.b16 {%0,%1,%2,%3}, [%4];"
        : "=r"(r0), "=r"(r1), "=r"(r2), "=r"(r3) : "r"(addr));
}

__device__ __forceinline__ void ldsm_x4t(uint32_t& r0, uint32_t& r1,
                                         uint32_t& r2, uint32_t& r3,
                                         uint32_t addr) {
    asm volatile(
        "ldmatrix.sync.aligned.m8n8.x4.trans.shared.b16 {%0,%1,%2,%3}, [%4];"
        : "=r"(r0), "=r"(r1), "=r"(r2), "=r"(r3) : "r"(addr));
}

__device__ __forceinline__ void cp_async16(uint32_t smem, const void* g) {
    asm volatile("cp.async.cg.shared.global [%0], [%1], 16;"
                 :: "r"(smem), "l"(g));
}

__device__ __forceinline__ uint32_t packh2(float a, float b) {
    __half2 h = __floats2half2_rn(a, b);
    return *reinterpret_cast<uint32_t*>(&h);
}

__device__ __forceinline__ float ex2f(float x) {
    float r;
    asm("ex2.approx.f32 %0, %1;" : "=f"(r) : "f"(x));
    return r;
}

// ---------------------------------------------------------------------------
// Weights -> half + zero rsum/rsumsq (one launch).
// ---------------------------------------------------------------------------
__global__ void __launch_bounds__(256) w2h_kernel(
    const float* __restrict__ w0, const float* __restrict__ w1,
    const float* __restrict__ w2, __half* __restrict__ h0,
    __half* __restrict__ h1, __half* __restrict__ h2,
    float* __restrict__ rsum, float* __restrict__ rsumsq) {
    int i = blockIdx.x * 256 + threadIdx.x;
    if (i < 98304) {
        const float2* s;
        __half2* d;
        int j;
        if (i < 32768)      { s = (const float2*)w0; d = (__half2*)h0; j = i; }
        else if (i < 65536) { s = (const float2*)w1; d = (__half2*)h1; j = i - 32768; }
        else                { s = (const float2*)w2; d = (__half2*)h2; j = i - 65536; }
        float2 v = s[j];
        d[j] = __floats2half2_rn(v.x, v.y);
    } else {
        int j = i - 98304;
        float4 z = make_float4(0.f, 0.f, 0.f, 0.f);
        if (j < 12800) reinterpret_cast<float4*>(rsum)[j] = z;
        else           reinterpret_cast<float4*>(rsumsq)[j - 12800] = z;
    }
}

// ---------------------------------------------------------------------------
// Warp-per-row LayerNorm; both streams emit HALF.
// ---------------------------------------------------------------------------
__global__ void __launch_bounds__(256) ln_fast(
    const float* __restrict__ x0, const float* __restrict__ ga0,
    const float* __restrict__ gb0, __half* __restrict__ y0,
    const float* __restrict__ x1, const float* __restrict__ ga1,
    const float* __restrict__ gb1, __half* __restrict__ y1, int split) {
    int blk = blockIdx.x;
    const float *x, *ga, *gb;
    __half* y;
    int rowbase;
    if (blk < split) { x = x0; ga = ga0; gb = gb0; y = y0; rowbase = blk * 8; }
    else { x = x1; ga = ga1; gb = gb1; y = y1; rowbase = (blk - split) * 8; }
    int w = threadIdx.x >> 5, lane = threadIdx.x & 31;
    size_t row = rowbase + w;
    const float4* x4 = reinterpret_cast<const float4*>(x + row * Dsz);
    float4 v0 = x4[lane];
    float4 v1 = x4[lane + 32];

    float s = v0.x + v0.y + v0.z + v0.w + v1.x + v1.y + v1.z + v1.w;
#pragma unroll
    for (int o = 16; o; o >>= 1) s += __shfl_xor_sync(0xffffffffu, s, o);
    float mean = s * (1.0f / Dsz);

    float d0x = v0.x - mean, d0y = v0.y - mean, d0z = v0.z - mean, d0w = v0.w - mean;
    float d1x = v1.x - mean, d1y = v1.y - mean, d1z = v1.z - mean, d1w = v1.w - mean;
    float ss = d0x * d0x + d0y * d0y + d0z * d0z + d0w * d0w +
               d1x * d1x + d1y * d1y + d1z * d1z + d1w * d1w;
#pragma unroll
    for (int o = 16; o; o >>= 1) ss += __shfl_xor_sync(0xffffffffu, ss, o);
    float var = ss * (1.0f / (Dsz - 1));
    float inv = 1.0f / (sqrtf(var) + 1e-6f);

    const float4* ga4 = reinterpret_cast<const float4*>(ga);
    const float4* gb4 = reinterpret_cast<const float4*>(gb);
    float4 g0 = ga4[lane], g1 = ga4[lane + 32];
    float4 b0 = gb4[lane], b1 = gb4[lane + 32];
    float4 o0 = make_float4(g0.x * d0x * inv + b0.x, g0.y * d0y * inv + b0.y,
                            g0.z * d0z * inv + b0.z, g0.w * d0w * inv + b0.w);
    float4 o1 = make_float4(g1.x * d1x * inv + b1.x, g1.y * d1y * inv + b1.y,
                            g1.z * d1z * inv + b1.z, g1.w * d1w * inv + b1.w);
    uint2* y2 = reinterpret_cast<uint2*>(y + row * Dsz);
    y2[lane] = make_uint2(packh2(o0.x, o0.y), packh2(o0.z, o0.w));
    y2[lane + 32] = make_uint2(packh2(o1.x, o1.y), packh2(o1.z, o1.w));
}

// ---------------------------------------------------------------------------
// fp16 GEMM (fp32 accum).
// EPI==0: out = acc + bias + add; ADDH: add is half; OUTH: out is half.
//         STATS: row sum/sumsq atomics.
// EPI==2: A is float, LN-staged (rsum/rsumsq,lga,lgb); gelu epilogue, float.
// ---------------------------------------------------------------------------
#define GBM 128
#define GBN 128
#define HPITCH 80
#define TILE_B (128 * HPITCH)
#define STAGE_B (2 * TILE_B)

template <int EPI, bool STATS, bool ADDH, bool OUTH>
__global__ void __launch_bounds__(256) gemm_f16(
    const void* __restrict__ Aptr, const __half* __restrict__ W,
    const float* __restrict__ bias, const void* __restrict__ addp,
    const float* __restrict__ sffn, void* __restrict__ outp,
    const float* __restrict__ lga, const float* __restrict__ lgb,
    float* __restrict__ rsum, float* __restrict__ rsumsq) {
    extern __shared__ char gsm[];
    uint32_t smemU = (uint32_t)__cvta_generic_to_shared(gsm);

    int m0 = blockIdx.y * GBM;
    int n0 = blockIdx.x * GBN;
    int tid = threadIdx.x;
    int wid = tid >> 5, lane = tid & 31;
    int wm = wid >> 1, wn = wid & 1;
    int grp = lane >> 2, qd = lane & 3;

    int rA = (lane & 7) + ((lane >> 3) & 1) * 8;
    int offA = (wm * 32 + rA) * HPITCH + ((lane >> 4) & 1) * 16;
    int rB = (lane & 7) + ((lane >> 4) & 1) * 8;
    int offB = (wn * 64 + rB) * HPITCH + ((lane >> 3) & 1) * 16;

    float mean_t[4], inv_t[4];
    int lr = tid >> 3;
    int c4f = (tid & 7) * 4;
    if (EPI == 2) {
#pragma unroll
        for (int t = 0; t < 4; t++) {
            int r = m0 + lr + 32 * t;
            float s = rsum[r], sq = rsumsq[r];
            float mn = s * (1.0f / Dsz);
            float var = (sq - (float)Dsz * mn * mn) * (1.0f / (Dsz - 1));
            mean_t[t] = mn;
            inv_t[t] = 1.0f / (sqrtf(var) + 1e-6f);
        }
    }

    float acc[2][8][4];
#pragma unroll
    for (int i = 0; i < 2; i++)
#pragma unroll
        for (int n = 0; n < 8; n++)
#pragma unroll
            for (int e = 0; e < 4; e++) acc[i][n][e] = 0.f;

    int crow = tid >> 2, cu = tid & 3;
    const __half* Ah = (const __half*)Aptr;
    const float* Af = (const float*)Aptr;

    auto stageW = [&](int buf, int k0) {
        uint32_t sb = smemU + buf * STAGE_B + TILE_B;
        cp_async16(sb + crow * HPITCH + cu * 16,
                   W + (size_t)(n0 + crow) * Dsz + k0 + cu * 8);
        cp_async16(sb + (crow + 64) * HPITCH + cu * 16,
                   W + (size_t)(n0 + crow + 64) * Dsz + k0 + cu * 8);
    };
    auto stageA = [&](int buf, int k0) {
        uint32_t sa = smemU + buf * STAGE_B;
        cp_async16(sa + crow * HPITCH + cu * 16,
                   Ah + (size_t)(m0 + crow) * Dsz + k0 + cu * 8);
        cp_async16(sa + (crow + 64) * HPITCH + cu * 16,
                   Ah + (size_t)(m0 + crow + 64) * Dsz + k0 + cu * 8);
    };

    const int NSTEP = Dsz / 32;
    float4 pa[4];

    if (EPI == 2) {
#pragma unroll
        for (int t = 0; t < 4; t++)
            pa[t] = *reinterpret_cast<const float4*>(
                Af + (size_t)(m0 + lr + 32 * t) * Dsz + c4f);
        stageW(0, 0);
        asm volatile("cp.async.commit_group;");
    } else {
        stageA(0, 0);
        stageW(0, 0);
        asm volatile("cp.async.commit_group;");
    }

    for (int s = 0; s < NSTEP; s++) {
        if (EPI == 2) {
            float4 g4 = *reinterpret_cast<const float4*>(lga + s * 32 + c4f);
            float4 b4 = *reinterpret_cast<const float4*>(lgb + s * 32 + c4f);
            uint32_t sa = smemU + (s & 1) * STAGE_B;
#pragma unroll
            for (int t = 0; t < 4; t++) {
                int r = lr + 32 * t;
                float vx = (pa[t].x - mean_t[t]) * inv_t[t] * g4.x + b4.x;
                float vy = (pa[t].y - mean_t[t]) * inv_t[t] * g4.y + b4.y;
                float vz = (pa[t].z - mean_t[t]) * inv_t[t] * g4.z + b4.z;
                float vw = (pa[t].w - mean_t[t]) * inv_t[t] * g4.w + b4.w;
                asm volatile("st.shared.v2.b32 [%0], {%1,%2};"
                             :: "r"(sa + r * HPITCH + c4f * 2),
                                "r"(packh2(vx, vy)), "r"(packh2(vz, vw)));
            }
            if (s + 1 < NSTEP) {
#pragma unroll
                for (int t = 0; t < 4; t++)
                    pa[t] = *reinterpret_cast<const float4*>(
                        Af + (size_t)(m0 + lr + 32 * t) * Dsz + (s + 1) * 32 + c4f);
                stageW((s + 1) & 1, (s + 1) * 32);
                asm volatile("cp.async.commit_group;");
                asm volatile("cp.async.wait_group 1;");
            } else {
                asm volatile("cp.async.wait_group 0;");
            }
        } else {
            if (s + 1 < NSTEP) {
                stageA((s + 1) & 1, (s + 1) * 32);
                stageW((s + 1) & 1, (s + 1) * 32);
                asm volatile("cp.async.commit_group;");
                asm volatile("cp.async.wait_group 1;");
            } else {
                asm volatile("cp.async.wait_group 0;");
            }
        }
        __syncthreads();

        uint32_t aB = smemU + (s & 1) * STAGE_B + offA;
        uint32_t bB = smemU + (s & 1) * STAGE_B + TILE_B + offB;
#pragma unroll
        for (int kb = 0; kb < 2; kb++) {
            uint32_t af[2][4];
#pragma unroll
            for (int i = 0; i < 2; i++)
                ldsm_x4(af[i][0], af[i][1], af[i][2], af[i][3],
                        aB + i * 16 * HPITCH + kb * 32);
            uint32_t bf[8][2];
#pragma unroll
            for (int p = 0; p < 4; p++) {
                uint32_t r0, r1, r2, r3;
                ldsm_x4(r0, r1, r2, r3, bB + p * 16 * HPITCH + kb * 32);
                bf[2 * p][0] = r0; bf[2 * p][1] = r1;
                bf[2 * p + 1][0] = r2; bf[2 * p + 1][1] = r3;
            }
#pragma unroll
            for (int i = 0; i < 2; i++)
#pragma unroll
                for (int n = 0; n < 8; n++)
                    mma_f16(acc[i][n], af[i], bf[n][0], bf[n][1]);
        }
        __syncthreads();
    }

    const float* addf = (const float*)addp;
    const __half* addh = (const __half*)addp;
    float* outf = (float*)outp;
    __half* outh = (__half*)outp;

#pragma unroll
    for (int i = 0; i < 2; i++) {
        int mr0 = m0 + wm * 32 + i * 16 + grp;
        int mr1 = mr0 + 8;
        float sf0 = 0.f, sf1 = 0.f;
        if (EPI == 2) {
            sf0 = sffn[mr0 % Ssz];
            sf1 = sffn[mr1 % Ssz];
        }
        float s0 = 0.f, q0s = 0.f, s1 = 0.f, q1s = 0.f;
#pragma unroll
        for (int n = 0; n < 8; n++) {
            int col = n0 + wn * 64 + n * 8 + 2 * qd;
            float2 bv = *reinterpret_cast<const float2*>(bias + col);
            float2 a0, a1;
            if (ADDH) {
                __half2 h0 = *reinterpret_cast<const __half2*>(
                    addh + (size_t)mr0 * Dsz + col);
                __half2 h1v = *reinterpret_cast<const __half2*>(
                    addh + (size_t)mr1 * Dsz + col);
                a0 = __half22float2(h0);
                a1 = __half22float2(h1v);
            } else {
                a0 = *reinterpret_cast<const float2*>(
                    addf + (size_t)mr0 * Dsz + col);
                a1 = *reinterpret_cast<const float2*>(
                    addf + (size_t)mr1 * Dsz + col);
            }
            float r00 = acc[i][n][0] + bv.x, r01 = acc[i][n][1] + bv.y;
            float r10 = acc[i][n][2] + bv.x, r11 = acc[i][n][3] + bv.y;
            if (EPI == 0) {
                r00 += a0.x; r01 += a0.y; r10 += a1.x; r11 += a1.y;
                if (STATS) {
                    s0 += r00 + r01; q0s += r00 * r00 + r01 * r01;
                    s1 += r10 + r11; q1s += r10 * r10 + r11 * r11;
                }
            } else {
                float z, th;
                z = sf0 * r00;
                th = tanhf(0.79788456080286536f * (z + 0.044715f * z * z * z));
                r00 = a0.x + 0.5f * z * (1.0f + th);
                z = sf0 * r01;
                th = tanhf(0.79788456080286536f * (z + 0.044715f * z * z * z));
                r01 = a0.y + 0.5f * z * (1.0f + th);
                z = sf1 * r10;
                th = tanhf(0.79788456080286536f * (z + 0.044715f * z * z * z));
                r10 = a1.x + 0.5f * z * (1.0f + th);
                z = sf1 * r11;
                th = tanhf(0.79788456080286536f * (z + 0.044715f * z * z * z));
                r11 = a1.y + 0.5f * z * (1.0f + th);
            }
            if (OUTH) {
                *reinterpret_cast<uint32_t*>(outh + (size_t)mr0 * Dsz + col) =
                    packh2(r00, r01);
                *reinterpret_cast<uint32_t*>(outh + (size_t)mr1 * Dsz + col) =
                    packh2(r10, r11);
            } else {
                *reinterpret_cast<float2*>(outf + (size_t)mr0 * Dsz + col) =
                    make_float2(r00, r01);
                *reinterpret_cast<float2*>(outf + (size_t)mr1 * Dsz + col) =
                    make_float2(r10, r11);
            }
        }
        if (STATS) {
            const unsigned FULL = 0xffffffffu;
            s0 += __shfl_xor_sync(FULL, s0, 1);
            s0 += __shfl_xor_sync(FULL, s0, 2);
            q0s += __shfl_xor_sync(FULL, q0s, 1);
            q0s += __shfl_xor_sync(FULL, q0s, 2);
            s1 += __shfl_xor_sync(FULL, s1, 1);
            s1 += __shfl_xor_sync(FULL, s1, 2);
            q1s += __shfl_xor_sync(FULL, q1s, 1);
            q1s += __shfl_xor_sync(FULL, q1s, 2);
            if (qd == 0) {
                atomicAdd(&rsum[mr0], s0);
                atomicAdd(&rsumsq[mr0], q0s);
                atomicAdd(&rsum[mr1], s1);
                atomicAdd(&rsumsq[mr1], q1s);
            }
        }
    }
}

// ---------------------------------------------------------------------------
// fp16 flash-attention. Q/V/K already half in gmem: loader is pure
// LDG.128 -> STS.128. Softmax in exp2 domain (log2e folded into scale and
// mask bias): bare MUFU.EX2, no FMULs. Online max over 32-key double tiles,
// deferred ell. S padded to 224 (V=0, bias=-inf-ish).
// ---------------------------------------------------------------------------
#define SPAD 224
#define HP 80
#define QV_B (SPAD * HP)
#define ATHR 416
#define LOG2E 1.4426950408889634f

__global__ void __launch_bounds__(ATHR) attn_flash(
    const __half* __restrict__ img_h, const __half* __restrict__ keff_h,
    const int* __restrict__ mask, const float* __restrict__ sattn,
    __half* __restrict__ ctx_h) {
    extern __shared__ char smw[];
    uint32_t smemU = (uint32_t)__cvta_generic_to_shared(smw);
    uint32_t qvU = smemU;
    uint32_t ksU = smemU + QV_B;
    float* bias_s = reinterpret_cast<float*>(smw + 2 * QV_B);  // 0 or -1e9*log2e

    int b = blockIdx.x >> 3;
    int h = blockIdx.x & 7;
    int tid = threadIdx.x;
    size_t base = ((size_t)b * Ssz) * Dsz + h * DHsz;

    for (int idx = tid; idx < SPAD * 4; idx += ATHR) {
        int r = idx >> 2, c8 = (idx & 3) * 8;
        uint4 q = make_uint4(0u, 0u, 0u, 0u);
        uint4 k = make_uint4(0u, 0u, 0u, 0u);
        if (r < Ssz) {
            q = *reinterpret_cast<const uint4*>(img_h + base + (size_t)r * Dsz + c8);
            k = *reinterpret_cast<const uint4*>(keff_h + base + (size_t)r * Dsz + c8);
        }
        asm volatile("st.shared.v4.b32 [%0], {%1,%2,%3,%4};"
                     :: "r"(qvU + r * HP + c8 * 2),
                        "r"(q.x), "r"(q.y), "r"(q.z), "r"(q.w));
        asm volatile("st.shared.v4.b32 [%0], {%1,%2,%3,%4};"
                     :: "r"(ksU + r * HP + c8 * 2),
                        "r"(k.x), "r"(k.y), "r"(k.z), "r"(k.w));
    }
    for (int k = tid; k < SPAD; k += ATHR)
        bias_s[k] = (k >= Ssz || mask[b * Ssz + k] == 0)
                        ? -1.4426950e9f : 0.f;
    __syncthreads();

    int w = tid >> 5, lane = tid & 31;
    int grp = lane >> 2;
    int qd = lane & 3;
    const float isq2 = 0.17677669529663687f * LOG2E;  // fold log2e into scale
    const unsigned FULL = 0xffffffffu;

    int q0 = w * 16;
    int qr0 = q0 + grp, qr1 = q0 + grp + 8;
    float f0 = (qr0 < Ssz) ? isq2 * sattn[h * Ssz + qr0] : 0.f;
    float f1 = (qr1 < Ssz) ? isq2 * sattn[h * Ssz + qr1] : 0.f;

    uint32_t aq[2][4];
    {
        int rA = (lane & 7) + ((lane >> 3) & 1) * 8;
        uint32_t offA = qvU + (q0 + rA) * HP + ((lane >> 4) & 1) * 16;
        ldsm_x4(aq[0][0], aq[0][1], aq[0][2], aq[0][3], offA);
        ldsm_x4(aq[1][0], aq[1][1], aq[1][2], aq[1][3], offA + 32);
    }

    int rB = (lane & 7) + ((lane >> 4) & 1) * 8;
    int rV = (lane & 7) + ((lane >> 3) & 1) * 8;
    int cB = ((lane >> 3) & 1) * 16;
    int cV = ((lane >> 4) & 1) * 16;

    float m0 = -3.0e38f, m1 = -3.0e38f, l0 = 0.f, l1 = 0.f;
    float co[4][4];
#pragma unroll
    for (int n = 0; n < 4; n++)
#pragma unroll
        for (int e = 0; e < 4; e++) co[n][e] = 0.f;

    for (int it = 0; it < 7; it++) {
        int key0 = it * 32;
        float sA[2][4] = {{0.f, 0.f, 0.f, 0.f}, {0.f, 0.f, 0.f, 0.f}};
        float sB[2][4] = {{0.f, 0.f, 0.f, 0.f}, {0.f, 0.f, 0.f, 0.f}};
        uint32_t offB = ksU + (key0 + rB) * HP + cB;
#pragma unroll
        for (int kk = 0; kk < 2; kk++) {
            uint32_t r0, r1, r2, r3;
            ldsm_x4(r0, r1, r2, r3, offB + kk * 32);
            mma_f16(sA[0], aq[kk], r0, r1);
            mma_f16(sA[1], aq[kk], r2, r3);
            ldsm_x4(r0, r1, r2, r3, offB + 16 * HP + kk * 32);
            mma_f16(sB[0], aq[kk], r0, r1);
            mma_f16(sB[1], aq[kk], r2, r3);
        }
        float vA[2][4], vB[2][4];
        float rm0 = -3.0e38f, rm1 = -3.0e38f;
#pragma unroll
        for (int n = 0; n < 2; n++) {
            float2 bkA = *reinterpret_cast<const float2*>(
                bias_s + key0 + n * 8 + 2 * qd);
            vA[n][0] = fmaf(sA[n][0], f0, bkA.x);
            vA[n][1] = fmaf(sA[n][1], f0, bkA.y);
            vA[n][2] = fmaf(sA[n][2], f1, bkA.x);
            vA[n][3] = fmaf(sA[n][3], f1, bkA.y);
            float2 bkB = *reinterpret_cast<const float2*>(
                bias_s + key0 + 16 + n * 8 + 2 * qd);
            vB[n][0] = fmaf(sB[n][0], f0, bkB.x);
            vB[n][1] = fmaf(sB[n][1], f0, bkB.y);
            vB[n][2] = fmaf(sB[n][2], f1, bkB.x);
            vB[n][3] = fmaf(sB[n][3], f1, bkB.y);
            rm0 = fmaxf(rm0, fmaxf(fmaxf(vA[n][0], vA[n][1]),
                                   fmaxf(vB[n][0], vB[n][1])));
            rm1 = fmaxf(rm1, fmaxf(fmaxf(vA[n][2], vA[n][3]),
                                   fmaxf(vB[n][2], vB[n][3])));
        }
        rm0 = fmaxf(rm0, __shfl_xor_sync(FULL, rm0, 1));
        rm0 = fmaxf(rm0, __shfl_xor_sync(FULL, rm0, 2));
        rm1 = fmaxf(rm1, __shfl_xor_sync(FULL, rm1, 1));
        rm1 = fmaxf(rm1, __shfl_xor_sync(FULL, rm1, 2));
        float nm0 = fmaxf(m0, rm0), nm1 = fmaxf(m1, rm1);
        float al0 = ex2f(m0 - nm0), al1 = ex2f(m1 - nm1);
        m0 = nm0; m1 = nm1;
#pragma unroll
        for (int n = 0; n < 4; n++) {
            co[n][0] *= al0; co[n][1] *= al0;
            co[n][2] *= al1; co[n][3] *= al1;
        }
        float ts0 = 0.f, ts1 = 0.f;
        uint32_t ap[4], ap2[4];
#pragma unroll
        for (int n = 0; n < 2; n++) {
            float e0 = ex2f(vA[n][0] - nm0);
            float e1 = ex2f(vA[n][1] - nm0);
            float e2 = ex2f(vA[n][2] - nm1);
            float e3 = ex2f(vA[n][3] - nm1);
            ts0 += e0 + e1;
            ts1 += e2 + e3;
            ap[2 * n]     = packh2(e0, e1);
            ap[2 * n + 1] = packh2(e2, e3);
            e0 = ex2f(vB[n][0] - nm0);
            e1 = ex2f(vB[n][1] - nm0);
            e2 = ex2f(vB[n][2] - nm1);
            e3 = ex2f(vB[n][3] - nm1);
            ts0 += e0 + e1;
            ts1 += e2 + e3;
            ap2[2 * n]     = packh2(e0, e1);
            ap2[2 * n + 1] = packh2(e2, e3);
        }
        l0 = l0 * al0 + ts0;
        l1 = l1 * al1 + ts1;
        uint32_t offV = qvU + (key0 + rV) * HP + cV;
        {
            uint32_t r0, r1, r2, r3;
            ldsm_x4t(r0, r1, r2, r3, offV);
            mma_f16(co[0], ap, r0, r1);
            mma_f16(co[1], ap, r2, r3);
            ldsm_x4t(r0, r1, r2, r3, offV + 32);
            mma_f16(co[2], ap, r0, r1);
            mma_f16(co[3], ap, r2, r3);
            ldsm_x4t(r0, r1, r2, r3, offV + 16 * HP);
            mma_f16(co[0], ap2, r0, r1);
            mma_f16(co[1], ap2, r2, r3);
            ldsm_x4t(r0, r1, r2, r3, offV + 16 * HP + 32);
            mma_f16(co[2], ap2, r0, r1);
            mma_f16(co[3], ap2, r2, r3);
        }
    }

    l0 += __shfl_xor_sync(FULL, l0, 1);
    l0 += __shfl_xor_sync(FULL, l0, 2);
    l1 += __shfl_xor_sync(FULL, l1, 1);
    l1 += __shfl_xor_sync(FULL, l1, 2);
    float inv0 = 1.f / l0, inv1 = 1.f / l1;
#pragma unroll
    for (int n4 = 0; n4 < 4; n4++) {
        if (qr0 < Ssz) {
            __half2 v = __floats2half2_rn(co[n4][0] * inv0, co[n4][1] * inv0);
            *reinterpret_cast<__half2*>(
                ctx_h + base + (size_t)qr0 * Dsz + n4 * 8 + 2 * qd) = v;
        }
        if (qr1 < Ssz) {
            __half2 v = __floats2half2_rn(co[n4][2] * inv1, co[n4][3] * inv1);
            *reinterpret_cast<__half2*>(
                ctx_h + base + (size_t)qr1 * Dsz + n4 * 8 + 2 * qd) = v;
        }
    }
}

// ---------------------------------------------------------------------------
extern "C" void kernel_launch(void* const* d_in, const int* in_sizes, int n_in,
                              void* d_out, int out_size) {
    const float* hidden_img   = (const float*)d_in[0];
    const float* hidden_title = (const float*)d_in[1];
    const int*   mask         = (const int*)  d_in[2];
    const float* a_img   = (const float*)d_in[3];
    const float* b_img   = (const float*)d_in[4];
    const float* a_title = (const float*)d_in[5];
    const float* b_title = (const float*)d_in[6];
    const float* Wb      = (const float*)d_in[7];
    const float* bb      = (const float*)d_in[8];
    const float* Wo      = (const float*)d_in[9];
    const float* bo      = (const float*)d_in[10];
    const float* sattn   = (const float*)d_in[11];
    const float* a_out   = (const float*)d_in[12];
    const float* b_out   = (const float*)d_in[13];
    const float* W1      = (const float*)d_in[14];
    const float* b1      = (const float*)d_in[15];
    const float* sffn    = (const float*)d_in[16];
    float* out = (float*)d_out;

    float *h1, *rsum, *rsumsq;
    __half *img_h, *title_h, *keff_h, *ctx_h, *Wb_h, *Wo_h, *W1_h;
    cudaGetSymbolAddress((void**)&h1,      g_h1);
    cudaGetSymbolAddress((void**)&rsum,    g_rsum);
    cudaGetSymbolAddress((void**)&rsumsq,  g_rsumsq);
    cudaGetSymbolAddress((void**)&img_h,   g_img_h);
    cudaGetSymbolAddress((void**)&title_h, g_title_h);
    cudaGetSymbolAddress((void**)&keff_h,  g_keff_h);
    cudaGetSymbolAddress((void**)&ctx_h,   g_ctx_h);
    cudaGetSymbolAddress((void**)&Wb_h,    g_Wb_h);
    cudaGetSymbolAddress((void**)&Wo_h,    g_Wo_h);
    cudaGetSymbolAddress((void**)&W1_h,    g_W1_h);

    const int LNB = BS / 8;
    const int gemm_smem = 2 * STAGE_B;
    cudaFuncSetAttribute((const void*)gemm_f16<0, false, true, true>,
                         cudaFuncAttributeMaxDynamicSharedMemorySize, gemm_smem);
    cudaFuncSetAttribute((const void*)gemm_f16<0, true, false, false>,
                         cudaFuncAttributeMaxDynamicSharedMemorySize, gemm_smem);
    cudaFuncSetAttribute((const void*)gemm_f16<2, false, false, false>,
                         cudaFuncAttributeMaxDynamicSharedMemorySize, gemm_smem);

    // 0) weights -> half + zero row stats
    w2h_kernel<<<484, 256>>>(Wb, Wo, W1, Wb_h, Wo_h, W1_h, rsum, rsumsq);

    // 1) both input LayerNorms -> half
    ln_fast<<<2 * LNB, 256>>>(hidden_img, a_img, b_img, img_h,
                              hidden_title, a_title, b_title, title_h, LNB);

    // 2) keff(half) = title_n @ Wb^T + bb + img_n(half)
    dim3 gg(Dsz / GBN, BS / GBM);
    gemm_f16<0, false, true, true><<<gg, 256, gemm_smem>>>(
        title_h, Wb_h, bb, img_h, nullptr, keff_h, nullptr, nullptr,
        nullptr, nullptr);

    // 3) fp16 flash attention (exp2 domain) -> ctx half
    const int attn_smem = 2 * QV_B + SPAD * 4;
    cudaFuncSetAttribute(attn_flash,
                         cudaFuncAttributeMaxDynamicSharedMemorySize, attn_smem);
    attn_flash<<<Bsz * Hsz, ATHR, attn_smem>>>(img_h, keff_h, mask, sattn, ctx_h);

    // 4) h1 = ctx @ Wo^T + bo + hidden_img  (+ row stats)
    gemm_f16<0, true, false, false><<<gg, 256, gemm_smem>>>(
        ctx_h, Wo_h, bo, hidden_img, nullptr, h1, nullptr, nullptr,
        rsum, rsumsq);

    // 5) out = h1 + gelu_tanh(scale_ffn * (LN(h1) @ W1^T + b1))
    gemm_f16<2, false, false, false><<<gg, 256, gemm_smem>>>(
        h1, W1_h, b1, h1, sffn, out, a_out, b_out, rsum, rsumsq);
}

// round 14
// speedup vs baseline: 4.7054x; 1.0183x over previous
#include <cuda_runtime.h>
#include <cuda_fp16.h>
#include <math.h>
#include <stdint.h>

#define Bsz 256
#define Ssz 200
#define Dsz 256
#define Hsz 8
#define DHsz 32
#define BS (Bsz * Ssz)   // 51200 rows

__device__ float g_rsum[BS];
__device__ float g_rsumsq[BS];
__device__ __half g_h1_h[BS * Dsz];
__device__ __half g_img_h[BS * Dsz];
__device__ __half g_title_h[BS * Dsz];
__device__ __half g_keff_h[BS * Dsz];
__device__ __half g_ctx_h[BS * Dsz];
__device__ __half g_Wb_h[Dsz * Dsz];
__device__ __half g_Wo_h[Dsz * Dsz];
__device__ __half g_W1_h[Dsz * Dsz];

__device__ __forceinline__ void mma_f16(float* c, const uint32_t* a,
                                        uint32_t b0, uint32_t b1) {
    asm volatile(
        "mma.sync.aligned.m16n8k16.row.col.f32.f16.f16.f32 "
        "{%0,%1,%2,%3}, {%4,%5,%6,%7}, {%8,%9}, {%0,%1,%2,%3};"
        : "+f"(c[0]), "+f"(c[1]), "+f"(c[2]), "+f"(c[3])
        : "r"(a[0]), "r"(a[1]), "r"(a[2]), "r"(a[3]), "r"(b0), "r"(b1));
}

__device__ __forceinline__ void ldsm_x4(uint32_t& r0, uint32_t& r1,
                                        uint32_t& r2, uint32_t& r3,
                                        uint32_t addr) {
    asm volatile(
        "ldmatrix.sync.aligned.m8n8.x4.shared.b16 {%0,%1,%2,%3}, [%4];"
        : "=r"(r0), "=r"(r1), "=r"(r2), "=r"(r3) : "r"(addr));
}

__device__ __forceinline__ void ldsm_x4t(uint32_t& r0, uint32_t& r1,
                                         uint32_t& r2, uint32_t& r3,
                                         uint32_t addr) {
    asm volatile(
        "ldmatrix.sync.aligned.m8n8.x4.trans.shared.b16 {%0,%1,%2,%3}, [%4];"
        : "=r"(r0), "=r"(r1), "=r"(r2), "=r"(r3) : "r"(addr));
}

__device__ __forceinline__ void cp_async16(uint32_t smem, const void* g) {
    asm volatile("cp.async.cg.shared.global [%0], [%1], 16;"
                 :: "r"(smem), "l"(g));
}

__device__ __forceinline__ uint32_t packh2(float a, float b) {
    __half2 h = __floats2half2_rn(a, b);
    return *reinterpret_cast<uint32_t*>(&h);
}

__device__ __forceinline__ float ex2f(float x) {
    float r;
    asm("ex2.approx.f32 %0, %1;" : "=f"(r) : "f"(x));
    return r;
}

// ---------------------------------------------------------------------------
// Weights -> half + zero rsum/rsumsq (one launch).
// ---------------------------------------------------------------------------
__global__ void __launch_bounds__(256) w2h_kernel(
    const float* __restrict__ w0, const float* __restrict__ w1,
    const float* __restrict__ w2, __half* __restrict__ h0,
    __half* __restrict__ h1, __half* __restrict__ h2,
    float* __restrict__ rsum, float* __restrict__ rsumsq) {
    int i = blockIdx.x * 256 + threadIdx.x;
    if (i < 98304) {
        const float2* s;
        __half2* d;
        int j;
        if (i < 32768)      { s = (const float2*)w0; d = (__half2*)h0; j = i; }
        else if (i < 65536) { s = (const float2*)w1; d = (__half2*)h1; j = i - 32768; }
        else                { s = (const float2*)w2; d = (__half2*)h2; j = i - 65536; }
        float2 v = s[j];
        d[j] = __floats2half2_rn(v.x, v.y);
    } else {
        int j = i - 98304;
        float4 z = make_float4(0.f, 0.f, 0.f, 0.f);
        if (j < 12800) reinterpret_cast<float4*>(rsum)[j] = z;
        else           reinterpret_cast<float4*>(rsumsq)[j - 12800] = z;
    }
}

// ---------------------------------------------------------------------------
// Warp-per-row LayerNorm; both streams emit HALF.
// ---------------------------------------------------------------------------
__global__ void __launch_bounds__(256) ln_fast(
    const float* __restrict__ x0, const float* __restrict__ ga0,
    const float* __restrict__ gb0, __half* __restrict__ y0,
    const float* __restrict__ x1, const float* __restrict__ ga1,
    const float* __restrict__ gb1, __half* __restrict__ y1, int split) {
    int blk = blockIdx.x;
    const float *x, *ga, *gb;
    __half* y;
    int rowbase;
    if (blk < split) { x = x0; ga = ga0; gb = gb0; y = y0; rowbase = blk * 8; }
    else { x = x1; ga = ga1; gb = gb1; y = y1; rowbase = (blk - split) * 8; }
    int w = threadIdx.x >> 5, lane = threadIdx.x & 31;
    size_t row = rowbase + w;
    const float4* x4 = reinterpret_cast<const float4*>(x + row * Dsz);
    float4 v0 = x4[lane];
    float4 v1 = x4[lane + 32];

    float s = v0.x + v0.y + v0.z + v0.w + v1.x + v1.y + v1.z + v1.w;
#pragma unroll
    for (int o = 16; o; o >>= 1) s += __shfl_xor_sync(0xffffffffu, s, o);
    float mean = s * (1.0f / Dsz);

    float d0x = v0.x - mean, d0y = v0.y - mean, d0z = v0.z - mean, d0w = v0.w - mean;
    float d1x = v1.x - mean, d1y = v1.y - mean, d1z = v1.z - mean, d1w = v1.w - mean;
    float ss = d0x * d0x + d0y * d0y + d0z * d0z + d0w * d0w +
               d1x * d1x + d1y * d1y + d1z * d1z + d1w * d1w;
#pragma unroll
    for (int o = 16; o; o >>= 1) ss += __shfl_xor_sync(0xffffffffu, ss, o);
    float var = ss * (1.0f / (Dsz - 1));
    float inv = 1.0f / (sqrtf(var) + 1e-6f);

    const float4* ga4 = reinterpret_cast<const float4*>(ga);
    const float4* gb4 = reinterpret_cast<const float4*>(gb);
    float4 g0 = ga4[lane], g1 = ga4[lane + 32];
    float4 b0 = gb4[lane], b1 = gb4[lane + 32];
    float4 o0 = make_float4(g0.x * d0x * inv + b0.x, g0.y * d0y * inv + b0.y,
                            g0.z * d0z * inv + b0.z, g0.w * d0w * inv + b0.w);
    float4 o1 = make_float4(g1.x * d1x * inv + b1.x, g1.y * d1y * inv + b1.y,
                            g1.z * d1z * inv + b1.z, g1.w * d1w * inv + b1.w);
    uint2* y2 = reinterpret_cast<uint2*>(y + row * Dsz);
    y2[lane] = make_uint2(packh2(o0.x, o0.y), packh2(o0.z, o0.w));
    y2[lane + 32] = make_uint2(packh2(o1.x, o1.y), packh2(o1.z, o1.w));
}

// ---------------------------------------------------------------------------
// fp16 GEMM (fp32 accum). Block 128x128, BK=64 (4 stages), 256 thr, 8 warps.
// EPI==0: out = acc + bias + add (ADDH: half add; OUTH: half out; STATS:
//         row sum/sumsq atomics).
// EPI==2: A is HALF, LN applied at staging (rsum/rsumsq + lga/lgb);
//         gelu epilogue; add half; out float.
// ---------------------------------------------------------------------------
#define GBM 128
#define GBN 128
#define GBK 64
#define HPITCH 144                      // bytes per 64-half row (+16 pad)
#define TILE_B (128 * HPITCH)           // 18432
#define STAGE_B (2 * TILE_B)            // 36864 per stage (A+B)

template <int EPI, bool STATS, bool ADDH, bool OUTH>
__global__ void __launch_bounds__(256) gemm_f16(
    const void* __restrict__ Aptr, const __half* __restrict__ W,
    const float* __restrict__ bias, const void* __restrict__ addp,
    const float* __restrict__ sffn, void* __restrict__ outp,
    const float* __restrict__ lga, const float* __restrict__ lgb,
    float* __restrict__ rsum, float* __restrict__ rsumsq) {
    extern __shared__ char gsm[];
    uint32_t smemU = (uint32_t)__cvta_generic_to_shared(gsm);

    int m0 = blockIdx.y * GBM;
    int n0 = blockIdx.x * GBN;
    int tid = threadIdx.x;
    int wid = tid >> 5, lane = tid & 31;
    int wm = wid >> 1, wn = wid & 1;
    int grp = lane >> 2, qd = lane & 3;

    int rA = (lane & 7) + ((lane >> 3) & 1) * 8;
    int offA = (wm * 32 + rA) * HPITCH + ((lane >> 4) & 1) * 16;
    int rB = (lane & 7) + ((lane >> 4) & 1) * 8;
    int offB = (wn * 64 + rB) * HPITCH + ((lane >> 3) & 1) * 16;

    float mean_t[4], inv_t[4];
    int lr = tid >> 3;              // 0..31 (EPI2 staging rows)
    int c8f = (tid & 7) * 8;        // 0..56 (half cols, chunk of 8)
    if (EPI == 2) {
#pragma unroll
        for (int t = 0; t < 4; t++) {
            int r = m0 + lr + 32 * t;
            float s = rsum[r], sq = rsumsq[r];
            float mn = s * (1.0f / Dsz);
            float var = (sq - (float)Dsz * mn * mn) * (1.0f / (Dsz - 1));
            mean_t[t] = mn;
            inv_t[t] = 1.0f / (sqrtf(var) + 1e-6f);
        }
    }

    float acc[2][8][4];
#pragma unroll
    for (int i = 0; i < 2; i++)
#pragma unroll
        for (int n = 0; n < 8; n++)
#pragma unroll
            for (int e = 0; e < 4; e++) acc[i][n][e] = 0.f;

    const __half* Ah = (const __half*)Aptr;

    auto stageW = [&](int buf, int k0) {
        uint32_t sb = smemU + buf * STAGE_B + TILE_B;
#pragma unroll
        for (int t = 0; t < 4; t++) {
            int idx = tid + 256 * t;
            int r = idx >> 3, c = idx & 7;
            cp_async16(sb + r * HPITCH + c * 16,
                       W + (size_t)(n0 + r) * Dsz + k0 + c * 8);
        }
    };
    auto stageA = [&](int buf, int k0) {
        uint32_t sa = smemU + buf * STAGE_B;
#pragma unroll
        for (int t = 0; t < 4; t++) {
            int idx = tid + 256 * t;
            int r = idx >> 3, c = idx & 7;
            cp_async16(sa + r * HPITCH + c * 16,
                       Ah + (size_t)(m0 + r) * Dsz + k0 + c * 8);
        }
    };

    const int NSTEP = Dsz / GBK;  // 4
    uint4 pa[4];

    if (EPI == 2) {
#pragma unroll
        for (int t = 0; t < 4; t++)
            pa[t] = *reinterpret_cast<const uint4*>(
                Ah + (size_t)(m0 + lr + 32 * t) * Dsz + c8f);
        stageW(0, 0);
        asm volatile("cp.async.commit_group;");
    } else {
        stageA(0, 0);
        stageW(0, 0);
        asm volatile("cp.async.commit_group;");
    }

    for (int s = 0; s < NSTEP; s++) {
        if (EPI == 2) {
            int k0 = s * GBK;
            float4 gaa = *reinterpret_cast<const float4*>(lga + k0 + c8f);
            float4 gab = *reinterpret_cast<const float4*>(lga + k0 + c8f + 4);
            float4 gba = *reinterpret_cast<const float4*>(lgb + k0 + c8f);
            float4 gbb = *reinterpret_cast<const float4*>(lgb + k0 + c8f + 4);
            uint32_t sa = smemU + (s & 1) * STAGE_B;
#pragma unroll
            for (int t = 0; t < 4; t++) {
                int r = lr + 32 * t;
                float2 p0 = __half22float2(*reinterpret_cast<__half2*>(&pa[t].x));
                float2 p1 = __half22float2(*reinterpret_cast<__half2*>(&pa[t].y));
                float2 p2 = __half22float2(*reinterpret_cast<__half2*>(&pa[t].z));
                float2 p3 = __half22float2(*reinterpret_cast<__half2*>(&pa[t].w));
                float mt = mean_t[t], it = inv_t[t];
                float v0 = (p0.x - mt) * it * gaa.x + gba.x;
                float v1 = (p0.y - mt) * it * gaa.y + gba.y;
                float v2 = (p1.x - mt) * it * gaa.z + gba.z;
                float v3 = (p1.y - mt) * it * gaa.w + gba.w;
                float v4 = (p2.x - mt) * it * gab.x + gbb.x;
                float v5 = (p2.y - mt) * it * gab.y + gbb.y;
                float v6 = (p3.x - mt) * it * gab.z + gbb.z;
                float v7 = (p3.y - mt) * it * gab.w + gbb.w;
                asm volatile("st.shared.v4.b32 [%0], {%1,%2,%3,%4};"
                             :: "r"(sa + r * HPITCH + c8f * 2),
                                "r"(packh2(v0, v1)), "r"(packh2(v2, v3)),
                                "r"(packh2(v4, v5)), "r"(packh2(v6, v7)));
            }
            if (s + 1 < NSTEP) {
#pragma unroll
                for (int t = 0; t < 4; t++)
                    pa[t] = *reinterpret_cast<const uint4*>(
                        Ah + (size_t)(m0 + lr + 32 * t) * Dsz + (s + 1) * GBK + c8f);
                stageW((s + 1) & 1, (s + 1) * GBK);
                asm volatile("cp.async.commit_group;");
                asm volatile("cp.async.wait_group 1;");
            } else {
                asm volatile("cp.async.wait_group 0;");
            }
        } else {
            if (s + 1 < NSTEP) {
                stageA((s + 1) & 1, (s + 1) * GBK);
                stageW((s + 1) & 1, (s + 1) * GBK);
                asm volatile("cp.async.commit_group;");
                asm volatile("cp.async.wait_group 1;");
            } else {
                asm volatile("cp.async.wait_group 0;");
            }
        }
        __syncthreads();

        uint32_t aB = smemU + (s & 1) * STAGE_B + offA;
        uint32_t bB = smemU + (s & 1) * STAGE_B + TILE_B + offB;
#pragma unroll
        for (int kb = 0; kb < 4; kb++) {
            uint32_t af[2][4];
#pragma unroll
            for (int i = 0; i < 2; i++)
                ldsm_x4(af[i][0], af[i][1], af[i][2], af[i][3],
                        aB + i * 16 * HPITCH + kb * 32);
            uint32_t bf[8][2];
#pragma unroll
            for (int p = 0; p < 4; p++) {
                uint32_t r0, r1, r2, r3;
                ldsm_x4(r0, r1, r2, r3, bB + p * 16 * HPITCH + kb * 32);
                bf[2 * p][0] = r0; bf[2 * p][1] = r1;
                bf[2 * p + 1][0] = r2; bf[2 * p + 1][1] = r3;
            }
#pragma unroll
            for (int i = 0; i < 2; i++)
#pragma unroll
                for (int n = 0; n < 8; n++)
                    mma_f16(acc[i][n], af[i], bf[n][0], bf[n][1]);
        }
        __syncthreads();
    }

    const float* addf = (const float*)addp;
    const __half* addh = (const __half*)addp;
    float* outf = (float*)outp;
    __half* outh = (__half*)outp;

#pragma unroll
    for (int i = 0; i < 2; i++) {
        int mr0 = m0 + wm * 32 + i * 16 + grp;
        int mr1 = mr0 + 8;
        float sf0 = 0.f, sf1 = 0.f;
        if (EPI == 2) {
            sf0 = sffn[mr0 % Ssz];
            sf1 = sffn[mr1 % Ssz];
        }
        float s0 = 0.f, q0s = 0.f, s1 = 0.f, q1s = 0.f;
#pragma unroll
        for (int n = 0; n < 8; n++) {
            int col = n0 + wn * 64 + n * 8 + 2 * qd;
            float2 bv = *reinterpret_cast<const float2*>(bias + col);
            float2 a0, a1;
            if (ADDH) {
                __half2 h0 = *reinterpret_cast<const __half2*>(
                    addh + (size_t)mr0 * Dsz + col);
                __half2 h1v = *reinterpret_cast<const __half2*>(
                    addh + (size_t)mr1 * Dsz + col);
                a0 = __half22float2(h0);
                a1 = __half22float2(h1v);
            } else {
                a0 = *reinterpret_cast<const float2*>(
                    addf + (size_t)mr0 * Dsz + col);
                a1 = *reinterpret_cast<const float2*>(
                    addf + (size_t)mr1 * Dsz + col);
            }
            float r00 = acc[i][n][0] + bv.x, r01 = acc[i][n][1] + bv.y;
            float r10 = acc[i][n][2] + bv.x, r11 = acc[i][n][3] + bv.y;
            if (EPI == 0) {
                r00 += a0.x; r01 += a0.y; r10 += a1.x; r11 += a1.y;
                if (STATS) {
                    s0 += r00 + r01; q0s += r00 * r00 + r01 * r01;
                    s1 += r10 + r11; q1s += r10 * r10 + r11 * r11;
                }
            } else {
                float z, th;
                z = sf0 * r00;
                th = tanhf(0.79788456080286536f * (z + 0.044715f * z * z * z));
                r00 = a0.x + 0.5f * z * (1.0f + th);
                z = sf0 * r01;
                th = tanhf(0.79788456080286536f * (z + 0.044715f * z * z * z));
                r01 = a0.y + 0.5f * z * (1.0f + th);
                z = sf1 * r10;
                th = tanhf(0.79788456080286536f * (z + 0.044715f * z * z * z));
                r10 = a1.x + 0.5f * z * (1.0f + th);
                z = sf1 * r11;
                th = tanhf(0.79788456080286536f * (z + 0.044715f * z * z * z));
                r11 = a1.y + 0.5f * z * (1.0f + th);
            }
            if (OUTH) {
                *reinterpret_cast<uint32_t*>(outh + (size_t)mr0 * Dsz + col) =
                    packh2(r00, r01);
                *reinterpret_cast<uint32_t*>(outh + (size_t)mr1 * Dsz + col) =
                    packh2(r10, r11);
            } else {
                *reinterpret_cast<float2*>(outf + (size_t)mr0 * Dsz + col) =
                    make_float2(r00, r01);
                *reinterpret_cast<float2*>(outf + (size_t)mr1 * Dsz + col) =
                    make_float2(r10, r11);
            }
        }
        if (STATS) {
            const unsigned FULL = 0xffffffffu;
            s0 += __shfl_xor_sync(FULL, s0, 1);
            s0 += __shfl_xor_sync(FULL, s0, 2);
            q0s += __shfl_xor_sync(FULL, q0s, 1);
            q0s += __shfl_xor_sync(FULL, q0s, 2);
            s1 += __shfl_xor_sync(FULL, s1, 1);
            s1 += __shfl_xor_sync(FULL, s1, 2);
            q1s += __shfl_xor_sync(FULL, q1s, 1);
            q1s += __shfl_xor_sync(FULL, q1s, 2);
            if (qd == 0) {
                atomicAdd(&rsum[mr0], s0);
                atomicAdd(&rsumsq[mr0], q0s);
                atomicAdd(&rsum[mr1], s1);
                atomicAdd(&rsumsq[mr1], q1s);
            }
        }
    }
}

// ---------------------------------------------------------------------------
// fp16 flash-attention (unchanged from R12, 64.5us).
// ---------------------------------------------------------------------------
#define SPAD 224
#define HP 80
#define QV_B (SPAD * HP)
#define ATHR 416
#define LOG2E 1.4426950408889634f

__global__ void __launch_bounds__(ATHR) attn_flash(
    const __half* __restrict__ img_h, const __half* __restrict__ keff_h,
    const int* __restrict__ mask, const float* __restrict__ sattn,
    __half* __restrict__ ctx_h) {
    extern __shared__ char smw[];
    uint32_t smemU = (uint32_t)__cvta_generic_to_shared(smw);
    uint32_t qvU = smemU;
    uint32_t ksU = smemU + QV_B;
    float* bias_s = reinterpret_cast<float*>(smw + 2 * QV_B);

    int b = blockIdx.x >> 3;
    int h = blockIdx.x & 7;
    int tid = threadIdx.x;
    size_t base = ((size_t)b * Ssz) * Dsz + h * DHsz;

    for (int idx = tid; idx < SPAD * 4; idx += ATHR) {
        int r = idx >> 2, c8 = (idx & 3) * 8;
        uint4 q = make_uint4(0u, 0u, 0u, 0u);
        uint4 k = make_uint4(0u, 0u, 0u, 0u);
        if (r < Ssz) {
            q = *reinterpret_cast<const uint4*>(img_h + base + (size_t)r * Dsz + c8);
            k = *reinterpret_cast<const uint4*>(keff_h + base + (size_t)r * Dsz + c8);
        }
        asm volatile("st.shared.v4.b32 [%0], {%1,%2,%3,%4};"
                     :: "r"(qvU + r * HP + c8 * 2),
                        "r"(q.x), "r"(q.y), "r"(q.z), "r"(q.w));
        asm volatile("st.shared.v4.b32 [%0], {%1,%2,%3,%4};"
                     :: "r"(ksU + r * HP + c8 * 2),
                        "r"(k.x), "r"(k.y), "r"(k.z), "r"(k.w));
    }
    for (int k = tid; k < SPAD; k += ATHR)
        bias_s[k] = (k >= Ssz || mask[b * Ssz + k] == 0) ? -1.4426950e9f : 0.f;
    __syncthreads();

    int w = tid >> 5, lane = tid & 31;
    int grp = lane >> 2;
    int qd = lane & 3;
    const float isq2 = 0.17677669529663687f * LOG2E;
    const unsigned FULL = 0xffffffffu;

    int q0 = w * 16;
    int qr0 = q0 + grp, qr1 = q0 + grp + 8;
    float f0 = (qr0 < Ssz) ? isq2 * sattn[h * Ssz + qr0] : 0.f;
    float f1 = (qr1 < Ssz) ? isq2 * sattn[h * Ssz + qr1] : 0.f;

    uint32_t aq[2][4];
    {
        int rA = (lane & 7) + ((lane >> 3) & 1) * 8;
        uint32_t offA = qvU + (q0 + rA) * HP + ((lane >> 4) & 1) * 16;
        ldsm_x4(aq[0][0], aq[0][1], aq[0][2], aq[0][3], offA);
        ldsm_x4(aq[1][0], aq[1][1], aq[1][2], aq[1][3], offA + 32);
    }

    int rB = (lane & 7) + ((lane >> 4) & 1) * 8;
    int rV = (lane & 7) + ((lane >> 3) & 1) * 8;
    int cB = ((lane >> 3) & 1) * 16;
    int cV = ((lane >> 4) & 1) * 16;

    float m0 = -3.0e38f, m1 = -3.0e38f, l0 = 0.f, l1 = 0.f;
    float co[4][4];
#pragma unroll
    for (int n = 0; n < 4; n++)
#pragma unroll
        for (int e = 0; e < 4; e++) co[n][e] = 0.f;

    for (int it = 0; it < 7; it++) {
        int key0 = it * 32;
        float sA[2][4] = {{0.f, 0.f, 0.f, 0.f}, {0.f, 0.f, 0.f, 0.f}};
        float sB[2][4] = {{0.f, 0.f, 0.f, 0.f}, {0.f, 0.f, 0.f, 0.f}};
        uint32_t offB = ksU + (key0 + rB) * HP + cB;
#pragma unroll
        for (int kk = 0; kk < 2; kk++) {
            uint32_t r0, r1, r2, r3;
            ldsm_x4(r0, r1, r2, r3, offB + kk * 32);
            mma_f16(sA[0], aq[kk], r0, r1);
            mma_f16(sA[1], aq[kk], r2, r3);
            ldsm_x4(r0, r1, r2, r3, offB + 16 * HP + kk * 32);
            mma_f16(sB[0], aq[kk], r0, r1);
            mma_f16(sB[1], aq[kk], r2, r3);
        }
        float vA[2][4], vB[2][4];
        float rm0 = -3.0e38f, rm1 = -3.0e38f;
#pragma unroll
        for (int n = 0; n < 2; n++) {
            float2 bkA = *reinterpret_cast<const float2*>(
                bias_s + key0 + n * 8 + 2 * qd);
            vA[n][0] = fmaf(sA[n][0], f0, bkA.x);
            vA[n][1] = fmaf(sA[n][1], f0, bkA.y);
            vA[n][2] = fmaf(sA[n][2], f1, bkA.x);
            vA[n][3] = fmaf(sA[n][3], f1, bkA.y);
            float2 bkB = *reinterpret_cast<const float2*>(
                bias_s + key0 + 16 + n * 8 + 2 * qd);
            vB[n][0] = fmaf(sB[n][0], f0, bkB.x);
            vB[n][1] = fmaf(sB[n][1], f0, bkB.y);
            vB[n][2] = fmaf(sB[n][2], f1, bkB.x);
            vB[n][3] = fmaf(sB[n][3], f1, bkB.y);
            rm0 = fmaxf(rm0, fmaxf(fmaxf(vA[n][0], vA[n][1]),
                                   fmaxf(vB[n][0], vB[n][1])));
            rm1 = fmaxf(rm1, fmaxf(fmaxf(vA[n][2], vA[n][3]),
                                   fmaxf(vB[n][2], vB[n][3])));
        }
        rm0 = fmaxf(rm0, __shfl_xor_sync(FULL, rm0, 1));
        rm0 = fmaxf(rm0, __shfl_xor_sync(FULL, rm0, 2));
        rm1 = fmaxf(rm1, __shfl_xor_sync(FULL, rm1, 1));
        rm1 = fmaxf(rm1, __shfl_xor_sync(FULL, rm1, 2));
        float nm0 = fmaxf(m0, rm0), nm1 = fmaxf(m1, rm1);
        float al0 = ex2f(m0 - nm0), al1 = ex2f(m1 - nm1);
        m0 = nm0; m1 = nm1;
#pragma unroll
        for (int n = 0; n < 4; n++) {
            co[n][0] *= al0; co[n][1] *= al0;
            co[n][2] *= al1; co[n][3] *= al1;
        }
        float ts0 = 0.f, ts1 = 0.f;
        uint32_t ap[4], ap2[4];
#pragma unroll
        for (int n = 0; n < 2; n++) {
            float e0 = ex2f(vA[n][0] - nm0);
            float e1 = ex2f(vA[n][1] - nm0);
            float e2 = ex2f(vA[n][2] - nm1);
            float e3 = ex2f(vA[n][3] - nm1);
            ts0 += e0 + e1;
            ts1 += e2 + e3;
            ap[2 * n]     = packh2(e0, e1);
            ap[2 * n + 1] = packh2(e2, e3);
            e0 = ex2f(vB[n][0] - nm0);
            e1 = ex2f(vB[n][1] - nm0);
            e2 = ex2f(vB[n][2] - nm1);
            e3 = ex2f(vB[n][3] - nm1);
            ts0 += e0 + e1;
            ts1 += e2 + e3;
            ap2[2 * n]     = packh2(e0, e1);
            ap2[2 * n + 1] = packh2(e2, e3);
        }
        l0 = l0 * al0 + ts0;
        l1 = l1 * al1 + ts1;
        uint32_t offV = qvU + (key0 + rV) * HP + cV;
        {
            uint32_t r0, r1, r2, r3;
            ldsm_x4t(r0, r1, r2, r3, offV);
            mma_f16(co[0], ap, r0, r1);
            mma_f16(co[1], ap, r2, r3);
            ldsm_x4t(r0, r1, r2, r3, offV + 32);
            mma_f16(co[2], ap, r0, r1);
            mma_f16(co[3], ap, r2, r3);
            ldsm_x4t(r0, r1, r2, r3, offV + 16 * HP);
            mma_f16(co[0], ap2, r0, r1);
            mma_f16(co[1], ap2, r2, r3);
            ldsm_x4t(r0, r1, r2, r3, offV + 16 * HP + 32);
            mma_f16(co[2], ap2, r0, r1);
            mma_f16(co[3], ap2, r2, r3);
        }
    }

    l0 += __shfl_xor_sync(FULL, l0, 1);
    l0 += __shfl_xor_sync(FULL, l0, 2);
    l1 += __shfl_xor_sync(FULL, l1, 1);
    l1 += __shfl_xor_sync(FULL, l1, 2);
    float inv0 = 1.f / l0, inv1 = 1.f / l1;
#pragma unroll
    for (int n4 = 0; n4 < 4; n4++) {
        if (qr0 < Ssz) {
            __half2 v = __floats2half2_rn(co[n4][0] * inv0, co[n4][1] * inv0);
            *reinterpret_cast<__half2*>(
                ctx_h + base + (size_t)qr0 * Dsz + n4 * 8 + 2 * qd) = v;
        }
        if (qr1 < Ssz) {
            __half2 v = __floats2half2_rn(co[n4][2] * inv1, co[n4][3] * inv1);
            *reinterpret_cast<__half2*>(
                ctx_h + base + (size_t)qr1 * Dsz + n4 * 8 + 2 * qd) = v;
        }
    }
}

// ---------------------------------------------------------------------------
extern "C" void kernel_launch(void* const* d_in, const int* in_sizes, int n_in,
                              void* d_out, int out_size) {
    const float* hidden_img   = (const float*)d_in[0];
    const float* hidden_title = (const float*)d_in[1];
    const int*   mask         = (const int*)  d_in[2];
    const float* a_img   = (const float*)d_in[3];
    const float* b_img   = (const float*)d_in[4];
    const float* a_title = (const float*)d_in[5];
    const float* b_title = (const float*)d_in[6];
    const float* Wb      = (const float*)d_in[7];
    const float* bb      = (const float*)d_in[8];
    const float* Wo      = (const float*)d_in[9];
    const float* bo      = (const float*)d_in[10];
    const float* sattn   = (const float*)d_in[11];
    const float* a_out   = (const float*)d_in[12];
    const float* b_out   = (const float*)d_in[13];
    const float* W1      = (const float*)d_in[14];
    const float* b1      = (const float*)d_in[15];
    const float* sffn    = (const float*)d_in[16];
    float* out = (float*)d_out;

    float *rsum, *rsumsq;
    __half *h1_h, *img_h, *title_h, *keff_h, *ctx_h, *Wb_h, *Wo_h, *W1_h;
    cudaGetSymbolAddress((void**)&rsum,    g_rsum);
    cudaGetSymbolAddress((void**)&rsumsq,  g_rsumsq);
    cudaGetSymbolAddress((void**)&h1_h,    g_h1_h);
    cudaGetSymbolAddress((void**)&img_h,   g_img_h);
    cudaGetSymbolAddress((void**)&title_h, g_title_h);
    cudaGetSymbolAddress((void**)&keff_h,  g_keff_h);
    cudaGetSymbolAddress((void**)&ctx_h,   g_ctx_h);
    cudaGetSymbolAddress((void**)&Wb_h,    g_Wb_h);
    cudaGetSymbolAddress((void**)&Wo_h,    g_Wo_h);
    cudaGetSymbolAddress((void**)&W1_h,    g_W1_h);

    const int LNB = BS / 8;
    const int gemm_smem = 2 * STAGE_B;   // 73728 B
    cudaFuncSetAttribute((const void*)gemm_f16<0, false, true, true>,
                         cudaFuncAttributeMaxDynamicSharedMemorySize, gemm_smem);
    cudaFuncSetAttribute((const void*)gemm_f16<0, true, false, true>,
                         cudaFuncAttributeMaxDynamicSharedMemorySize, gemm_smem);
    cudaFuncSetAttribute((const void*)gemm_f16<2, false, true, false>,
                         cudaFuncAttributeMaxDynamicSharedMemorySize, gemm_smem);

    // 0) weights -> half + zero row stats
    w2h_kernel<<<484, 256>>>(Wb, Wo, W1, Wb_h, Wo_h, W1_h, rsum, rsumsq);

    // 1) both input LayerNorms -> half
    ln_fast<<<2 * LNB, 256>>>(hidden_img, a_img, b_img, img_h,
                              hidden_title, a_title, b_title, title_h, LNB);

    // 2) keff(half) = title_n @ Wb^T + bb + img_n(half)
    dim3 gg(Dsz / GBN, BS / GBM);
    gemm_f16<0, false, true, true><<<gg, 256, gemm_smem>>>(
        title_h, Wb_h, bb, img_h, nullptr, keff_h, nullptr, nullptr,
        nullptr, nullptr);

    // 3) fp16 flash attention -> ctx half
    const int attn_smem = 2 * QV_B + SPAD * 4;
    cudaFuncSetAttribute(attn_flash,
                         cudaFuncAttributeMaxDynamicSharedMemorySize, attn_smem);
    attn_flash<<<Bsz * Hsz, ATHR, attn_smem>>>(img_h, keff_h, mask, sattn, ctx_h);

    // 4) h1(half) = ctx @ Wo^T + bo + hidden_img  (+ row stats)
    gemm_f16<0, true, false, true><<<gg, 256, gemm_smem>>>(
        ctx_h, Wo_h, bo, hidden_img, nullptr, h1_h, nullptr, nullptr,
        rsum, rsumsq);

    // 5) out = h1 + gelu_tanh(scale_ffn * (LN(h1) @ W1^T + b1))
    gemm_f16<2, false, true, false><<<gg, 256, gemm_smem>>>(
        h1_h, W1_h, b1, h1_h, sffn, out, a_out, b_out, rsum, rsumsq);
}

// round 15
// speedup vs baseline: 4.7800x; 1.0159x over previous
#include <cuda_runtime.h>
#include <cuda_fp16.h>
#include <math.h>
#include <stdint.h>

#define Bsz 256
#define Ssz 200
#define Dsz 256
#define Hsz 8
#define DHsz 32
#define BS (Bsz * Ssz)   // 51200 rows

__device__ float g_rsum[BS];
__device__ float g_rsumsq[BS];
__device__ __half g_h1_h[BS * Dsz];
__device__ __half g_img_h[BS * Dsz];
__device__ __half g_title_h[BS * Dsz];
__device__ __half g_keff_h[BS * Dsz];
__device__ __half g_ctx_h[BS * Dsz];
__device__ __half g_Wb_h[Dsz * Dsz];
__device__ __half g_Wo_h[Dsz * Dsz];
__device__ __half g_W1_h[Dsz * Dsz];

__device__ __forceinline__ void mma_f16(float* c, const uint32_t* a,
                                        uint32_t b0, uint32_t b1) {
    asm volatile(
        "mma.sync.aligned.m16n8k16.row.col.f32.f16.f16.f32 "
        "{%0,%1,%2,%3}, {%4,%5,%6,%7}, {%8,%9}, {%0,%1,%2,%3};"
        : "+f"(c[0]), "+f"(c[1]), "+f"(c[2]), "+f"(c[3])
        : "r"(a[0]), "r"(a[1]), "r"(a[2]), "r"(a[3]), "r"(b0), "r"(b1));
}

__device__ __forceinline__ void ldsm_x4(uint32_t& r0, uint32_t& r1,
                                        uint32_t& r2, uint32_t& r3,
                                        uint32_t addr) {
    asm volatile(
        "ldmatrix.sync.aligned.m8n8.x4.shared.b16 {%0,%1,%2,%3}, [%4];"
        : "=r"(r0), "=r"(r1), "=r"(r2), "=r"(r3) : "r"(addr));
}

__device__ __forceinline__ void ldsm_x4t(uint32_t& r0, uint32_t& r1,
                                         uint32_t& r2, uint32_t& r3,
                                         uint32_t addr) {
    asm volatile(
        "ldmatrix.sync.aligned.m8n8.x4.trans.shared.b16 {%0,%1,%2,%3}, [%4];"
        : "=r"(r0), "=r"(r1), "=r"(r2), "=r"(r3) : "r"(addr));
}

__device__ __forceinline__ void cp_async16(uint32_t smem, const void* g) {
    asm volatile("cp.async.cg.shared.global [%0], [%1], 16;"
                 :: "r"(smem), "l"(g));
}

__device__ __forceinline__ uint32_t packh2(float a, float b) {
    __half2 h = __floats2half2_rn(a, b);
    return *reinterpret_cast<uint32_t*>(&h);
}

__device__ __forceinline__ float ex2f(float x) {
    float r;
    asm("ex2.approx.f32 %0, %1;" : "=f"(r) : "f"(x));
    return r;
}

// ---------------------------------------------------------------------------
// Fused: LayerNorm both streams -> half (blocks [0, 2*split)), then
// weights->half + rsum/rsumsq zero (blocks [2*split, 2*split+484)).
// ---------------------------------------------------------------------------
__global__ void __launch_bounds__(256) ln_w2h(
    const float* __restrict__ x0, const float* __restrict__ ga0,
    const float* __restrict__ gb0, __half* __restrict__ y0,
    const float* __restrict__ x1, const float* __restrict__ ga1,
    const float* __restrict__ gb1, __half* __restrict__ y1, int split,
    const float* __restrict__ w0, const float* __restrict__ w1,
    const float* __restrict__ w2, __half* __restrict__ h0,
    __half* __restrict__ h1, __half* __restrict__ h2,
    float* __restrict__ rsum, float* __restrict__ rsumsq) {
    int blk = blockIdx.x;
    if (blk >= 2 * split) {
        int i = (blk - 2 * split) * 256 + threadIdx.x;
        if (i < 98304) {
            const float2* s;
            __half2* d;
            int j;
            if (i < 32768)      { s = (const float2*)w0; d = (__half2*)h0; j = i; }
            else if (i < 65536) { s = (const float2*)w1; d = (__half2*)h1; j = i - 32768; }
            else                { s = (const float2*)w2; d = (__half2*)h2; j = i - 65536; }
            float2 v = s[j];
            d[j] = __floats2half2_rn(v.x, v.y);
        } else {
            int j = i - 98304;
            float4 z = make_float4(0.f, 0.f, 0.f, 0.f);
            if (j < 12800) reinterpret_cast<float4*>(rsum)[j] = z;
            else           reinterpret_cast<float4*>(rsumsq)[j - 12800] = z;
        }
        return;
    }
    const float *x, *ga, *gb;
    __half* y;
    int rowbase;
    if (blk < split) { x = x0; ga = ga0; gb = gb0; y = y0; rowbase = blk * 8; }
    else { x = x1; ga = ga1; gb = gb1; y = y1; rowbase = (blk - split) * 8; }
    int w = threadIdx.x >> 5, lane = threadIdx.x & 31;
    size_t row = rowbase + w;
    const float4* x4 = reinterpret_cast<const float4*>(x + row * Dsz);
    float4 v0 = x4[lane];
    float4 v1 = x4[lane + 32];

    float s = v0.x + v0.y + v0.z + v0.w + v1.x + v1.y + v1.z + v1.w;
#pragma unroll
    for (int o = 16; o; o >>= 1) s += __shfl_xor_sync(0xffffffffu, s, o);
    float mean = s * (1.0f / Dsz);

    float d0x = v0.x - mean, d0y = v0.y - mean, d0z = v0.z - mean, d0w = v0.w - mean;
    float d1x = v1.x - mean, d1y = v1.y - mean, d1z = v1.z - mean, d1w = v1.w - mean;
    float ss = d0x * d0x + d0y * d0y + d0z * d0z + d0w * d0w +
               d1x * d1x + d1y * d1y + d1z * d1z + d1w * d1w;
#pragma unroll
    for (int o = 16; o; o >>= 1) ss += __shfl_xor_sync(0xffffffffu, ss, o);
    float var = ss * (1.0f / (Dsz - 1));
    float inv = 1.0f / (sqrtf(var) + 1e-6f);

    const float4* ga4 = reinterpret_cast<const float4*>(ga);
    const float4* gb4 = reinterpret_cast<const float4*>(gb);
    float4 g0 = ga4[lane], g1 = ga4[lane + 32];
    float4 b0 = gb4[lane], b1 = gb4[lane + 32];
    float4 o0 = make_float4(g0.x * d0x * inv + b0.x, g0.y * d0y * inv + b0.y,
                            g0.z * d0z * inv + b0.z, g0.w * d0w * inv + b0.w);
    float4 o1 = make_float4(g1.x * d1x * inv + b1.x, g1.y * d1y * inv + b1.y,
                            g1.z * d1z * inv + b1.z, g1.w * d1w * inv + b1.w);
    uint2* y2 = reinterpret_cast<uint2*>(y + row * Dsz);
    y2[lane] = make_uint2(packh2(o0.x, o0.y), packh2(o0.z, o0.w));
    y2[lane + 32] = make_uint2(packh2(o1.x, o1.y), packh2(o1.z, o1.w));
}

// ---------------------------------------------------------------------------
// fp16 GEMM (fp32 accum). Block 128x128, BK=64 (4 stages), 256 thr, 8 warps.
// Single-sync pipeline: wait(s) -> sync -> issue copies(s+1) -> mma(s).
// EPI==0: out = acc + bias + add (ADDH/OUTH/STATS as before).
// EPI==2: A half, LN at staging; A(s+1) transform runs after mma(s).
// ---------------------------------------------------------------------------
#define GBM 128
#define GBN 128
#define GBK 64
#define HPITCH 144
#define TILE_B (128 * HPITCH)
#define STAGE_B (2 * TILE_B)

template <int EPI, bool STATS, bool ADDH, bool OUTH>
__global__ void __launch_bounds__(256) gemm_f16(
    const void* __restrict__ Aptr, const __half* __restrict__ W,
    const float* __restrict__ bias, const void* __restrict__ addp,
    const float* __restrict__ sffn, void* __restrict__ outp,
    const float* __restrict__ lga, const float* __restrict__ lgb,
    float* __restrict__ rsum, float* __restrict__ rsumsq) {
    extern __shared__ char gsm[];
    uint32_t smemU = (uint32_t)__cvta_generic_to_shared(gsm);

    int m0 = blockIdx.y * GBM;
    int n0 = blockIdx.x * GBN;
    int tid = threadIdx.x;
    int wid = tid >> 5, lane = tid & 31;
    int wm = wid >> 1, wn = wid & 1;
    int grp = lane >> 2, qd = lane & 3;

    int rA = (lane & 7) + ((lane >> 3) & 1) * 8;
    int offA = (wm * 32 + rA) * HPITCH + ((lane >> 4) & 1) * 16;
    int rB = (lane & 7) + ((lane >> 4) & 1) * 8;
    int offB = (wn * 64 + rB) * HPITCH + ((lane >> 3) & 1) * 16;

    float mean_t[4], inv_t[4];
    int lr = tid >> 3;
    int c8f = (tid & 7) * 8;
    if (EPI == 2) {
#pragma unroll
        for (int t = 0; t < 4; t++) {
            int r = m0 + lr + 32 * t;
            float s = rsum[r], sq = rsumsq[r];
            float mn = s * (1.0f / Dsz);
            float var = (sq - (float)Dsz * mn * mn) * (1.0f / (Dsz - 1));
            mean_t[t] = mn;
            inv_t[t] = 1.0f / (sqrtf(var) + 1e-6f);
        }
    }

    float acc[2][8][4];
#pragma unroll
    for (int i = 0; i < 2; i++)
#pragma unroll
        for (int n = 0; n < 8; n++)
#pragma unroll
            for (int e = 0; e < 4; e++) acc[i][n][e] = 0.f;

    const __half* Ah = (const __half*)Aptr;

    auto stageW = [&](int buf, int k0) {
        uint32_t sb = smemU + buf * STAGE_B + TILE_B;
#pragma unroll
        for (int t = 0; t < 4; t++) {
            int idx = tid + 256 * t;
            int r = idx >> 3, c = idx & 7;
            cp_async16(sb + r * HPITCH + c * 16,
                       W + (size_t)(n0 + r) * Dsz + k0 + c * 8);
        }
    };
    auto stageA = [&](int buf, int k0) {
        uint32_t sa = smemU + buf * STAGE_B;
#pragma unroll
        for (int t = 0; t < 4; t++) {
            int idx = tid + 256 * t;
            int r = idx >> 3, c = idx & 7;
            cp_async16(sa + r * HPITCH + c * 16,
                       Ah + (size_t)(m0 + r) * Dsz + k0 + c * 8);
        }
    };
    auto transA = [&](int buf, int k0, const uint4* pa) {
        float4 gaa = *reinterpret_cast<const float4*>(lga + k0 + c8f);
        float4 gab = *reinterpret_cast<const float4*>(lga + k0 + c8f + 4);
        float4 gba = *reinterpret_cast<const float4*>(lgb + k0 + c8f);
        float4 gbb = *reinterpret_cast<const float4*>(lgb + k0 + c8f + 4);
        uint32_t sa = smemU + buf * STAGE_B;
#pragma unroll
        for (int t = 0; t < 4; t++) {
            int r = lr + 32 * t;
            float2 p0 = __half22float2(*reinterpret_cast<const __half2*>(&pa[t].x));
            float2 p1 = __half22float2(*reinterpret_cast<const __half2*>(&pa[t].y));
            float2 p2 = __half22float2(*reinterpret_cast<const __half2*>(&pa[t].z));
            float2 p3 = __half22float2(*reinterpret_cast<const __half2*>(&pa[t].w));
            float mt = mean_t[t], it = inv_t[t];
            float v0 = (p0.x - mt) * it * gaa.x + gba.x;
            float v1 = (p0.y - mt) * it * gaa.y + gba.y;
            float v2 = (p1.x - mt) * it * gaa.z + gba.z;
            float v3 = (p1.y - mt) * it * gaa.w + gba.w;
            float v4 = (p2.x - mt) * it * gab.x + gbb.x;
            float v5 = (p2.y - mt) * it * gab.y + gbb.y;
            float v6 = (p3.x - mt) * it * gab.z + gbb.z;
            float v7 = (p3.y - mt) * it * gab.w + gbb.w;
            asm volatile("st.shared.v4.b32 [%0], {%1,%2,%3,%4};"
                         :: "r"(sa + r * HPITCH + c8f * 2),
                            "r"(packh2(v0, v1)), "r"(packh2(v2, v3)),
                            "r"(packh2(v4, v5)), "r"(packh2(v6, v7)));
        }
    };

    const int NSTEP = Dsz / GBK;  // 4
    uint4 pa[4];

    if (EPI == 2) {
#pragma unroll
        for (int t = 0; t < 4; t++)
            pa[t] = *reinterpret_cast<const uint4*>(
                Ah + (size_t)(m0 + lr + 32 * t) * Dsz + c8f);
        stageW(0, 0);
        asm volatile("cp.async.commit_group;");
        transA(0, 0, pa);   // stalls on pa LDG once
    } else {
        stageA(0, 0);
        stageW(0, 0);
        asm volatile("cp.async.commit_group;");
    }

    for (int s = 0; s < NSTEP; s++) {
        if (EPI == 2 && s + 1 < NSTEP) {
            // issue raw-A loads for s+1 early (hidden under mma(s))
#pragma unroll
            for (int t = 0; t < 4; t++)
                pa[t] = *reinterpret_cast<const uint4*>(
                    Ah + (size_t)(m0 + lr + 32 * t) * Dsz + (s + 1) * GBK + c8f);
        }
        asm volatile("cp.async.wait_group 0;");
        __syncthreads();   // copies(s) visible; all warps done with mma(s-1)
        if (s + 1 < NSTEP) {
            if (EPI != 2) stageA((s + 1) & 1, (s + 1) * GBK);
            stageW((s + 1) & 1, (s + 1) * GBK);
            asm volatile("cp.async.commit_group;");
        }

        uint32_t aB = smemU + (s & 1) * STAGE_B + offA;
        uint32_t bB = smemU + (s & 1) * STAGE_B + TILE_B + offB;
#pragma unroll
        for (int kb = 0; kb < 4; kb++) {
            uint32_t af[2][4];
#pragma unroll
            for (int i = 0; i < 2; i++)
                ldsm_x4(af[i][0], af[i][1], af[i][2], af[i][3],
                        aB + i * 16 * HPITCH + kb * 32);
            uint32_t bf[8][2];
#pragma unroll
            for (int p = 0; p < 4; p++) {
                uint32_t r0, r1, r2, r3;
                ldsm_x4(r0, r1, r2, r3, bB + p * 16 * HPITCH + kb * 32);
                bf[2 * p][0] = r0; bf[2 * p][1] = r1;
                bf[2 * p + 1][0] = r2; bf[2 * p + 1][1] = r3;
            }
#pragma unroll
            for (int i = 0; i < 2; i++)
#pragma unroll
                for (int n = 0; n < 8; n++)
                    mma_f16(acc[i][n], af[i], bf[n][0], bf[n][1]);
        }
        if (EPI == 2 && s + 1 < NSTEP)
            transA((s + 1) & 1, (s + 1) * GBK, pa);   // pa arrived during mma
    }

    const float* addf = (const float*)addp;
    const __half* addh = (const __half*)addp;
    float* outf = (float*)outp;
    __half* outh = (__half*)outp;

#pragma unroll
    for (int i = 0; i < 2; i++) {
        int mr0 = m0 + wm * 32 + i * 16 + grp;
        int mr1 = mr0 + 8;
        float sf0 = 0.f, sf1 = 0.f;
        if (EPI == 2) {
            sf0 = sffn[mr0 % Ssz];
            sf1 = sffn[mr1 % Ssz];
        }
        float s0 = 0.f, q0s = 0.f, s1 = 0.f, q1s = 0.f;
#pragma unroll
        for (int n = 0; n < 8; n++) {
            int col = n0 + wn * 64 + n * 8 + 2 * qd;
            float2 bv = *reinterpret_cast<const float2*>(bias + col);
            float2 a0, a1;
            if (ADDH) {
                __half2 h0 = *reinterpret_cast<const __half2*>(
                    addh + (size_t)mr0 * Dsz + col);
                __half2 h1v = *reinterpret_cast<const __half2*>(
                    addh + (size_t)mr1 * Dsz + col);
                a0 = __half22float2(h0);
                a1 = __half22float2(h1v);
            } else {
                a0 = *reinterpret_cast<const float2*>(
                    addf + (size_t)mr0 * Dsz + col);
                a1 = *reinterpret_cast<const float2*>(
                    addf + (size_t)mr1 * Dsz + col);
            }
            float r00 = acc[i][n][0] + bv.x, r01 = acc[i][n][1] + bv.y;
            float r10 = acc[i][n][2] + bv.x, r11 = acc[i][n][3] + bv.y;
            if (EPI == 0) {
                r00 += a0.x; r01 += a0.y; r10 += a1.x; r11 += a1.y;
                if (STATS) {
                    s0 += r00 + r01; q0s += r00 * r00 + r01 * r01;
                    s1 += r10 + r11; q1s += r10 * r10 + r11 * r11;
                }
            } else {
                float z, th;
                z = sf0 * r00;
                th = tanhf(0.79788456080286536f * (z + 0.044715f * z * z * z));
                r00 = a0.x + 0.5f * z * (1.0f + th);
                z = sf0 * r01;
                th = tanhf(0.79788456080286536f * (z + 0.044715f * z * z * z));
                r01 = a0.y + 0.5f * z * (1.0f + th);
                z = sf1 * r10;
                th = tanhf(0.79788456080286536f * (z + 0.044715f * z * z * z));
                r10 = a1.x + 0.5f * z * (1.0f + th);
                z = sf1 * r11;
                th = tanhf(0.79788456080286536f * (z + 0.044715f * z * z * z));
                r11 = a1.y + 0.5f * z * (1.0f + th);
            }
            if (OUTH) {
                *reinterpret_cast<uint32_t*>(outh + (size_t)mr0 * Dsz + col) =
                    packh2(r00, r01);
                *reinterpret_cast<uint32_t*>(outh + (size_t)mr1 * Dsz + col) =
                    packh2(r10, r11);
            } else {
                *reinterpret_cast<float2*>(outf + (size_t)mr0 * Dsz + col) =
                    make_float2(r00, r01);
                *reinterpret_cast<float2*>(outf + (size_t)mr1 * Dsz + col) =
                    make_float2(r10, r11);
            }
        }
        if (STATS) {
            const unsigned FULL = 0xffffffffu;
            s0 += __shfl_xor_sync(FULL, s0, 1);
            s0 += __shfl_xor_sync(FULL, s0, 2);
            q0s += __shfl_xor_sync(FULL, q0s, 1);
            q0s += __shfl_xor_sync(FULL, q0s, 2);
            s1 += __shfl_xor_sync(FULL, s1, 1);
            s1 += __shfl_xor_sync(FULL, s1, 2);
            q1s += __shfl_xor_sync(FULL, q1s, 1);
            q1s += __shfl_xor_sync(FULL, q1s, 2);
            if (qd == 0) {
                atomicAdd(&rsum[mr0], s0);
                atomicAdd(&rsumsq[mr0], q0s);
                atomicAdd(&rsum[mr1], s1);
                atomicAdd(&rsumsq[mr1], q1s);
            }
        }
    }
}

// ---------------------------------------------------------------------------
// fp16 flash-attention (unchanged, 65us).
// ---------------------------------------------------------------------------
#define SPAD 224
#define HP 80
#define QV_B (SPAD * HP)
#define ATHR 416
#define LOG2E 1.4426950408889634f

__global__ void __launch_bounds__(ATHR) attn_flash(
    const __half* __restrict__ img_h, const __half* __restrict__ keff_h,
    const int* __restrict__ mask, const float* __restrict__ sattn,
    __half* __restrict__ ctx_h) {
    extern __shared__ char smw[];
    uint32_t smemU = (uint32_t)__cvta_generic_to_shared(smw);
    uint32_t qvU = smemU;
    uint32_t ksU = smemU + QV_B;
    float* bias_s = reinterpret_cast<float*>(smw + 2 * QV_B);

    int b = blockIdx.x >> 3;
    int h = blockIdx.x & 7;
    int tid = threadIdx.x;
    size_t base = ((size_t)b * Ssz) * Dsz + h * DHsz;

    for (int idx = tid; idx < SPAD * 4; idx += ATHR) {
        int r = idx >> 2, c8 = (idx & 3) * 8;
        uint4 q = make_uint4(0u, 0u, 0u, 0u);
        uint4 k = make_uint4(0u, 0u, 0u, 0u);
        if (r < Ssz) {
            q = *reinterpret_cast<const uint4*>(img_h + base + (size_t)r * Dsz + c8);
            k = *reinterpret_cast<const uint4*>(keff_h + base + (size_t)r * Dsz + c8);
        }
        asm volatile("st.shared.v4.b32 [%0], {%1,%2,%3,%4};"
                     :: "r"(qvU + r * HP + c8 * 2),
                        "r"(q.x), "r"(q.y), "r"(q.z), "r"(q.w));
        asm volatile("st.shared.v4.b32 [%0], {%1,%2,%3,%4};"
                     :: "r"(ksU + r * HP + c8 * 2),
                        "r"(k.x), "r"(k.y), "r"(k.z), "r"(k.w));
    }
    for (int k = tid; k < SPAD; k += ATHR)
        bias_s[k] = (k >= Ssz || mask[b * Ssz + k] == 0) ? -1.4426950e9f : 0.f;
    __syncthreads();

    int w = tid >> 5, lane = tid & 31;
    int grp = lane >> 2;
    int qd = lane & 3;
    const float isq2 = 0.17677669529663687f * LOG2E;
    const unsigned FULL = 0xffffffffu;

    int q0 = w * 16;
    int qr0 = q0 + grp, qr1 = q0 + grp + 8;
    float f0 = (qr0 < Ssz) ? isq2 * sattn[h * Ssz + qr0] : 0.f;
    float f1 = (qr1 < Ssz) ? isq2 * sattn[h * Ssz + qr1] : 0.f;

    uint32_t aq[2][4];
    {
        int rA = (lane & 7) + ((lane >> 3) & 1) * 8;
        uint32_t offA = qvU + (q0 + rA) * HP + ((lane >> 4) & 1) * 16;
        ldsm_x4(aq[0][0], aq[0][1], aq[0][2], aq[0][3], offA);
        ldsm_x4(aq[1][0], aq[1][1], aq[1][2], aq[1][3], offA + 32);
    }

    int rB = (lane & 7) + ((lane >> 4) & 1) * 8;
    int rV = (lane & 7) + ((lane >> 3) & 1) * 8;
    int cB = ((lane >> 3) & 1) * 16;
    int cV = ((lane >> 4) & 1) * 16;

    float m0 = -3.0e38f, m1 = -3.0e38f, l0 = 0.f, l1 = 0.f;
    float co[4][4];
#pragma unroll
    for (int n = 0; n < 4; n++)
#pragma unroll
        for (int e = 0; e < 4; e++) co[n][e] = 0.f;

    for (int it = 0; it < 7; it++) {
        int key0 = it * 32;
        float sA[2][4] = {{0.f, 0.f, 0.f, 0.f}, {0.f, 0.f, 0.f, 0.f}};
        float sB[2][4] = {{0.f, 0.f, 0.f, 0.f}, {0.f, 0.f, 0.f, 0.f}};
        uint32_t offB = ksU + (key0 + rB) * HP + cB;
#pragma unroll
        for (int kk = 0; kk < 2; kk++) {
            uint32_t r0, r1, r2, r3;
            ldsm_x4(r0, r1, r2, r3, offB + kk * 32);
            mma_f16(sA[0], aq[kk], r0, r1);
            mma_f16(sA[1], aq[kk], r2, r3);
            ldsm_x4(r0, r1, r2, r3, offB + 16 * HP + kk * 32);
            mma_f16(sB[0], aq[kk], r0, r1);
            mma_f16(sB[1], aq[kk], r2, r3);
        }
        float vA[2][4], vB[2][4];
        float rm0 = -3.0e38f, rm1 = -3.0e38f;
#pragma unroll
        for (int n = 0; n < 2; n++) {
            float2 bkA = *reinterpret_cast<const float2*>(
                bias_s + key0 + n * 8 + 2 * qd);
            vA[n][0] = fmaf(sA[n][0], f0, bkA.x);
            vA[n][1] = fmaf(sA[n][1], f0, bkA.y);
            vA[n][2] = fmaf(sA[n][2], f1, bkA.x);
            vA[n][3] = fmaf(sA[n][3], f1, bkA.y);
            float2 bkB = *reinterpret_cast<const float2*>(
                bias_s + key0 + 16 + n * 8 + 2 * qd);
            vB[n][0] = fmaf(sB[n][0], f0, bkB.x);
            vB[n][1] = fmaf(sB[n][1], f0, bkB.y);
            vB[n][2] = fmaf(sB[n][2], f1, bkB.x);
            vB[n][3] = fmaf(sB[n][3], f1, bkB.y);
            rm0 = fmaxf(rm0, fmaxf(fmaxf(vA[n][0], vA[n][1]),
                                   fmaxf(vB[n][0], vB[n][1])));
            rm1 = fmaxf(rm1, fmaxf(fmaxf(vA[n][2], vA[n][3]),
                                   fmaxf(vB[n][2], vB[n][3])));
        }
        rm0 = fmaxf(rm0, __shfl_xor_sync(FULL, rm0, 1));
        rm0 = fmaxf(rm0, __shfl_xor_sync(FULL, rm0, 2));
        rm1 = fmaxf(rm1, __shfl_xor_sync(FULL, rm1, 1));
        rm1 = fmaxf(rm1, __shfl_xor_sync(FULL, rm1, 2));
        float nm0 = fmaxf(m0, rm0), nm1 = fmaxf(m1, rm1);
        float al0 = ex2f(m0 - nm0), al1 = ex2f(m1 - nm1);
        m0 = nm0; m1 = nm1;
#pragma unroll
        for (int n = 0; n < 4; n++) {
            co[n][0] *= al0; co[n][1] *= al0;
            co[n][2] *= al1; co[n][3] *= al1;
        }
        float ts0 = 0.f, ts1 = 0.f;
        uint32_t ap[4], ap2[4];
#pragma unroll
        for (int n = 0; n < 2; n++) {
            float e0 = ex2f(vA[n][0] - nm0);
            float e1 = ex2f(vA[n][1] - nm0);
            float e2 = ex2f(vA[n][2] - nm1);
            float e3 = ex2f(vA[n][3] - nm1);
            ts0 += e0 + e1;
            ts1 += e2 + e3;
            ap[2 * n]     = packh2(e0, e1);
            ap[2 * n + 1] = packh2(e2, e3);
            e0 = ex2f(vB[n][0] - nm0);
            e1 = ex2f(vB[n][1] - nm0);
            e2 = ex2f(vB[n][2] - nm1);
            e3 = ex2f(vB[n][3] - nm1);
            ts0 += e0 + e1;
            ts1 += e2 + e3;
            ap2[2 * n]     = packh2(e0, e1);
            ap2[2 * n + 1] = packh2(e2, e3);
        }
        l0 = l0 * al0 + ts0;
        l1 = l1 * al1 + ts1;
        uint32_t offV = qvU + (key0 + rV) * HP + cV;
        {
            uint32_t r0, r1, r2, r3;
            ldsm_x4t(r0, r1, r2, r3, offV);
            mma_f16(co[0], ap, r0, r1);
            mma_f16(co[1], ap, r2, r3);
            ldsm_x4t(r0, r1, r2, r3, offV + 32);
            mma_f16(co[2], ap, r0, r1);
            mma_f16(co[3], ap, r2, r3);
            ldsm_x4t(r0, r1, r2, r3, offV + 16 * HP);
            mma_f16(co[0], ap2, r0, r1);
            mma_f16(co[1], ap2, r2, r3);
            ldsm_x4t(r0, r1, r2, r3, offV + 16 * HP + 32);
            mma_f16(co[2], ap2, r0, r1);
            mma_f16(co[3], ap2, r2, r3);
        }
    }

    l0 += __shfl_xor_sync(FULL, l0, 1);
    l0 += __shfl_xor_sync(FULL, l0, 2);
    l1 += __shfl_xor_sync(FULL, l1, 1);
    l1 += __shfl_xor_sync(FULL, l1, 2);
    float inv0 = 1.f / l0, inv1 = 1.f / l1;
#pragma unroll
    for (int n4 = 0; n4 < 4; n4++) {
        if (qr0 < Ssz) {
            __half2 v = __floats2half2_rn(co[n4][0] * inv0, co[n4][1] * inv0);
            *reinterpret_cast<__half2*>(
                ctx_h + base + (size_t)qr0 * Dsz + n4 * 8 + 2 * qd) = v;
        }
        if (qr1 < Ssz) {
            __half2 v = __floats2half2_rn(co[n4][2] * inv1, co[n4][3] * inv1);
            *reinterpret_cast<__half2*>(
                ctx_h + base + (size_t)qr1 * Dsz + n4 * 8 + 2 * qd) = v;
        }
    }
}

// ---------------------------------------------------------------------------
extern "C" void kernel_launch(void* const* d_in, const int* in_sizes, int n_in,
                              void* d_out, int out_size) {
    const float* hidden_img   = (const float*)d_in[0];
    const float* hidden_title = (const float*)d_in[1];
    const int*   mask         = (const int*)  d_in[2];
    const float* a_img   = (const float*)d_in[3];
    const float* b_img   = (const float*)d_in[4];
    const float* a_title = (const float*)d_in[5];
    const float* b_title = (const float*)d_in[6];
    const float* Wb      = (const float*)d_in[7];
    const float* bb      = (const float*)d_in[8];
    const float* Wo      = (const float*)d_in[9];
    const float* bo      = (const float*)d_in[10];
    const float* sattn   = (const float*)d_in[11];
    const float* a_out   = (const float*)d_in[12];
    const float* b_out   = (const float*)d_in[13];
    const float* W1      = (const float*)d_in[14];
    const float* b1      = (const float*)d_in[15];
    const float* sffn    = (const float*)d_in[16];
    float* out = (float*)d_out;

    float *rsum, *rsumsq;
    __half *h1_h, *img_h, *title_h, *keff_h, *ctx_h, *Wb_h, *Wo_h, *W1_h;
    cudaGetSymbolAddress((void**)&rsum,    g_rsum);
    cudaGetSymbolAddress((void**)&rsumsq,  g_rsumsq);
    cudaGetSymbolAddress((void**)&h1_h,    g_h1_h);
    cudaGetSymbolAddress((void**)&img_h,   g_img_h);
    cudaGetSymbolAddress((void**)&title_h, g_title_h);
    cudaGetSymbolAddress((void**)&keff_h,  g_keff_h);
    cudaGetSymbolAddress((void**)&ctx_h,   g_ctx_h);
    cudaGetSymbolAddress((void**)&Wb_h,    g_Wb_h);
    cudaGetSymbolAddress((void**)&Wo_h,    g_Wo_h);
    cudaGetSymbolAddress((void**)&W1_h,    g_W1_h);

    const int LNB = BS / 8;
    const int gemm_smem = 2 * STAGE_B;   // 73728 B
    cudaFuncSetAttribute((const void*)gemm_f16<0, false, true, true>,
                         cudaFuncAttributeMaxDynamicSharedMemorySize, gemm_smem);
    cudaFuncSetAttribute((const void*)gemm_f16<0, true, false, true>,
                         cudaFuncAttributeMaxDynamicSharedMemorySize, gemm_smem);
    cudaFuncSetAttribute((const void*)gemm_f16<2, false, true, false>,
                         cudaFuncAttributeMaxDynamicSharedMemorySize, gemm_smem);

    // 1) LayerNorms (both streams) + weights->half + stats zero, one launch
    ln_w2h<<<2 * LNB + 484, 256>>>(
        hidden_img, a_img, b_img, img_h,
        hidden_title, a_title, b_title, title_h, LNB,
        Wb, Wo, W1, Wb_h, Wo_h, W1_h, rsum, rsumsq);

    // 2) keff(half) = title_n @ Wb^T + bb + img_n(half)
    dim3 gg(Dsz / GBN, BS / GBM);
    gemm_f16<0, false, true, true><<<gg, 256, gemm_smem>>>(
        title_h, Wb_h, bb, img_h, nullptr, keff_h, nullptr, nullptr,
        nullptr, nullptr);

    // 3) fp16 flash attention -> ctx half
    const int attn_smem = 2 * QV_B + SPAD * 4;
    cudaFuncSetAttribute(attn_flash,
                         cudaFuncAttributeMaxDynamicSharedMemorySize, attn_smem);
    attn_flash<<<Bsz * Hsz, ATHR, attn_smem>>>(img_h, keff_h, mask, sattn, ctx_h);

    // 4) h1(half) = ctx @ Wo^T + bo + hidden_img  (+ row stats)
    gemm_f16<0, true, false, true><<<gg, 256, gemm_smem>>>(
        ctx_h, Wo_h, bo, hidden_img, nullptr, h1_h, nullptr, nullptr,
        rsum, rsumsq);

    // 5) out = h1 + gelu_tanh(scale_ffn * (LN(h1) @ W1^T + b1))
    gemm_f16<2, false, true, false><<<gg, 256, gemm_smem>>>(
        h1_h, W1_h, b1, h1_h, sffn, out, a_out, b_out, rsum, rsumsq);
}

// round 16
// speedup vs baseline: 4.9190x; 1.0291x over previous
#include <cuda_runtime.h>
#include <cuda_fp16.h>
#include <math.h>
#include <stdint.h>

#define Bsz 256
#define Ssz 200
#define Dsz 256
#define Hsz 8
#define DHsz 32
#define BS (Bsz * Ssz)   // 51200 rows

__device__ float g_rsum[BS];
__device__ float g_rsumsq[BS];
__device__ __half g_h1_h[BS * Dsz];
__device__ __half g_img_h[BS * Dsz];
__device__ __half g_title_h[BS * Dsz];
__device__ __half g_keff_h[BS * Dsz];
__device__ __half g_ctx_h[BS * Dsz];
__device__ __half g_Wb_h[Dsz * Dsz];
__device__ __half g_Wo_h[Dsz * Dsz];
__device__ __half g_W1_h[Dsz * Dsz];

__device__ __forceinline__ void mma_f16(float* c, const uint32_t* a,
                                        uint32_t b0, uint32_t b1) {
    asm volatile(
        "mma.sync.aligned.m16n8k16.row.col.f32.f16.f16.f32 "
        "{%0,%1,%2,%3}, {%4,%5,%6,%7}, {%8,%9}, {%0,%1,%2,%3};"
        : "+f"(c[0]), "+f"(c[1]), "+f"(c[2]), "+f"(c[3])
        : "r"(a[0]), "r"(a[1]), "r"(a[2]), "r"(a[3]), "r"(b0), "r"(b1));
}

__device__ __forceinline__ void ldsm_x4(uint32_t& r0, uint32_t& r1,
                                        uint32_t& r2, uint32_t& r3,
                                        uint32_t addr) {
    asm volatile(
        "ldmatrix.sync.aligned.m8n8.x4.shared.b16 {%0,%1,%2,%3}, [%4];"
        : "=r"(r0), "=r"(r1), "=r"(r2), "=r"(r3) : "r"(addr));
}

__device__ __forceinline__ void ldsm_x4t(uint32_t& r0, uint32_t& r1,
                                         uint32_t& r2, uint32_t& r3,
                                         uint32_t addr) {
    asm volatile(
        "ldmatrix.sync.aligned.m8n8.x4.trans.shared.b16 {%0,%1,%2,%3}, [%4];"
        : "=r"(r0), "=r"(r1), "=r"(r2), "=r"(r3) : "r"(addr));
}

__device__ __forceinline__ void cp_async16(uint32_t smem, const void* g) {
    asm volatile("cp.async.cg.shared.global [%0], [%1], 16;"
                 :: "r"(smem), "l"(g));
}

__device__ __forceinline__ uint32_t packh2(float a, float b) {
    __half2 h = __floats2half2_rn(a, b);
    return *reinterpret_cast<uint32_t*>(&h);
}

__device__ __forceinline__ float ex2f(float x) {
    float r;
    asm("ex2.approx.f32 %0, %1;" : "=f"(r) : "f"(x));
    return r;
}

// ---------------------------------------------------------------------------
// Fused: LayerNorm both streams -> half, then weights->half + stats zero.
// ---------------------------------------------------------------------------
__global__ void __launch_bounds__(256) ln_w2h(
    const float* __restrict__ x0, const float* __restrict__ ga0,
    const float* __restrict__ gb0, __half* __restrict__ y0,
    const float* __restrict__ x1, const float* __restrict__ ga1,
    const float* __restrict__ gb1, __half* __restrict__ y1, int split,
    const float* __restrict__ w0, const float* __restrict__ w1,
    const float* __restrict__ w2, __half* __restrict__ h0,
    __half* __restrict__ h1, __half* __restrict__ h2,
    float* __restrict__ rsum, float* __restrict__ rsumsq) {
    int blk = blockIdx.x;
    if (blk >= 2 * split) {
        int i = (blk - 2 * split) * 256 + threadIdx.x;
        if (i < 98304) {
            const float2* s;
            __half2* d;
            int j;
            if (i < 32768)      { s = (const float2*)w0; d = (__half2*)h0; j = i; }
            else if (i < 65536) { s = (const float2*)w1; d = (__half2*)h1; j = i - 32768; }
            else                { s = (const float2*)w2; d = (__half2*)h2; j = i - 65536; }
            float2 v = s[j];
            d[j] = __floats2half2_rn(v.x, v.y);
        } else {
            int j = i - 98304;
            float4 z = make_float4(0.f, 0.f, 0.f, 0.f);
            if (j < 12800) reinterpret_cast<float4*>(rsum)[j] = z;
            else           reinterpret_cast<float4*>(rsumsq)[j - 12800] = z;
        }
        return;
    }
    const float *x, *ga, *gb;
    __half* y;
    int rowbase;
    if (blk < split) { x = x0; ga = ga0; gb = gb0; y = y0; rowbase = blk * 8; }
    else { x = x1; ga = ga1; gb = gb1; y = y1; rowbase = (blk - split) * 8; }
    int w = threadIdx.x >> 5, lane = threadIdx.x & 31;
    size_t row = rowbase + w;
    const float4* x4 = reinterpret_cast<const float4*>(x + row * Dsz);
    float4 v0 = x4[lane];
    float4 v1 = x4[lane + 32];

    float s = v0.x + v0.y + v0.z + v0.w + v1.x + v1.y + v1.z + v1.w;
#pragma unroll
    for (int o = 16; o; o >>= 1) s += __shfl_xor_sync(0xffffffffu, s, o);
    float mean = s * (1.0f / Dsz);

    float d0x = v0.x - mean, d0y = v0.y - mean, d0z = v0.z - mean, d0w = v0.w - mean;
    float d1x = v1.x - mean, d1y = v1.y - mean, d1z = v1.z - mean, d1w = v1.w - mean;
    float ss = d0x * d0x + d0y * d0y + d0z * d0z + d0w * d0w +
               d1x * d1x + d1y * d1y + d1z * d1z + d1w * d1w;
#pragma unroll
    for (int o = 16; o; o >>= 1) ss += __shfl_xor_sync(0xffffffffu, ss, o);
    float var = ss * (1.0f / (Dsz - 1));
    float inv = 1.0f / (sqrtf(var) + 1e-6f);

    const float4* ga4 = reinterpret_cast<const float4*>(ga);
    const float4* gb4 = reinterpret_cast<const float4*>(gb);
    float4 g0 = ga4[lane], g1 = ga4[lane + 32];
    float4 b0 = gb4[lane], b1 = gb4[lane + 32];
    float4 o0 = make_float4(g0.x * d0x * inv + b0.x, g0.y * d0y * inv + b0.y,
                            g0.z * d0z * inv + b0.z, g0.w * d0w * inv + b0.w);
    float4 o1 = make_float4(g1.x * d1x * inv + b1.x, g1.y * d1y * inv + b1.y,
                            g1.z * d1z * inv + b1.z, g1.w * d1w * inv + b1.w);
    uint2* y2 = reinterpret_cast<uint2*>(y + row * Dsz);
    y2[lane] = make_uint2(packh2(o0.x, o0.y), packh2(o0.z, o0.w));
    y2[lane + 32] = make_uint2(packh2(o1.x, o1.y), packh2(o1.z, o1.w));
}

// ---------------------------------------------------------------------------
// fp16 GEMM (fp32 accum). Block 128x128, BK=32 (8 stages), 256 thr, 8 warps.
// __launch_bounds__(256,2): regs<=128 -> 2 CTAs/SM. Single-sync pipeline:
// wait(s) -> sync -> issue copies(s+1) -> mma(s).
// EPI==0: out = acc + bias + add (ADDH/OUTH/STATS).
// EPI==2: A half, LN at staging; A(s+1) transform after mma(s).
// ---------------------------------------------------------------------------
#define GBM 128
#define GBN 128
#define GBK 32
#define HPITCH 80
#define TILE_B (128 * HPITCH)        // 10240
#define STAGE_B (2 * TILE_B)         // 20480

template <int EPI, bool STATS, bool ADDH, bool OUTH>
__global__ void __launch_bounds__(256, 2) gemm_f16(
    const void* __restrict__ Aptr, const __half* __restrict__ W,
    const float* __restrict__ bias, const void* __restrict__ addp,
    const float* __restrict__ sffn, void* __restrict__ outp,
    const float* __restrict__ lga, const float* __restrict__ lgb,
    float* __restrict__ rsum, float* __restrict__ rsumsq) {
    extern __shared__ char gsm[];
    uint32_t smemU = (uint32_t)__cvta_generic_to_shared(gsm);

    int m0 = blockIdx.y * GBM;
    int n0 = blockIdx.x * GBN;
    int tid = threadIdx.x;
    int wid = tid >> 5, lane = tid & 31;
    int wm = wid >> 1, wn = wid & 1;
    int grp = lane >> 2, qd = lane & 3;

    int rA = (lane & 7) + ((lane >> 3) & 1) * 8;
    int offA = (wm * 32 + rA) * HPITCH + ((lane >> 4) & 1) * 16;
    int rB = (lane & 7) + ((lane >> 4) & 1) * 8;
    int offB = (wn * 64 + rB) * HPITCH + ((lane >> 3) & 1) * 16;

    float mean_t[4], inv_t[4];
    int lr = tid >> 3;              // 0..31 (EPI2 staging rows)
    int c4f = (tid & 7) * 4;        // 0..28 (half cols, chunk of 4)
    if (EPI == 2) {
#pragma unroll
        for (int t = 0; t < 4; t++) {
            int r = m0 + lr + 32 * t;
            float s = rsum[r], sq = rsumsq[r];
            float mn = s * (1.0f / Dsz);
            float var = (sq - (float)Dsz * mn * mn) * (1.0f / (Dsz - 1));
            mean_t[t] = mn;
            inv_t[t] = 1.0f / (sqrtf(var) + 1e-6f);
        }
    }

    float acc[2][8][4];
#pragma unroll
    for (int i = 0; i < 2; i++)
#pragma unroll
        for (int n = 0; n < 8; n++)
#pragma unroll
            for (int e = 0; e < 4; e++) acc[i][n][e] = 0.f;

    const __half* Ah = (const __half*)Aptr;
    int crow = tid >> 2, cu = tid & 3;   // 64 rows x 4 16B-chunks

    auto stageW = [&](int buf, int k0) {
        uint32_t sb = smemU + buf * STAGE_B + TILE_B;
        cp_async16(sb + crow * HPITCH + cu * 16,
                   W + (size_t)(n0 + crow) * Dsz + k0 + cu * 8);
        cp_async16(sb + (crow + 64) * HPITCH + cu * 16,
                   W + (size_t)(n0 + crow + 64) * Dsz + k0 + cu * 8);
    };
    auto stageA = [&](int buf, int k0) {
        uint32_t sa = smemU + buf * STAGE_B;
        cp_async16(sa + crow * HPITCH + cu * 16,
                   Ah + (size_t)(m0 + crow) * Dsz + k0 + cu * 8);
        cp_async16(sa + (crow + 64) * HPITCH + cu * 16,
                   Ah + (size_t)(m0 + crow + 64) * Dsz + k0 + cu * 8);
    };
    auto transA = [&](int buf, int k0, const uint2* pa) {
        float4 g4 = *reinterpret_cast<const float4*>(lga + k0 + c4f);
        float4 b4 = *reinterpret_cast<const float4*>(lgb + k0 + c4f);
        uint32_t sa = smemU + buf * STAGE_B;
#pragma unroll
        for (int t = 0; t < 4; t++) {
            int r = lr + 32 * t;
            float2 p0 = __half22float2(*reinterpret_cast<const __half2*>(&pa[t].x));
            float2 p1 = __half22float2(*reinterpret_cast<const __half2*>(&pa[t].y));
            float mt = mean_t[t], it = inv_t[t];
            float v0 = (p0.x - mt) * it * g4.x + b4.x;
            float v1 = (p0.y - mt) * it * g4.y + b4.y;
            float v2 = (p1.x - mt) * it * g4.z + b4.z;
            float v3 = (p1.y - mt) * it * g4.w + b4.w;
            asm volatile("st.shared.v2.b32 [%0], {%1,%2};"
                         :: "r"(sa + r * HPITCH + c4f * 2),
                            "r"(packh2(v0, v1)), "r"(packh2(v2, v3)));
        }
    };

    const int NSTEP = Dsz / GBK;  // 8
    uint2 pa[4];

    if (EPI == 2) {
#pragma unroll
        for (int t = 0; t < 4; t++)
            pa[t] = *reinterpret_cast<const uint2*>(
                Ah + (size_t)(m0 + lr + 32 * t) * Dsz + c4f);
        stageW(0, 0);
        asm volatile("cp.async.commit_group;");
        transA(0, 0, pa);
    } else {
        stageA(0, 0);
        stageW(0, 0);
        asm volatile("cp.async.commit_group;");
    }

    for (int s = 0; s < NSTEP; s++) {
        if (EPI == 2 && s + 1 < NSTEP) {
#pragma unroll
            for (int t = 0; t < 4; t++)
                pa[t] = *reinterpret_cast<const uint2*>(
                    Ah + (size_t)(m0 + lr + 32 * t) * Dsz + (s + 1) * GBK + c4f);
        }
        asm volatile("cp.async.wait_group 0;");
        __syncthreads();
        if (s + 1 < NSTEP) {
            if (EPI != 2) stageA((s + 1) & 1, (s + 1) * GBK);
            stageW((s + 1) & 1, (s + 1) * GBK);
            asm volatile("cp.async.commit_group;");
        }

        uint32_t aB = smemU + (s & 1) * STAGE_B + offA;
        uint32_t bB = smemU + (s & 1) * STAGE_B + TILE_B + offB;
#pragma unroll
        for (int kb = 0; kb < 2; kb++) {
            uint32_t af[2][4];
#pragma unroll
            for (int i = 0; i < 2; i++)
                ldsm_x4(af[i][0], af[i][1], af[i][2], af[i][3],
                        aB + i * 16 * HPITCH + kb * 32);
            uint32_t bf[8][2];
#pragma unroll
            for (int p = 0; p < 4; p++) {
                uint32_t r0, r1, r2, r3;
                ldsm_x4(r0, r1, r2, r3, bB + p * 16 * HPITCH + kb * 32);
                bf[2 * p][0] = r0; bf[2 * p][1] = r1;
                bf[2 * p + 1][0] = r2; bf[2 * p + 1][1] = r3;
            }
#pragma unroll
            for (int i = 0; i < 2; i++)
#pragma unroll
                for (int n = 0; n < 8; n++)
                    mma_f16(acc[i][n], af[i], bf[n][0], bf[n][1]);
        }
        if (EPI == 2 && s + 1 < NSTEP)
            transA((s + 1) & 1, (s + 1) * GBK, pa);
    }

    const float* addf = (const float*)addp;
    const __half* addh = (const __half*)addp;
    float* outf = (float*)outp;
    __half* outh = (__half*)outp;

#pragma unroll
    for (int i = 0; i < 2; i++) {
        int mr0 = m0 + wm * 32 + i * 16 + grp;
        int mr1 = mr0 + 8;
        float sf0 = 0.f, sf1 = 0.f;
        if (EPI == 2) {
            sf0 = sffn[mr0 % Ssz];
            sf1 = sffn[mr1 % Ssz];
        }
        float s0 = 0.f, q0s = 0.f, s1 = 0.f, q1s = 0.f;
#pragma unroll
        for (int n = 0; n < 8; n++) {
            int col = n0 + wn * 64 + n * 8 + 2 * qd;
            float2 bv = *reinterpret_cast<const float2*>(bias + col);
            float2 a0, a1;
            if (ADDH) {
                __half2 h0 = *reinterpret_cast<const __half2*>(
                    addh + (size_t)mr0 * Dsz + col);
                __half2 h1v = *reinterpret_cast<const __half2*>(
                    addh + (size_t)mr1 * Dsz + col);
                a0 = __half22float2(h0);
                a1 = __half22float2(h1v);
            } else {
                a0 = *reinterpret_cast<const float2*>(
                    addf + (size_t)mr0 * Dsz + col);
                a1 = *reinterpret_cast<const float2*>(
                    addf + (size_t)mr1 * Dsz + col);
            }
            float r00 = acc[i][n][0] + bv.x, r01 = acc[i][n][1] + bv.y;
            float r10 = acc[i][n][2] + bv.x, r11 = acc[i][n][3] + bv.y;
            if (EPI == 0) {
                r00 += a0.x; r01 += a0.y; r10 += a1.x; r11 += a1.y;
                if (STATS) {
                    s0 += r00 + r01; q0s += r00 * r00 + r01 * r01;
                    s1 += r10 + r11; q1s += r10 * r10 + r11 * r11;
                }
            } else {
                float z, th;
                z = sf0 * r00;
                th = tanhf(0.79788456080286536f * (z + 0.044715f * z * z * z));
                r00 = a0.x + 0.5f * z * (1.0f + th);
                z = sf0 * r01;
                th = tanhf(0.79788456080286536f * (z + 0.044715f * z * z * z));
                r01 = a0.y + 0.5f * z * (1.0f + th);
                z = sf1 * r10;
                th = tanhf(0.79788456080286536f * (z + 0.044715f * z * z * z));
                r10 = a1.x + 0.5f * z * (1.0f + th);
                z = sf1 * r11;
                th = tanhf(0.79788456080286536f * (z + 0.044715f * z * z * z));
                r11 = a1.y + 0.5f * z * (1.0f + th);
            }
            if (OUTH) {
                *reinterpret_cast<uint32_t*>(outh + (size_t)mr0 * Dsz + col) =
                    packh2(r00, r01);
                *reinterpret_cast<uint32_t*>(outh + (size_t)mr1 * Dsz + col) =
                    packh2(r10, r11);
            } else {
                *reinterpret_cast<float2*>(outf + (size_t)mr0 * Dsz + col) =
                    make_float2(r00, r01);
                *reinterpret_cast<float2*>(outf + (size_t)mr1 * Dsz + col) =
                    make_float2(r10, r11);
            }
        }
        if (STATS) {
            const unsigned FULL = 0xffffffffu;
            s0 += __shfl_xor_sync(FULL, s0, 1);
            s0 += __shfl_xor_sync(FULL, s0, 2);
            q0s += __shfl_xor_sync(FULL, q0s, 1);
            q0s += __shfl_xor_sync(FULL, q0s, 2);
            s1 += __shfl_xor_sync(FULL, s1, 1);
            s1 += __shfl_xor_sync(FULL, s1, 2);
            q1s += __shfl_xor_sync(FULL, q1s, 1);
            q1s += __shfl_xor_sync(FULL, q1s, 2);
            if (qd == 0) {
                atomicAdd(&rsum[mr0], s0);
                atomicAdd(&rsumsq[mr0], q0s);
                atomicAdd(&rsum[mr1], s1);
                atomicAdd(&rsumsq[mr1], q1s);
            }
        }
    }
}

// ---------------------------------------------------------------------------
// fp16 flash-attention (unchanged, 65us).
// ---------------------------------------------------------------------------
#define SPAD 224
#define HP 80
#define QV_B (SPAD * HP)
#define ATHR 416
#define LOG2E 1.4426950408889634f

__global__ void __launch_bounds__(ATHR) attn_flash(
    const __half* __restrict__ img_h, const __half* __restrict__ keff_h,
    const int* __restrict__ mask, const float* __restrict__ sattn,
    __half* __restrict__ ctx_h) {
    extern __shared__ char smw[];
    uint32_t smemU = (uint32_t)__cvta_generic_to_shared(smw);
    uint32_t qvU = smemU;
    uint32_t ksU = smemU + QV_B;
    float* bias_s = reinterpret_cast<float*>(smw + 2 * QV_B);

    int b = blockIdx.x >> 3;
    int h = blockIdx.x & 7;
    int tid = threadIdx.x;
    size_t base = ((size_t)b * Ssz) * Dsz + h * DHsz;

    for (int idx = tid; idx < SPAD * 4; idx += ATHR) {
        int r = idx >> 2, c8 = (idx & 3) * 8;
        uint4 q = make_uint4(0u, 0u, 0u, 0u);
        uint4 k = make_uint4(0u, 0u, 0u, 0u);
        if (r < Ssz) {
            q = *reinterpret_cast<const uint4*>(img_h + base + (size_t)r * Dsz + c8);
            k = *reinterpret_cast<const uint4*>(keff_h + base + (size_t)r * Dsz + c8);
        }
        asm volatile("st.shared.v4.b32 [%0], {%1,%2,%3,%4};"
                     :: "r"(qvU + r * HP + c8 * 2),
                        "r"(q.x), "r"(q.y), "r"(q.z), "r"(q.w));
        asm volatile("st.shared.v4.b32 [%0], {%1,%2,%3,%4};"
                     :: "r"(ksU + r * HP + c8 * 2),
                        "r"(k.x), "r"(k.y), "r"(k.z), "r"(k.w));
    }
    for (int k = tid; k < SPAD; k += ATHR)
        bias_s[k] = (k >= Ssz || mask[b * Ssz + k] == 0) ? -1.4426950e9f : 0.f;
    __syncthreads();

    int w = tid >> 5, lane = tid & 31;
    int grp = lane >> 2;
    int qd = lane & 3;
    const float isq2 = 0.17677669529663687f * LOG2E;
    const unsigned FULL = 0xffffffffu;

    int q0 = w * 16;
    int qr0 = q0 + grp, qr1 = q0 + grp + 8;
    float f0 = (qr0 < Ssz) ? isq2 * sattn[h * Ssz + qr0] : 0.f;
    float f1 = (qr1 < Ssz) ? isq2 * sattn[h * Ssz + qr1] : 0.f;

    uint32_t aq[2][4];
    {
        int rA = (lane & 7) + ((lane >> 3) & 1) * 8;
        uint32_t offA = qvU + (q0 + rA) * HP + ((lane >> 4) & 1) * 16;
        ldsm_x4(aq[0][0], aq[0][1], aq[0][2], aq[0][3], offA);
        ldsm_x4(aq[1][0], aq[1][1], aq[1][2], aq[1][3], offA + 32);
    }

    int rB = (lane & 7) + ((lane >> 4) & 1) * 8;
    int rV = (lane & 7) + ((lane >> 3) & 1) * 8;
    int cB = ((lane >> 3) & 1) * 16;
    int cV = ((lane >> 4) & 1) * 16;

    float m0 = -3.0e38f, m1 = -3.0e38f, l0 = 0.f, l1 = 0.f;
    float co[4][4];
#pragma unroll
    for (int n = 0; n < 4; n++)
#pragma unroll
        for (int e = 0; e < 4; e++) co[n][e] = 0.f;

    for (int it = 0; it < 7; it++) {
        int key0 = it * 32;
        float sA[2][4] = {{0.f, 0.f, 0.f, 0.f}, {0.f, 0.f, 0.f, 0.f}};
        float sB[2][4] = {{0.f, 0.f, 0.f, 0.f}, {0.f, 0.f, 0.f, 0.f}};
        uint32_t offB = ksU + (key0 + rB) * HP + cB;
#pragma unroll
        for (int kk = 0; kk < 2; kk++) {
            uint32_t r0, r1, r2, r3;
            ldsm_x4(r0, r1, r2, r3, offB + kk * 32);
            mma_f16(sA[0], aq[kk], r0, r1);
            mma_f16(sA[1], aq[kk], r2, r3);
            ldsm_x4(r0, r1, r2, r3, offB + 16 * HP + kk * 32);
            mma_f16(sB[0], aq[kk], r0, r1);
            mma_f16(sB[1], aq[kk], r2, r3);
        }
        float vA[2][4], vB[2][4];
        float rm0 = -3.0e38f, rm1 = -3.0e38f;
#pragma unroll
        for (int n = 0; n < 2; n++) {
            float2 bkA = *reinterpret_cast<const float2*>(
                bias_s + key0 + n * 8 + 2 * qd);
            vA[n][0] = fmaf(sA[n][0], f0, bkA.x);
            vA[n][1] = fmaf(sA[n][1], f0, bkA.y);
            vA[n][2] = fmaf(sA[n][2], f1, bkA.x);
            vA[n][3] = fmaf(sA[n][3], f1, bkA.y);
            float2 bkB = *reinterpret_cast<const float2*>(
                bias_s + key0 + 16 + n * 8 + 2 * qd);
            vB[n][0] = fmaf(sB[n][0], f0, bkB.x);
            vB[n][1] = fmaf(sB[n][1], f0, bkB.y);
            vB[n][2] = fmaf(sB[n][2], f1, bkB.x);
            vB[n][3] = fmaf(sB[n][3], f1, bkB.y);
            rm0 = fmaxf(rm0, fmaxf(fmaxf(vA[n][0], vA[n][1]),
                                   fmaxf(vB[n][0], vB[n][1])));
            rm1 = fmaxf(rm1, fmaxf(fmaxf(vA[n][2], vA[n][3]),
                                   fmaxf(vB[n][2], vB[n][3])));
        }
        rm0 = fmaxf(rm0, __shfl_xor_sync(FULL, rm0, 1));
        rm0 = fmaxf(rm0, __shfl_xor_sync(FULL, rm0, 2));
        rm1 = fmaxf(rm1, __shfl_xor_sync(FULL, rm1, 1));
        rm1 = fmaxf(rm1, __shfl_xor_sync(FULL, rm1, 2));
        float nm0 = fmaxf(m0, rm0), nm1 = fmaxf(m1, rm1);
        float al0 = ex2f(m0 - nm0), al1 = ex2f(m1 - nm1);
        m0 = nm0; m1 = nm1;
#pragma unroll
        for (int n = 0; n < 4; n++) {
            co[n][0] *= al0; co[n][1] *= al0;
            co[n][2] *= al1; co[n][3] *= al1;
        }
        float ts0 = 0.f, ts1 = 0.f;
        uint32_t ap[4], ap2[4];
#pragma unroll
        for (int n = 0; n < 2; n++) {
            float e0 = ex2f(vA[n][0] - nm0);
            float e1 = ex2f(vA[n][1] - nm0);
            float e2 = ex2f(vA[n][2] - nm1);
            float e3 = ex2f(vA[n][3] - nm1);
            ts0 += e0 + e1;
            ts1 += e2 + e3;
            ap[2 * n]     = packh2(e0, e1);
            ap[2 * n + 1] = packh2(e2, e3);
            e0 = ex2f(vB[n][0] - nm0);
            e1 = ex2f(vB[n][1] - nm0);
            e2 = ex2f(vB[n][2] - nm1);
            e3 = ex2f(vB[n][3] - nm1);
            ts0 += e0 + e1;
            ts1 += e2 + e3;
            ap2[2 * n]     = packh2(e0, e1);
            ap2[2 * n + 1] = packh2(e2, e3);
        }
        l0 = l0 * al0 + ts0;
        l1 = l1 * al1 + ts1;
        uint32_t offV = qvU + (key0 + rV) * HP + cV;
        {
            uint32_t r0, r1, r2, r3;
            ldsm_x4t(r0, r1, r2, r3, offV);
            mma_f16(co[0], ap, r0, r1);
            mma_f16(co[1], ap, r2, r3);
            ldsm_x4t(r0, r1, r2, r3, offV + 32);
            mma_f16(co[2], ap, r0, r1);
            mma_f16(co[3], ap, r2, r3);
            ldsm_x4t(r0, r1, r2, r3, offV + 16 * HP);
            mma_f16(co[0], ap2, r0, r1);
            mma_f16(co[1], ap2, r2, r3);
            ldsm_x4t(r0, r1, r2, r3, offV + 16 * HP + 32);
            mma_f16(co[2], ap2, r0, r1);
            mma_f16(co[3], ap2, r2, r3);
        }
    }

    l0 += __shfl_xor_sync(FULL, l0, 1);
    l0 += __shfl_xor_sync(FULL, l0, 2);
    l1 += __shfl_xor_sync(FULL, l1, 1);
    l1 += __shfl_xor_sync(FULL, l1, 2);
    float inv0 = 1.f / l0, inv1 = 1.f / l1;
#pragma unroll
    for (int n4 = 0; n4 < 4; n4++) {
        if (qr0 < Ssz) {
            __half2 v = __floats2half2_rn(co[n4][0] * inv0, co[n4][1] * inv0);
            *reinterpret_cast<__half2*>(
                ctx_h + base + (size_t)qr0 * Dsz + n4 * 8 + 2 * qd) = v;
        }
        if (qr1 < Ssz) {
            __half2 v = __floats2half2_rn(co[n4][2] * inv1, co[n4][3] * inv1);
            *reinterpret_cast<__half2*>(
                ctx_h + base + (size_t)qr1 * Dsz + n4 * 8 + 2 * qd) = v;
        }
    }
}

// ---------------------------------------------------------------------------
extern "C" void kernel_launch(void* const* d_in, const int* in_sizes, int n_in,
                              void* d_out, int out_size) {
    const float* hidden_img   = (const float*)d_in[0];
    const float* hidden_title = (const float*)d_in[1];
    const int*   mask         = (const int*)  d_in[2];
    const float* a_img   = (const float*)d_in[3];
    const float* b_img   = (const float*)d_in[4];
    const float* a_title = (const float*)d_in[5];
    const float* b_title = (const float*)d_in[6];
    const float* Wb      = (const float*)d_in[7];
    const float* bb      = (const float*)d_in[8];
    const float* Wo      = (const float*)d_in[9];
    const float* bo      = (const float*)d_in[10];
    const float* sattn   = (const float*)d_in[11];
    const float* a_out   = (const float*)d_in[12];
    const float* b_out   = (const float*)d_in[13];
    const float* W1      = (const float*)d_in[14];
    const float* b1      = (const float*)d_in[15];
    const float* sffn    = (const float*)d_in[16];
    float* out = (float*)d_out;

    float *rsum, *rsumsq;
    __half *h1_h, *img_h, *title_h, *keff_h, *ctx_h, *Wb_h, *Wo_h, *W1_h;
    cudaGetSymbolAddress((void**)&rsum,    g_rsum);
    cudaGetSymbolAddress((void**)&rsumsq,  g_rsumsq);
    cudaGetSymbolAddress((void**)&h1_h,    g_h1_h);
    cudaGetSymbolAddress((void**)&img_h,   g_img_h);
    cudaGetSymbolAddress((void**)&title_h, g_title_h);
    cudaGetSymbolAddress((void**)&keff_h,  g_keff_h);
    cudaGetSymbolAddress((void**)&ctx_h,   g_ctx_h);
    cudaGetSymbolAddress((void**)&Wb_h,    g_Wb_h);
    cudaGetSymbolAddress((void**)&Wo_h,    g_Wo_h);
    cudaGetSymbolAddress((void**)&W1_h,    g_W1_h);

    const int LNB = BS / 8;
    const int gemm_smem = 2 * STAGE_B;   // 40960 B
    cudaFuncSetAttribute((const void*)gemm_f16<0, false, true, true>,
                         cudaFuncAttributeMaxDynamicSharedMemorySize, gemm_smem);
    cudaFuncSetAttribute((const void*)gemm_f16<0, true, false, true>,
                         cudaFuncAttributeMaxDynamicSharedMemorySize, gemm_smem);
    cudaFuncSetAttribute((const void*)gemm_f16<2, false, true, false>,
                         cudaFuncAttributeMaxDynamicSharedMemorySize, gemm_smem);

    // 1) LayerNorms + weights->half + stats zero, one launch
    ln_w2h<<<2 * LNB + 484, 256>>>(
        hidden_img, a_img, b_img, img_h,
        hidden_title, a_title, b_title, title_h, LNB,
        Wb, Wo, W1, Wb_h, Wo_h, W1_h, rsum, rsumsq);

    // 2) keff(half) = title_n @ Wb^T + bb + img_n(half)
    dim3 gg(Dsz / GBN, BS / GBM);
    gemm_f16<0, false, true, true><<<gg, 256, gemm_smem>>>(
        title_h, Wb_h, bb, img_h, nullptr, keff_h, nullptr, nullptr,
        nullptr, nullptr);

    // 3) fp16 flash attention -> ctx half
    const int attn_smem = 2 * QV_B + SPAD * 4;
    cudaFuncSetAttribute(attn_flash,
                         cudaFuncAttributeMaxDynamicSharedMemorySize, attn_smem);
    attn_flash<<<Bsz * Hsz, ATHR, attn_smem>>>(img_h, keff_h, mask, sattn, ctx_h);

    // 4) h1(half) = ctx @ Wo^T + bo + hidden_img  (+ row stats)
    gemm_f16<0, true, false, true><<<gg, 256, gemm_smem>>>(
        ctx_h, Wo_h, bo, hidden_img, nullptr, h1_h, nullptr, nullptr,
        rsum, rsumsq);

    // 5) out = h1 + gelu_tanh(scale_ffn * (LN(h1) @ W1^T + b1))
    gemm_f16<2, false, true, false><<<gg, 256, gemm_smem>>>(
        h1_h, W1_h, b1, h1_h, sffn, out, a_out, b_out, rsum, rsumsq);
}

// round 17
// speedup vs baseline: 5.0113x; 1.0188x over previous
#include <cuda_runtime.h>
#include <cuda_fp16.h>
#include <math.h>
#include <stdint.h>

#define Bsz 256
#define Ssz 200
#define Dsz 256
#define Hsz 8
#define DHsz 32
#define BS (Bsz * Ssz)   // 51200 rows

__device__ float g_rsum[BS];
__device__ float g_rsumsq[BS];
__device__ __half g_h1_h[BS * Dsz];
__device__ __half g_img_h[BS * Dsz];
__device__ __half g_title_h[BS * Dsz];
__device__ __half g_keff_h[BS * Dsz];
__device__ __half g_ctx_h[BS * Dsz];
__device__ __half g_Wb_h[Dsz * Dsz];
__device__ __half g_Wo_h[Dsz * Dsz];
__device__ __half g_W1_h[Dsz * Dsz];

__device__ __forceinline__ void mma_f16(float* c, const uint32_t* a,
                                        uint32_t b0, uint32_t b1) {
    asm volatile(
        "mma.sync.aligned.m16n8k16.row.col.f32.f16.f16.f32 "
        "{%0,%1,%2,%3}, {%4,%5,%6,%7}, {%8,%9}, {%0,%1,%2,%3};"
        : "+f"(c[0]), "+f"(c[1]), "+f"(c[2]), "+f"(c[3])
        : "r"(a[0]), "r"(a[1]), "r"(a[2]), "r"(a[3]), "r"(b0), "r"(b1));
}

__device__ __forceinline__ void ldsm_x4(uint32_t& r0, uint32_t& r1,
                                        uint32_t& r2, uint32_t& r3,
                                        uint32_t addr) {
    asm volatile(
        "ldmatrix.sync.aligned.m8n8.x4.shared.b16 {%0,%1,%2,%3}, [%4];"
        : "=r"(r0), "=r"(r1), "=r"(r2), "=r"(r3) : "r"(addr));
}

__device__ __forceinline__ void ldsm_x4t(uint32_t& r0, uint32_t& r1,
                                         uint32_t& r2, uint32_t& r3,
                                         uint32_t addr) {
    asm volatile(
        "ldmatrix.sync.aligned.m8n8.x4.trans.shared.b16 {%0,%1,%2,%3}, [%4];"
        : "=r"(r0), "=r"(r1), "=r"(r2), "=r"(r3) : "r"(addr));
}

__device__ __forceinline__ void cp_async16(uint32_t smem, const void* g) {
    asm volatile("cp.async.cg.shared.global [%0], [%1], 16;"
                 :: "r"(smem), "l"(g));
}

__device__ __forceinline__ uint32_t packh2(float a, float b) {
    __half2 h = __floats2half2_rn(a, b);
    return *reinterpret_cast<uint32_t*>(&h);
}

__device__ __forceinline__ float ex2f(float x) {
    float r;
    asm("ex2.approx.f32 %0, %1;" : "=f"(r) : "f"(x));
    return r;
}

// ---------------------------------------------------------------------------
// Fused: LayerNorm both streams -> half, then weights->half + stats zero.
// ---------------------------------------------------------------------------
__global__ void __launch_bounds__(256) ln_w2h(
    const float* __restrict__ x0, const float* __restrict__ ga0,
    const float* __restrict__ gb0, __half* __restrict__ y0,
    const float* __restrict__ x1, const float* __restrict__ ga1,
    const float* __restrict__ gb1, __half* __restrict__ y1, int split,
    const float* __restrict__ w0, const float* __restrict__ w1,
    const float* __restrict__ w2, __half* __restrict__ h0,
    __half* __restrict__ h1, __half* __restrict__ h2,
    float* __restrict__ rsum, float* __restrict__ rsumsq) {
    int blk = blockIdx.x;
    if (blk >= 2 * split) {
        int i = (blk - 2 * split) * 256 + threadIdx.x;
        if (i < 98304) {
            const float2* s;
            __half2* d;
            int j;
            if (i < 32768)      { s = (const float2*)w0; d = (__half2*)h0; j = i; }
            else if (i < 65536) { s = (const float2*)w1; d = (__half2*)h1; j = i - 32768; }
            else                { s = (const float2*)w2; d = (__half2*)h2; j = i - 65536; }
            float2 v = s[j];
            d[j] = __floats2half2_rn(v.x, v.y);
        } else {
            int j = i - 98304;
            float4 z = make_float4(0.f, 0.f, 0.f, 0.f);
            if (j < 12800) reinterpret_cast<float4*>(rsum)[j] = z;
            else           reinterpret_cast<float4*>(rsumsq)[j - 12800] = z;
        }
        return;
    }
    const float *x, *ga, *gb;
    __half* y;
    int rowbase;
    if (blk < split) { x = x0; ga = ga0; gb = gb0; y = y0; rowbase = blk * 8; }
    else { x = x1; ga = ga1; gb = gb1; y = y1; rowbase = (blk - split) * 8; }
    int w = threadIdx.x >> 5, lane = threadIdx.x & 31;
    size_t row = rowbase + w;
    const float4* x4 = reinterpret_cast<const float4*>(x + row * Dsz);
    float4 v0 = x4[lane];
    float4 v1 = x4[lane + 32];

    float s = v0.x + v0.y + v0.z + v0.w + v1.x + v1.y + v1.z + v1.w;
#pragma unroll
    for (int o = 16; o; o >>= 1) s += __shfl_xor_sync(0xffffffffu, s, o);
    float mean = s * (1.0f / Dsz);

    float d0x = v0.x - mean, d0y = v0.y - mean, d0z = v0.z - mean, d0w = v0.w - mean;
    float d1x = v1.x - mean, d1y = v1.y - mean, d1z = v1.z - mean, d1w = v1.w - mean;
    float ss = d0x * d0x + d0y * d0y + d0z * d0z + d0w * d0w +
               d1x * d1x + d1y * d1y + d1z * d1z + d1w * d1w;
#pragma unroll
    for (int o = 16; o; o >>= 1) ss += __shfl_xor_sync(0xffffffffu, ss, o);
    float var = ss * (1.0f / (Dsz - 1));
    float inv = 1.0f / (sqrtf(var) + 1e-6f);

    const float4* ga4 = reinterpret_cast<const float4*>(ga);
    const float4* gb4 = reinterpret_cast<const float4*>(gb);
    float4 g0 = ga4[lane], g1 = ga4[lane + 32];
    float4 b0 = gb4[lane], b1 = gb4[lane + 32];
    float4 o0 = make_float4(g0.x * d0x * inv + b0.x, g0.y * d0y * inv + b0.y,
                            g0.z * d0z * inv + b0.z, g0.w * d0w * inv + b0.w);
    float4 o1 = make_float4(g1.x * d1x * inv + b1.x, g1.y * d1y * inv + b1.y,
                            g1.z * d1z * inv + b1.z, g1.w * d1w * inv + b1.w);
    uint2* y2 = reinterpret_cast<uint2*>(y + row * Dsz);
    y2[lane] = make_uint2(packh2(o0.x, o0.y), packh2(o0.z, o0.w));
    y2[lane + 32] = make_uint2(packh2(o1.x, o1.y), packh2(o1.z, o1.w));
}

// ---------------------------------------------------------------------------
// fp16 GEMM (fp32 accum). Block 128x128, BK=32 (8 stages), 256 thr, 8 warps.
// __launch_bounds__(256,2). EPI0: 3-stage cp.async pipeline (copies issued
// two mma-phases ahead; wait_group 1 in steady state). EPI2: 2-stage with
// LN-at-staging transform (proven path).
// ---------------------------------------------------------------------------
#define GBM 128
#define GBN 128
#define GBK 32
#define HPITCH 80
#define TILE_B (128 * HPITCH)        // 10240
#define STAGE_B (2 * TILE_B)         // 20480

template <int EPI, bool STATS, bool ADDH, bool OUTH>
__global__ void __launch_bounds__(256, 2) gemm_f16(
    const void* __restrict__ Aptr, const __half* __restrict__ W,
    const float* __restrict__ bias, const void* __restrict__ addp,
    const float* __restrict__ sffn, void* __restrict__ outp,
    const float* __restrict__ lga, const float* __restrict__ lgb,
    float* __restrict__ rsum, float* __restrict__ rsumsq) {
    extern __shared__ char gsm[];
    uint32_t smemU = (uint32_t)__cvta_generic_to_shared(gsm);

    int m0 = blockIdx.y * GBM;
    int n0 = blockIdx.x * GBN;
    int tid = threadIdx.x;
    int wid = tid >> 5, lane = tid & 31;
    int wm = wid >> 1, wn = wid & 1;
    int grp = lane >> 2, qd = lane & 3;

    int rA = (lane & 7) + ((lane >> 3) & 1) * 8;
    int offA = (wm * 32 + rA) * HPITCH + ((lane >> 4) & 1) * 16;
    int rB = (lane & 7) + ((lane >> 4) & 1) * 8;
    int offB = (wn * 64 + rB) * HPITCH + ((lane >> 3) & 1) * 16;

    float mean_t[4], inv_t[4];
    int lr = tid >> 3;
    int c4f = (tid & 7) * 4;
    if (EPI == 2) {
#pragma unroll
        for (int t = 0; t < 4; t++) {
            int r = m0 + lr + 32 * t;
            float s = rsum[r], sq = rsumsq[r];
            float mn = s * (1.0f / Dsz);
            float var = (sq - (float)Dsz * mn * mn) * (1.0f / (Dsz - 1));
            mean_t[t] = mn;
            inv_t[t] = 1.0f / (sqrtf(var) + 1e-6f);
        }
    }

    float acc[2][8][4];
#pragma unroll
    for (int i = 0; i < 2; i++)
#pragma unroll
        for (int n = 0; n < 8; n++)
#pragma unroll
            for (int e = 0; e < 4; e++) acc[i][n][e] = 0.f;

    const __half* Ah = (const __half*)Aptr;
    int crow = tid >> 2, cu = tid & 3;

    auto stageW = [&](int buf, int k0) {
        uint32_t sb = smemU + buf * STAGE_B + TILE_B;
        cp_async16(sb + crow * HPITCH + cu * 16,
                   W + (size_t)(n0 + crow) * Dsz + k0 + cu * 8);
        cp_async16(sb + (crow + 64) * HPITCH + cu * 16,
                   W + (size_t)(n0 + crow + 64) * Dsz + k0 + cu * 8);
    };
    auto stageA = [&](int buf, int k0) {
        uint32_t sa = smemU + buf * STAGE_B;
        cp_async16(sa + crow * HPITCH + cu * 16,
                   Ah + (size_t)(m0 + crow) * Dsz + k0 + cu * 8);
        cp_async16(sa + (crow + 64) * HPITCH + cu * 16,
                   Ah + (size_t)(m0 + crow + 64) * Dsz + k0 + cu * 8);
    };
    auto transA = [&](int buf, int k0, const uint2* pa) {
        float4 g4 = *reinterpret_cast<const float4*>(lga + k0 + c4f);
        float4 b4 = *reinterpret_cast<const float4*>(lgb + k0 + c4f);
        uint32_t sa = smemU + buf * STAGE_B;
#pragma unroll
        for (int t = 0; t < 4; t++) {
            int r = lr + 32 * t;
            float2 p0 = __half22float2(*reinterpret_cast<const __half2*>(&pa[t].x));
            float2 p1 = __half22float2(*reinterpret_cast<const __half2*>(&pa[t].y));
            float mt = mean_t[t], it = inv_t[t];
            float v0 = (p0.x - mt) * it * g4.x + b4.x;
            float v1 = (p0.y - mt) * it * g4.y + b4.y;
            float v2 = (p1.x - mt) * it * g4.z + b4.z;
            float v3 = (p1.y - mt) * it * g4.w + b4.w;
            asm volatile("st.shared.v2.b32 [%0], {%1,%2};"
                         :: "r"(sa + r * HPITCH + c4f * 2),
                            "r"(packh2(v0, v1)), "r"(packh2(v2, v3)));
        }
    };

    const int NSTEP = Dsz / GBK;  // 8
    uint2 pa[4];

    if (EPI == 2) {
        // 2-stage path with LN transform at staging
#pragma unroll
        for (int t = 0; t < 4; t++)
            pa[t] = *reinterpret_cast<const uint2*>(
                Ah + (size_t)(m0 + lr + 32 * t) * Dsz + c4f);
        stageW(0, 0);
        asm volatile("cp.async.commit_group;");
        transA(0, 0, pa);

        for (int s = 0; s < NSTEP; s++) {
            if (s + 1 < NSTEP) {
#pragma unroll
                for (int t = 0; t < 4; t++)
                    pa[t] = *reinterpret_cast<const uint2*>(
                        Ah + (size_t)(m0 + lr + 32 * t) * Dsz + (s + 1) * GBK + c4f);
            }
            asm volatile("cp.async.wait_group 0;");
            __syncthreads();
            if (s + 1 < NSTEP) {
                stageW((s + 1) & 1, (s + 1) * GBK);
                asm volatile("cp.async.commit_group;");
            }
            uint32_t aB = smemU + (s & 1) * STAGE_B + offA;
            uint32_t bB = smemU + (s & 1) * STAGE_B + TILE_B + offB;
#pragma unroll
            for (int kb = 0; kb < 2; kb++) {
                uint32_t af[2][4];
#pragma unroll
                for (int i = 0; i < 2; i++)
                    ldsm_x4(af[i][0], af[i][1], af[i][2], af[i][3],
                            aB + i * 16 * HPITCH + kb * 32);
                uint32_t bf[8][2];
#pragma unroll
                for (int p = 0; p < 4; p++) {
                    uint32_t r0, r1, r2, r3;
                    ldsm_x4(r0, r1, r2, r3, bB + p * 16 * HPITCH + kb * 32);
                    bf[2 * p][0] = r0; bf[2 * p][1] = r1;
                    bf[2 * p + 1][0] = r2; bf[2 * p + 1][1] = r3;
                }
#pragma unroll
                for (int i = 0; i < 2; i++)
#pragma unroll
                    for (int n = 0; n < 8; n++)
                        mma_f16(acc[i][n], af[i], bf[n][0], bf[n][1]);
            }
            if (s + 1 < NSTEP)
                transA((s + 1) & 1, (s + 1) * GBK, pa);
        }
    } else {
        // 3-stage pipeline: copies issued 2 stages ahead
        stageA(0, 0);
        stageW(0, 0);
        asm volatile("cp.async.commit_group;");
        stageA(1, GBK);
        stageW(1, GBK);
        asm volatile("cp.async.commit_group;");

        for (int s = 0; s < NSTEP; s++) {
            if (s + 1 < NSTEP) {
                asm volatile("cp.async.wait_group 1;");
            } else {
                asm volatile("cp.async.wait_group 0;");
            }
            __syncthreads();
            if (s + 2 < NSTEP) {
                int buf2 = (s + 2) % 3;
                stageA(buf2, (s + 2) * GBK);
                stageW(buf2, (s + 2) * GBK);
                asm volatile("cp.async.commit_group;");
            }
            uint32_t aB = smemU + (s % 3) * STAGE_B + offA;
            uint32_t bB = smemU + (s % 3) * STAGE_B + TILE_B + offB;
#pragma unroll
            for (int kb = 0; kb < 2; kb++) {
                uint32_t af[2][4];
#pragma unroll
                for (int i = 0; i < 2; i++)
                    ldsm_x4(af[i][0], af[i][1], af[i][2], af[i][3],
                            aB + i * 16 * HPITCH + kb * 32);
                uint32_t bf[8][2];
#pragma unroll
                for (int p = 0; p < 4; p++) {
                    uint32_t r0, r1, r2, r3;
                    ldsm_x4(r0, r1, r2, r3, bB + p * 16 * HPITCH + kb * 32);
                    bf[2 * p][0] = r0; bf[2 * p][1] = r1;
                    bf[2 * p + 1][0] = r2; bf[2 * p + 1][1] = r3;
                }
#pragma unroll
                for (int i = 0; i < 2; i++)
#pragma unroll
                    for (int n = 0; n < 8; n++)
                        mma_f16(acc[i][n], af[i], bf[n][0], bf[n][1]);
            }
        }
    }

    const float* addf = (const float*)addp;
    const __half* addh = (const __half*)addp;
    float* outf = (float*)outp;
    __half* outh = (__half*)outp;

#pragma unroll
    for (int i = 0; i < 2; i++) {
        int mr0 = m0 + wm * 32 + i * 16 + grp;
        int mr1 = mr0 + 8;
        float sf0 = 0.f, sf1 = 0.f;
        if (EPI == 2) {
            sf0 = sffn[mr0 % Ssz];
            sf1 = sffn[mr1 % Ssz];
        }
        float s0 = 0.f, q0s = 0.f, s1 = 0.f, q1s = 0.f;
#pragma unroll
        for (int n = 0; n < 8; n++) {
            int col = n0 + wn * 64 + n * 8 + 2 * qd;
            float2 bv = *reinterpret_cast<const float2*>(bias + col);
            float2 a0, a1;
            if (ADDH) {
                __half2 h0 = *reinterpret_cast<const __half2*>(
                    addh + (size_t)mr0 * Dsz + col);
                __half2 h1v = *reinterpret_cast<const __half2*>(
                    addh + (size_t)mr1 * Dsz + col);
                a0 = __half22float2(h0);
                a1 = __half22float2(h1v);
            } else {
                a0 = *reinterpret_cast<const float2*>(
                    addf + (size_t)mr0 * Dsz + col);
                a1 = *reinterpret_cast<const float2*>(
                    addf + (size_t)mr1 * Dsz + col);
            }
            float r00 = acc[i][n][0] + bv.x, r01 = acc[i][n][1] + bv.y;
            float r10 = acc[i][n][2] + bv.x, r11 = acc[i][n][3] + bv.y;
            if (EPI == 0) {
                r00 += a0.x; r01 += a0.y; r10 += a1.x; r11 += a1.y;
                if (STATS) {
                    s0 += r00 + r01; q0s += r00 * r00 + r01 * r01;
                    s1 += r10 + r11; q1s += r10 * r10 + r11 * r11;
                }
            } else {
                float z, th;
                z = sf0 * r00;
                th = tanhf(0.79788456080286536f * (z + 0.044715f * z * z * z));
                r00 = a0.x + 0.5f * z * (1.0f + th);
                z = sf0 * r01;
                th = tanhf(0.79788456080286536f * (z + 0.044715f * z * z * z));
                r01 = a0.y + 0.5f * z * (1.0f + th);
                z = sf1 * r10;
                th = tanhf(0.79788456080286536f * (z + 0.044715f * z * z * z));
                r10 = a1.x + 0.5f * z * (1.0f + th);
                z = sf1 * r11;
                th = tanhf(0.79788456080286536f * (z + 0.044715f * z * z * z));
                r11 = a1.y + 0.5f * z * (1.0f + th);
            }
            if (OUTH) {
                *reinterpret_cast<uint32_t*>(outh + (size_t)mr0 * Dsz + col) =
                    packh2(r00, r01);
                *reinterpret_cast<uint32_t*>(outh + (size_t)mr1 * Dsz + col) =
                    packh2(r10, r11);
            } else {
                *reinterpret_cast<float2*>(outf + (size_t)mr0 * Dsz + col) =
                    make_float2(r00, r01);
                *reinterpret_cast<float2*>(outf + (size_t)mr1 * Dsz + col) =
                    make_float2(r10, r11);
            }
        }
        if (STATS) {
            const unsigned FULL = 0xffffffffu;
            s0 += __shfl_xor_sync(FULL, s0, 1);
            s0 += __shfl_xor_sync(FULL, s0, 2);
            q0s += __shfl_xor_sync(FULL, q0s, 1);
            q0s += __shfl_xor_sync(FULL, q0s, 2);
            s1 += __shfl_xor_sync(FULL, s1, 1);
            s1 += __shfl_xor_sync(FULL, s1, 2);
            q1s += __shfl_xor_sync(FULL, q1s, 1);
            q1s += __shfl_xor_sync(FULL, q1s, 2);
            if (qd == 0) {
                atomicAdd(&rsum[mr0], s0);
                atomicAdd(&rsumsq[mr0], q0s);
                atomicAdd(&rsum[mr1], s1);
                atomicAdd(&rsumsq[mr1], q1s);
            }
        }
    }
}

// ---------------------------------------------------------------------------
// fp16 flash-attention (unchanged, 65us).
// ---------------------------------------------------------------------------
#define SPAD 224
#define HP 80
#define QV_B (SPAD * HP)
#define ATHR 416
#define LOG2E 1.4426950408889634f

__global__ void __launch_bounds__(ATHR) attn_flash(
    const __half* __restrict__ img_h, const __half* __restrict__ keff_h,
    const int* __restrict__ mask, const float* __restrict__ sattn,
    __half* __restrict__ ctx_h) {
    extern __shared__ char smw[];
    uint32_t smemU = (uint32_t)__cvta_generic_to_shared(smw);
    uint32_t qvU = smemU;
    uint32_t ksU = smemU + QV_B;
    float* bias_s = reinterpret_cast<float*>(smw + 2 * QV_B);

    int b = blockIdx.x >> 3;
    int h = blockIdx.x & 7;
    int tid = threadIdx.x;
    size_t base = ((size_t)b * Ssz) * Dsz + h * DHsz;

    for (int idx = tid; idx < SPAD * 4; idx += ATHR) {
        int r = idx >> 2, c8 = (idx & 3) * 8;
        uint4 q = make_uint4(0u, 0u, 0u, 0u);
        uint4 k = make_uint4(0u, 0u, 0u, 0u);
        if (r < Ssz) {
            q = *reinterpret_cast<const uint4*>(img_h + base + (size_t)r * Dsz + c8);
            k = *reinterpret_cast<const uint4*>(keff_h + base + (size_t)r * Dsz + c8);
        }
        asm volatile("st.shared.v4.b32 [%0], {%1,%2,%3,%4};"
                     :: "r"(qvU + r * HP + c8 * 2),
                        "r"(q.x), "r"(q.y), "r"(q.z), "r"(q.w));
        asm volatile("st.shared.v4.b32 [%0], {%1,%2,%3,%4};"
                     :: "r"(ksU + r * HP + c8 * 2),
                        "r"(k.x), "r"(k.y), "r"(k.z), "r"(k.w));
    }
    for (int k = tid; k < SPAD; k += ATHR)
        bias_s[k] = (k >= Ssz || mask[b * Ssz + k] == 0) ? -1.4426950e9f : 0.f;
    __syncthreads();

    int w = tid >> 5, lane = tid & 31;
    int grp = lane >> 2;
    int qd = lane & 3;
    const float isq2 = 0.17677669529663687f * LOG2E;
    const unsigned FULL = 0xffffffffu;

    int q0 = w * 16;
    int qr0 = q0 + grp, qr1 = q0 + grp + 8;
    float f0 = (qr0 < Ssz) ? isq2 * sattn[h * Ssz + qr0] : 0.f;
    float f1 = (qr1 < Ssz) ? isq2 * sattn[h * Ssz + qr1] : 0.f;

    uint32_t aq[2][4];
    {
        int rA = (lane & 7) + ((lane >> 3) & 1) * 8;
        uint32_t offA = qvU + (q0 + rA) * HP + ((lane >> 4) & 1) * 16;
        ldsm_x4(aq[0][0], aq[0][1], aq[0][2], aq[0][3], offA);
        ldsm_x4(aq[1][0], aq[1][1], aq[1][2], aq[1][3], offA + 32);
    }

    int rB = (lane & 7) + ((lane >> 4) & 1) * 8;
    int rV = (lane & 7) + ((lane >> 3) & 1) * 8;
    int cB = ((lane >> 3) & 1) * 16;
    int cV = ((lane >> 4) & 1) * 16;

    float m0 = -3.0e38f, m1 = -3.0e38f, l0 = 0.f, l1 = 0.f;
    float co[4][4];
#pragma unroll
    for (int n = 0; n < 4; n++)
#pragma unroll
        for (int e = 0; e < 4; e++) co[n][e] = 0.f;

    for (int it = 0; it < 7; it++) {
        int key0 = it * 32;
        float sA[2][4] = {{0.f, 0.f, 0.f, 0.f}, {0.f, 0.f, 0.f, 0.f}};
        float sB[2][4] = {{0.f, 0.f, 0.f, 0.f}, {0.f, 0.f, 0.f, 0.f}};
        uint32_t offB = ksU + (key0 + rB) * HP + cB;
#pragma unroll
        for (int kk = 0; kk < 2; kk++) {
            uint32_t r0, r1, r2, r3;
            ldsm_x4(r0, r1, r2, r3, offB + kk * 32);
            mma_f16(sA[0], aq[kk], r0, r1);
            mma_f16(sA[1], aq[kk], r2, r3);
            ldsm_x4(r0, r1, r2, r3, offB + 16 * HP + kk * 32);
            mma_f16(sB[0], aq[kk], r0, r1);
            mma_f16(sB[1], aq[kk], r2, r3);
        }
        float vA[2][4], vB[2][4];
        float rm0 = -3.0e38f, rm1 = -3.0e38f;
#pragma unroll
        for (int n = 0; n < 2; n++) {
            float2 bkA = *reinterpret_cast<const float2*>(
                bias_s + key0 + n * 8 + 2 * qd);
            vA[n][0] = fmaf(sA[n][0], f0, bkA.x);
            vA[n][1] = fmaf(sA[n][1], f0, bkA.y);
            vA[n][2] = fmaf(sA[n][2], f1, bkA.x);
            vA[n][3] = fmaf(sA[n][3], f1, bkA.y);
            float2 bkB = *reinterpret_cast<const float2*>(
                bias_s + key0 + 16 + n * 8 + 2 * qd);
            vB[n][0] = fmaf(sB[n][0], f0, bkB.x);
            vB[n][1] = fmaf(sB[n][1], f0, bkB.y);
            vB[n][2] = fmaf(sB[n][2], f1, bkB.x);
            vB[n][3] = fmaf(sB[n][3], f1, bkB.y);
            rm0 = fmaxf(rm0, fmaxf(fmaxf(vA[n][0], vA[n][1]),
                                   fmaxf(vB[n][0], vB[n][1])));
            rm1 = fmaxf(rm1, fmaxf(fmaxf(vA[n][2], vA[n][3]),
                                   fmaxf(vB[n][2], vB[n][3])));
        }
        rm0 = fmaxf(rm0, __shfl_xor_sync(FULL, rm0, 1));
        rm0 = fmaxf(rm0, __shfl_xor_sync(FULL, rm0, 2));
        rm1 = fmaxf(rm1, __shfl_xor_sync(FULL, rm1, 1));
        rm1 = fmaxf(rm1, __shfl_xor_sync(FULL, rm1, 2));
        float nm0 = fmaxf(m0, rm0), nm1 = fmaxf(m1, rm1);
        float al0 = ex2f(m0 - nm0), al1 = ex2f(m1 - nm1);
        m0 = nm0; m1 = nm1;
#pragma unroll
        for (int n = 0; n < 4; n++) {
            co[n][0] *= al0; co[n][1] *= al0;
            co[n][2] *= al1; co[n][3] *= al1;
        }
        float ts0 = 0.f, ts1 = 0.f;
        uint32_t ap[4], ap2[4];
#pragma unroll
        for (int n = 0; n < 2; n++) {
            float e0 = ex2f(vA[n][0] - nm0);
            float e1 = ex2f(vA[n][1] - nm0);
            float e2 = ex2f(vA[n][2] - nm1);
            float e3 = ex2f(vA[n][3] - nm1);
            ts0 += e0 + e1;
            ts1 += e2 + e3;
            ap[2 * n]     = packh2(e0, e1);
            ap[2 * n + 1] = packh2(e2, e3);
            e0 = ex2f(vB[n][0] - nm0);
            e1 = ex2f(vB[n][1] - nm0);
            e2 = ex2f(vB[n][2] - nm1);
            e3 = ex2f(vB[n][3] - nm1);
            ts0 += e0 + e1;
            ts1 += e2 + e3;
            ap2[2 * n]     = packh2(e0, e1);
            ap2[2 * n + 1] = packh2(e2, e3);
        }
        l0 = l0 * al0 + ts0;
        l1 = l1 * al1 + ts1;
        uint32_t offV = qvU + (key0 + rV) * HP + cV;
        {
            uint32_t r0, r1, r2, r3;
            ldsm_x4t(r0, r1, r2, r3, offV);
            mma_f16(co[0], ap, r0, r1);
            mma_f16(co[1], ap, r2, r3);
            ldsm_x4t(r0, r1, r2, r3, offV + 32);
            mma_f16(co[2], ap, r0, r1);
            mma_f16(co[3], ap, r2, r3);
            ldsm_x4t(r0, r1, r2, r3, offV + 16 * HP);
            mma_f16(co[0], ap2, r0, r1);
            mma_f16(co[1], ap2, r2, r3);
            ldsm_x4t(r0, r1, r2, r3, offV + 16 * HP + 32);
            mma_f16(co[2], ap2, r0, r1);
            mma_f16(co[3], ap2, r2, r3);
        }
    }

    l0 += __shfl_xor_sync(FULL, l0, 1);
    l0 += __shfl_xor_sync(FULL, l0, 2);
    l1 += __shfl_xor_sync(FULL, l1, 1);
    l1 += __shfl_xor_sync(FULL, l1, 2);
    float inv0 = 1.f / l0, inv1 = 1.f / l1;
#pragma unroll
    for (int n4 = 0; n4 < 4; n4++) {
        if (qr0 < Ssz) {
            __half2 v = __floats2half2_rn(co[n4][0] * inv0, co[n4][1] * inv0);
            *reinterpret_cast<__half2*>(
                ctx_h + base + (size_t)qr0 * Dsz + n4 * 8 + 2 * qd) = v;
        }
        if (qr1 < Ssz) {
            __half2 v = __floats2half2_rn(co[n4][2] * inv1, co[n4][3] * inv1);
            *reinterpret_cast<__half2*>(
                ctx_h + base + (size_t)qr1 * Dsz + n4 * 8 + 2 * qd) = v;
        }
    }
}

// ---------------------------------------------------------------------------
extern "C" void kernel_launch(void* const* d_in, const int* in_sizes, int n_in,
                              void* d_out, int out_size) {
    const float* hidden_img   = (const float*)d_in[0];
    const float* hidden_title = (const float*)d_in[1];
    const int*   mask         = (const int*)  d_in[2];
    const float* a_img   = (const float*)d_in[3];
    const float* b_img   = (const float*)d_in[4];
    const float* a_title = (const float*)d_in[5];
    const float* b_title = (const float*)d_in[6];
    const float* Wb      = (const float*)d_in[7];
    const float* bb      = (const float*)d_in[8];
    const float* Wo      = (const float*)d_in[9];
    const float* bo      = (const float*)d_in[10];
    const float* sattn   = (const float*)d_in[11];
    const float* a_out   = (const float*)d_in[12];
    const float* b_out   = (const float*)d_in[13];
    const float* W1      = (const float*)d_in[14];
    const float* b1      = (const float*)d_in[15];
    const float* sffn    = (const float*)d_in[16];
    float* out = (float*)d_out;

    float *rsum, *rsumsq;
    __half *h1_h, *img_h, *title_h, *keff_h, *ctx_h, *Wb_h, *Wo_h, *W1_h;
    cudaGetSymbolAddress((void**)&rsum,    g_rsum);
    cudaGetSymbolAddress((void**)&rsumsq,  g_rsumsq);
    cudaGetSymbolAddress((void**)&h1_h,    g_h1_h);
    cudaGetSymbolAddress((void**)&img_h,   g_img_h);
    cudaGetSymbolAddress((void**)&title_h, g_title_h);
    cudaGetSymbolAddress((void**)&keff_h,  g_keff_h);
    cudaGetSymbolAddress((void**)&ctx_h,   g_ctx_h);
    cudaGetSymbolAddress((void**)&Wb_h,    g_Wb_h);
    cudaGetSymbolAddress((void**)&Wo_h,    g_Wo_h);
    cudaGetSymbolAddress((void**)&W1_h,    g_W1_h);

    const int LNB = BS / 8;
    const int smem_epi0 = 3 * STAGE_B;   // 61440 B (3-stage)
    const int smem_epi2 = 2 * STAGE_B;   // 40960 B (2-stage)
    cudaFuncSetAttribute((const void*)gemm_f16<0, false, true, true>,
                         cudaFuncAttributeMaxDynamicSharedMemorySize, smem_epi0);
    cudaFuncSetAttribute((const void*)gemm_f16<0, true, false, true>,
                         cudaFuncAttributeMaxDynamicSharedMemorySize, smem_epi0);
    cudaFuncSetAttribute((const void*)gemm_f16<2, false, true, false>,
                         cudaFuncAttributeMaxDynamicSharedMemorySize, smem_epi2);

    // 1) LayerNorms + weights->half + stats zero, one launch
    ln_w2h<<<2 * LNB + 484, 256>>>(
        hidden_img, a_img, b_img, img_h,
        hidden_title, a_title, b_title, title_h, LNB,
        Wb, Wo, W1, Wb_h, Wo_h, W1_h, rsum, rsumsq);

    // 2) keff(half) = title_n @ Wb^T + bb + img_n(half)
    dim3 gg(Dsz / GBN, BS / GBM);
    gemm_f16<0, false, true, true><<<gg, 256, smem_epi0>>>(
        title_h, Wb_h, bb, img_h, nullptr, keff_h, nullptr, nullptr,
        nullptr, nullptr);

    // 3) fp16 flash attention -> ctx half
    const int attn_smem = 2 * QV_B + SPAD * 4;
    cudaFuncSetAttribute(attn_flash,
                         cudaFuncAttributeMaxDynamicSharedMemorySize, attn_smem);
    attn_flash<<<Bsz * Hsz, ATHR, attn_smem>>>(img_h, keff_h, mask, sattn, ctx_h);

    // 4) h1(half) = ctx @ Wo^T + bo + hidden_img  (+ row stats)
    gemm_f16<0, true, false, true><<<gg, 256, smem_epi0>>>(
        ctx_h, Wo_h, bo, hidden_img, nullptr, h1_h, nullptr, nullptr,
        rsum, rsumsq);

    // 5) out = h1 + gelu_tanh(scale_ffn * (LN(h1) @ W1^T + b1))
    gemm_f16<2, false, true, false><<<gg, 256, smem_epi2>>>(
        h1_h, W1_h, b1, h1_h, sffn, out, a_out, b_out, rsum, rsumsq);
}